// round 6
// baseline (speedup 1.0000x reference)
#include <cuda_runtime.h>
#include <cuda_bf16.h>
#include <cstdint>
#include <math.h>

// ---------------- problem constants ----------------
#define B_  4
#define T_  2048
#define C_  1024
#define H_  8
#define DH_ 128
#define DFF_ 4096
#define M_  (B_ * T_)            // 8192 rows

typedef __nv_bfloat16 bf16;

// ---------------- scratch (device globals, no allocation) ----------------
#define QKV_SZ (B_ * H_ * T_ * DH_)
__device__ bf16  g_h1h[M_ * C_],  g_h1l[M_ * C_];             // LN1 out hi/lo
__device__ bf16  g_q_h[QKV_SZ], g_q_l[QKV_SZ];
__device__ bf16  g_k_h[QKV_SZ], g_k_l[QKV_SZ];
__device__ float g_v  [QKV_SZ];
__device__ bf16  g_vT_h[QKV_SZ], g_vT_l[QKV_SZ];              // [z][Dh][T]
__device__ float g_sc[(size_t)B_ * H_ * T_ * T_];             // scores fp32
__device__ bf16  g_p_h[(size_t)B_ * H_ * T_ * T_];            // probs hi
__device__ bf16  g_p_l[(size_t)B_ * H_ * T_ * T_];            // probs lo
__device__ float g_x1[M_ * C_];                               // x + attn_out
__device__ bf16  g_h2h[M_ * C_], g_h2l[M_ * C_];              // LN2 out hi/lo
__device__ bf16  g_f1h[M_ * DFF_], g_f1l[M_ * DFF_];          // relu(h2 w1 + b1)
__device__ bf16  g_wTh[3 * H_ * DH_ * C_], g_wTl[3 * H_ * DH_ * C_];  // qkv w^T
__device__ bf16  g_w1Th[DFF_ * C_], g_w1Tl[DFF_ * C_];        // w1^T [Dff, C]
__device__ bf16  g_w2Th[C_ * DFF_], g_w2Tl[C_ * DFF_];        // w2^T [C, Dff]

// ---------------- low-level helpers ----------------
__device__ __forceinline__ uint32_t smem_u32(const void* p) {
    uint32_t a;
    asm("{ .reg .u64 t; cvta.to.shared.u64 t, %1; cvt.u32.u64 %0, t; }"
        : "=r"(a) : "l"(p));
    return a;
}
__device__ __forceinline__ void cp16(uint32_t dst, const void* src) {
    asm volatile("cp.async.cg.shared.global [%0], [%1], 16;\n"
                 :: "r"(dst), "l"(__cvta_generic_to_global(src)));
}
__device__ __forceinline__ void cp_commit() {
    asm volatile("cp.async.commit_group;\n" ::: "memory");
}
template<int N> __device__ __forceinline__ void cp_wait() {
    asm volatile("cp.async.wait_group %0;\n" :: "n"(N) : "memory");
}
__device__ __forceinline__ void ldsm4(uint32_t r[4], uint32_t addr) {
    asm volatile("ldmatrix.sync.aligned.m8n8.x4.shared.b16 {%0,%1,%2,%3}, [%4];"
        : "=r"(r[0]), "=r"(r[1]), "=r"(r[2]), "=r"(r[3]) : "r"(addr));
}
__device__ __forceinline__ void ldsm2(uint32_t r[2], uint32_t addr) {
    asm volatile("ldmatrix.sync.aligned.m8n8.x2.shared.b16 {%0,%1}, [%2];"
        : "=r"(r[0]), "=r"(r[1]) : "r"(addr));
}
__device__ __forceinline__ void mma_bf16(float c[4], const uint32_t a[4],
                                         const uint32_t b[2]) {
    asm volatile(
        "mma.sync.aligned.m16n8k16.row.col.f32.bf16.bf16.f32 "
        "{%0,%1,%2,%3}, {%4,%5,%6,%7}, {%8,%9}, {%0,%1,%2,%3};"
        : "+f"(c[0]), "+f"(c[1]), "+f"(c[2]), "+f"(c[3])
        : "r"(a[0]), "r"(a[1]), "r"(a[2]), "r"(a[3]), "r"(b[0]), "r"(b[1]));
}

// ---------------- smem geometry ----------------
// 4 mats per stage (Ah, Al, Bh, Bl), each 128 rows x 32 bf16, row stride 80B
// (80B = 20-bank stride -> ldmatrix 8-row groups hit 8 distinct 4-bank sets).
// 4-stage ring, prefetch distance 3.
#define ROWB    80
#define MATB    (128 * ROWB)        // 10240
#define STAGEB  (4 * MATB)          // 40960
#define NSTG    4
#define GEMM_SMEM (NSTG * STAGEB)   // 163840

// ---------------- stage loader: gmem -> smem via cp.async ----------------
__device__ __forceinline__ void issue_stage(
    uint32_t sbase, int buf,
    const bf16* __restrict__ Ah, const bf16* __restrict__ Al, int lda,
    const bf16* __restrict__ Bh, const bf16* __restrict__ Bl, int ldb, int k0)
{
    const int tid = threadIdx.x;
    const int mat = tid >> 6;
    const int t   = tid & 63;
    const bf16* src; int ld;
    if      (mat == 0) { src = Ah; ld = lda; }
    else if (mat == 1) { src = Al; ld = lda; }
    else if (mat == 2) { src = Bh; ld = ldb; }
    else               { src = Bl; ld = ldb; }
    uint32_t mbase = sbase + (uint32_t)buf * STAGEB + (uint32_t)mat * MATB;
    #pragma unroll
    for (int rr = 0; rr < 2; rr++) {
        int row = t * 2 + rr;
        const bf16* s = src + (size_t)row * ld + k0;
        uint32_t d = mbase + row * ROWB;
        #pragma unroll
        for (int seg = 0; seg < 4; seg++)
            cp16(d + seg * 16, s + seg * 8);
    }
    cp_commit();
}

// ---------------- block GEMM mainloop ----------------
// D(128x128 fp32) = (Ah+Al)(128xK) * (Bh+Bl)(128xK)^T, 3-term bf16 split.
// acc[mi][ni][4] per thread; warp (wid&3)->M32, (wid>>2)->N64.
__device__ __forceinline__ void gemm_mainloop(
    float acc[2][8][4],
    const bf16* __restrict__ Ah, const bf16* __restrict__ Al, int lda,
    const bf16* __restrict__ Bh, const bf16* __restrict__ Bl, int ldb, int K)
{
    extern __shared__ char smem_raw[];
    uint32_t sbase = smem_u32(smem_raw);
    const int tid  = threadIdx.x;
    const int wid  = tid >> 5, lane = tid & 31;
    const int m0w  = (wid & 3) * 32;
    const int n0w  = (wid >> 2) * 64;
    const int g    = lane >> 3, lr = lane & 7;

    // ldmatrix per-lane byte offsets within a mat
    const uint32_t a_off = (uint32_t)((m0w + (g & 1) * 8 + lr) * ROWB + (g >> 1) * 16);
    const uint32_t b_off = (uint32_t)((n0w + lr) * ROWB + (g & 1) * 16);

    #pragma unroll
    for (int mi = 0; mi < 2; mi++)
        #pragma unroll
        for (int ni = 0; ni < 8; ni++)
            #pragma unroll
            for (int i = 0; i < 4; i++)
                acc[mi][ni][i] = 0.f;

    const int nstage = K >> 5;                  // K32 per stage
    // prologue: fill 3 of 4 ring slots
    #pragma unroll
    for (int s = 0; s < NSTG - 1; s++)
        if (s < nstage)
            issue_stage(sbase, s, Ah, Al, lda, Bh, Bl, ldb, s << 5);

    for (int c = 0; c < nstage; c++) {
        cp_wait<NSTG - 2>();                    // stage c complete
        __syncthreads();                        // all warps done with slot (c-1)&3
        if (c + NSTG - 1 < nstage)
            issue_stage(sbase, (c + NSTG - 1) & (NSTG - 1),
                        Ah, Al, lda, Bh, Bl, ldb, (c + NSTG - 1) << 5);

        uint32_t st = sbase + (uint32_t)(c & (NSTG - 1)) * STAGEB;
        #pragma unroll
        for (int ks = 0; ks < 2; ks++) {
            uint32_t kb = (uint32_t)ks * 32;    // k16 step = 32 bytes
            uint32_t ah[2][4], al[2][4];
            ldsm4(ah[0], st + 0 * MATB + a_off + kb);
            ldsm4(ah[1], st + 0 * MATB + a_off + kb + 16 * ROWB);
            ldsm4(al[0], st + 1 * MATB + a_off + kb);
            ldsm4(al[1], st + 1 * MATB + a_off + kb + 16 * ROWB);
            #pragma unroll
            for (int ni = 0; ni < 8; ni++) {
                uint32_t bh[2], bl[2];
                ldsm2(bh, st + 2 * MATB + b_off + kb + (uint32_t)ni * 8 * ROWB);
                ldsm2(bl, st + 3 * MATB + b_off + kb + (uint32_t)ni * 8 * ROWB);
                #pragma unroll
                for (int mi = 0; mi < 2; mi++) {
                    mma_bf16(acc[mi][ni], ah[mi], bh);
                    mma_bf16(acc[mi][ni], ah[mi], bl);
                    mma_bf16(acc[mi][ni], al[mi], bh);
                }
            }
        }
    }
    __syncthreads();
}

// epilogue iteration: calls f(ml, nl, float2) for this thread's 32 output pairs
template<class F>
__device__ __forceinline__ void epilogue_loop(float acc[2][8][4], F f)
{
    const int wid = threadIdx.x >> 5, lane = threadIdx.x & 31;
    const int m0w = (wid & 3) * 32, n0w = (wid >> 2) * 64;
    const int lr = lane >> 2, lc = (lane & 3) * 2;
    #pragma unroll
    for (int mi = 0; mi < 2; mi++)
        #pragma unroll
        for (int hf = 0; hf < 2; hf++) {
            const int ml = m0w + mi * 16 + hf * 8 + lr;
            #pragma unroll
            for (int ni = 0; ni < 8; ni++) {
                const int nl = n0w + ni * 8 + lc;
                f(ml, nl, make_float2(acc[mi][ni][hf * 2], acc[mi][ni][hf * 2 + 1]));
            }
        }
}

__device__ __forceinline__ void store_hilo2(bf16* oh, bf16* ol, float2 v) {
    bf16 h0 = __float2bfloat16_rn(v.x);
    bf16 h1 = __float2bfloat16_rn(v.y);
    __nv_bfloat162 hh; hh.x = h0; hh.y = h1;
    __nv_bfloat162 ll;
    ll.x = __float2bfloat16_rn(v.x - __bfloat162float(h0));
    ll.y = __float2bfloat16_rn(v.y - __bfloat162float(h1));
    *reinterpret_cast<__nv_bfloat162*>(oh) = hh;
    *reinterpret_cast<__nv_bfloat162*>(ol) = ll;
}

// ============================================================================
// GEMM kernels
// ============================================================================
__global__ void __launch_bounds__(256) qkv_gemm()
{
    int m0   = blockIdx.x * 128;
    int sel  = blockIdx.y >> 3;
    int head = blockIdx.y & 7;
    size_t woff = (size_t)blockIdx.y * DH_ * C_;
    float acc[2][8][4];
    gemm_mainloop(acc,
        g_h1h + (size_t)m0 * C_, g_h1l + (size_t)m0 * C_, C_,
        g_wTh + woff,            g_wTl + woff,            C_, C_);

    const float AL = 11.313708498984761f;   // sqrt(128) folded into q
    epilogue_loop(acc, [&](int ml, int nl, float2 vv) {
        int m = m0 + ml, b = m >> 11, t = m & (T_ - 1);
        size_t base = ((size_t)(b * H_ + head) * T_ + t) * DH_ + nl;
        if (sel == 0)      store_hilo2(g_q_h + base, g_q_l + base,
                                       make_float2(vv.x * AL, vv.y * AL));
        else if (sel == 1) store_hilo2(g_k_h + base, g_k_l + base, vv);
        else               *(float2*)(g_v + base) = vv;
    });
}

__global__ void __launch_bounds__(256) qk_gemm()
{
    int z = blockIdx.z, m0 = blockIdx.x * 128, n0 = blockIdx.y * 128;
    size_t zb = (size_t)z * T_ * DH_;
    float acc[2][8][4];
    gemm_mainloop(acc,
        g_q_h + zb + (size_t)m0 * DH_, g_q_l + zb + (size_t)m0 * DH_, DH_,
        g_k_h + zb + (size_t)n0 * DH_, g_k_l + zb + (size_t)n0 * DH_, DH_, DH_);

    float* outp = g_sc + (size_t)z * T_ * T_;
    epilogue_loop(acc, [&](int ml, int nl, float2 vv) {
        *(float2*)(outp + (size_t)(m0 + ml) * T_ + n0 + nl) = vv;
    });
}

__global__ void __launch_bounds__(256) pv_gemm(const float* __restrict__ x)
{
    int z = blockIdx.z, m0 = blockIdx.x * 128;
    int b = z >> 3, head = z & 7;
    size_t pb = (size_t)z * T_ * T_ + (size_t)m0 * T_;
    size_t vb = (size_t)z * DH_ * T_;
    float acc[2][8][4];
    gemm_mainloop(acc,
        g_p_h + pb, g_p_l + pb, T_,
        g_vT_h + vb, g_vT_l + vb, T_, T_);

    epilogue_loop(acc, [&](int ml, int nl, float2 vv) {
        int t = m0 + ml;
        size_t idx = ((size_t)(b * T_ + t)) * C_ + head * DH_ + nl;
        float2 xr = *(const float2*)(x + idx);
        *(float2*)(g_x1 + idx) = make_float2(vv.x + xr.x, vv.y + xr.y);
    });
}

__global__ void __launch_bounds__(256) ff1_gemm(const float* __restrict__ b1)
{
    int m0 = blockIdx.x * 128, n0 = blockIdx.y * 128;
    float acc[2][8][4];
    gemm_mainloop(acc,
        g_h2h + (size_t)m0 * C_,  g_h2l + (size_t)m0 * C_,  C_,
        g_w1Th + (size_t)n0 * C_, g_w1Tl + (size_t)n0 * C_, C_, C_);

    epilogue_loop(acc, [&](int ml, int nl, float2 vv) {
        float2 bb = *(const float2*)(b1 + n0 + nl);
        float r0 = fmaxf(vv.x + bb.x, 0.f);
        float r1 = fmaxf(vv.y + bb.y, 0.f);
        size_t base = (size_t)(m0 + ml) * DFF_ + n0 + nl;
        store_hilo2(g_f1h + base, g_f1l + base, make_float2(r0, r1));
    });
}

__global__ void __launch_bounds__(256) ff2_gemm(const float* __restrict__ b2,
                                                float* __restrict__ out)
{
    int m0 = blockIdx.x * 128, n0 = blockIdx.y * 128;
    float acc[2][8][4];
    gemm_mainloop(acc,
        g_f1h + (size_t)m0 * DFF_,  g_f1l + (size_t)m0 * DFF_,  DFF_,
        g_w2Th + (size_t)n0 * DFF_, g_w2Tl + (size_t)n0 * DFF_, DFF_, DFF_);

    epilogue_loop(acc, [&](int ml, int nl, float2 vv) {
        float2 bb = *(const float2*)(b2 + n0 + nl);
        size_t idx = (size_t)(m0 + ml) * C_ + n0 + nl;
        float2 xr = *(const float2*)(g_x1 + idx);
        *(float2*)(out + idx) = make_float2(vv.x + bb.x + xr.x,
                                            vv.y + bb.y + xr.y);
    });
}

// ============================================================================
// transpose + bf16 hi/lo convert: in [R, Cc] fp32 -> out [Cc, R] hi/lo
// ============================================================================
__global__ void transpose_conv(const float* __restrict__ in, bf16* __restrict__ oh,
                               bf16* __restrict__ ol, int R, int Cc,
                               size_t in_bstride, size_t out_bstride)
{
    __shared__ float tile[32][33];
    const float* src = in + (size_t)blockIdx.z * in_bstride;
    int c0 = blockIdx.x * 32, r0 = blockIdx.y * 32;
    int tx = threadIdx.x, ty = threadIdx.y;          // 32 x 8
    #pragma unroll
    for (int i = 0; i < 32; i += 8)
        tile[ty + i][tx] = src[(size_t)(r0 + ty + i) * Cc + c0 + tx];
    __syncthreads();
    #pragma unroll
    for (int i = 0; i < 32; i += 8) {
        float v = tile[tx][ty + i];
        bf16 h = __float2bfloat16_rn(v);
        bf16 l = __float2bfloat16_rn(v - __bfloat162float(h));
        size_t o = (size_t)blockIdx.z * out_bstride + (size_t)(c0 + ty + i) * R + r0 + tx;
        oh[o] = h; ol[o] = l;
    }
}

// ============================================================================
// LayerNorm -> bf16 hi/lo
// ============================================================================
__device__ __forceinline__ void block_reduce2(float& a, float& b)
{
    #pragma unroll
    for (int o = 16; o; o >>= 1) {
        a += __shfl_xor_sync(0xFFFFFFFFu, a, o);
        b += __shfl_xor_sync(0xFFFFFFFFu, b, o);
    }
    __shared__ float sa[8], sb_[8];
    int w = threadIdx.x >> 5, l = threadIdx.x & 31;
    if (l == 0) { sa[w] = a; sb_[w] = b; }
    __syncthreads();
    a = 0.f; b = 0.f;
    #pragma unroll
    for (int i = 0; i < 8; i++) { a += sa[i]; b += sb_[i]; }
}

__global__ void ln_kernel(const float* __restrict__ x, const float* __restrict__ g,
                          const float* __restrict__ bb, bf16* __restrict__ oh,
                          bf16* __restrict__ ol)
{
    size_t row = blockIdx.x;
    float4 v = ((const float4*)(x + row * C_))[threadIdx.x];
    float s  = v.x + v.y + v.z + v.w;
    float sq = v.x*v.x + v.y*v.y + v.z*v.z + v.w*v.w;
    block_reduce2(s, sq);
    float mean = s * (1.0f / C_);
    float var  = sq * (1.0f / C_) - mean * mean;
    float inv  = rsqrtf(var + 1e-5f);
    float4 gv = ((const float4*)g)[threadIdx.x];
    float4 bv = ((const float4*)bb)[threadIdx.x];
    float o0 = (v.x - mean) * inv * gv.x + bv.x;
    float o1 = (v.y - mean) * inv * gv.y + bv.y;
    float o2 = (v.z - mean) * inv * gv.z + bv.z;
    float o3 = (v.w - mean) * inv * gv.w + bv.w;
    size_t base = row * C_ + threadIdx.x * 4;
    store_hilo2(oh + base,     ol + base,     make_float2(o0, o1));
    store_hilo2(oh + base + 2, ol + base + 2, make_float2(o2, o3));
}

// ============================================================================
// row softmax over 2048, fp32 scores in -> bf16 hi/lo probs out
// ============================================================================
__global__ void softmax_kernel()
{
    size_t row = blockIdx.x;
    const float* p = g_sc + row * T_;
    float4 v0 = *(const float4*)(p + threadIdx.x * 8);
    float4 v1 = *(const float4*)(p + threadIdx.x * 8 + 4);

    float mx = fmaxf(fmaxf(fmaxf(v0.x, v0.y), fmaxf(v0.z, v0.w)),
                     fmaxf(fmaxf(v1.x, v1.y), fmaxf(v1.z, v1.w)));
    #pragma unroll
    for (int o = 16; o; o >>= 1) mx = fmaxf(mx, __shfl_xor_sync(0xFFFFFFFFu, mx, o));
    __shared__ float sm[8];
    int w = threadIdx.x >> 5, l = threadIdx.x & 31;
    if (l == 0) sm[w] = mx;
    __syncthreads();
    mx = fmaxf(fmaxf(fmaxf(sm[0], sm[1]), fmaxf(sm[2], sm[3])),
               fmaxf(fmaxf(sm[4], sm[5]), fmaxf(sm[6], sm[7])));

    v0.x = expf(v0.x - mx); v0.y = expf(v0.y - mx); v0.z = expf(v0.z - mx); v0.w = expf(v0.w - mx);
    v1.x = expf(v1.x - mx); v1.y = expf(v1.y - mx); v1.z = expf(v1.z - mx); v1.w = expf(v1.w - mx);
    float s = v0.x + v0.y + v0.z + v0.w + v1.x + v1.y + v1.z + v1.w;
    float s2 = s;
    __syncthreads();
    block_reduce2(s, s2);
    float inv = 1.0f / s;
    float vals[8] = {v0.x*inv, v0.y*inv, v0.z*inv, v0.w*inv,
                     v1.x*inv, v1.y*inv, v1.z*inv, v1.w*inv};
    size_t base = row * T_ + threadIdx.x * 8;
    #pragma unroll
    for (int j = 0; j < 8; j += 2)
        store_hilo2(g_p_h + base + j, g_p_l + base + j,
                    make_float2(vals[j], vals[j + 1]));
}

// ============================================================================
// host
// ============================================================================
extern "C" void kernel_launch(void* const* d_in, const int* in_sizes, int n_in,
                              void* d_out, int out_size)
{
    const float* x     = (const float*)d_in[0];
    const float* wq    = (const float*)d_in[1];
    const float* wk    = (const float*)d_in[2];
    const float* wv    = (const float*)d_in[3];
    const float* w1    = (const float*)d_in[4];
    const float* b1    = (const float*)d_in[5];
    const float* w2    = (const float*)d_in[6];
    const float* b2    = (const float*)d_in[7];
    const float* ln1_g = (const float*)d_in[8];
    const float* ln1_b = (const float*)d_in[9];
    const float* ln2_g = (const float*)d_in[10];
    const float* ln2_b = (const float*)d_in[11];
    float* out = (float*)d_out;

    cudaFuncSetAttribute(qkv_gemm, cudaFuncAttributeMaxDynamicSharedMemorySize, GEMM_SMEM);
    cudaFuncSetAttribute(qk_gemm,  cudaFuncAttributeMaxDynamicSharedMemorySize, GEMM_SMEM);
    cudaFuncSetAttribute(pv_gemm,  cudaFuncAttributeMaxDynamicSharedMemorySize, GEMM_SMEM);
    cudaFuncSetAttribute(ff1_gemm, cudaFuncAttributeMaxDynamicSharedMemorySize, GEMM_SMEM);
    cudaFuncSetAttribute(ff2_gemm, cudaFuncAttributeMaxDynamicSharedMemorySize, GEMM_SMEM);

    bf16 *p_h1h, *p_h1l, *p_h2h, *p_h2l, *p_wTh, *p_wTl, *p_w1Th, *p_w1Tl, *p_w2Th, *p_w2Tl;
    bf16 *p_vTh, *p_vTl;
    float *p_x1, *p_v;
    cudaGetSymbolAddress((void**)&p_h1h, g_h1h);
    cudaGetSymbolAddress((void**)&p_h1l, g_h1l);
    cudaGetSymbolAddress((void**)&p_h2h, g_h2h);
    cudaGetSymbolAddress((void**)&p_h2l, g_h2l);
    cudaGetSymbolAddress((void**)&p_wTh, g_wTh);
    cudaGetSymbolAddress((void**)&p_wTl, g_wTl);
    cudaGetSymbolAddress((void**)&p_w1Th, g_w1Th);
    cudaGetSymbolAddress((void**)&p_w1Tl, g_w1Tl);
    cudaGetSymbolAddress((void**)&p_w2Th, g_w2Th);
    cudaGetSymbolAddress((void**)&p_w2Tl, g_w2Tl);
    cudaGetSymbolAddress((void**)&p_vTh, g_vT_h);
    cudaGetSymbolAddress((void**)&p_vTl, g_vT_l);
    cudaGetSymbolAddress((void**)&p_x1, g_x1);
    cudaGetSymbolAddress((void**)&p_v,  g_v);

    dim3 tb(32, 8);
    // weight transposes -> [N, K] bf16 hi/lo
    transpose_conv<<<dim3(DH_/32, C_/32, H_), tb>>>(wq, p_wTh, p_wTl, C_, DH_, (size_t)C_*DH_, (size_t)DH_*C_);
    transpose_conv<<<dim3(DH_/32, C_/32, H_), tb>>>(wk, p_wTh + (size_t)H_*DH_*C_, p_wTl + (size_t)H_*DH_*C_, C_, DH_, (size_t)C_*DH_, (size_t)DH_*C_);
    transpose_conv<<<dim3(DH_/32, C_/32, H_), tb>>>(wv, p_wTh + (size_t)2*H_*DH_*C_, p_wTl + (size_t)2*H_*DH_*C_, C_, DH_, (size_t)C_*DH_, (size_t)DH_*C_);
    transpose_conv<<<dim3(DFF_/32, C_/32, 1), tb>>>(w1, p_w1Th, p_w1Tl, C_, DFF_, 0, 0);
    transpose_conv<<<dim3(C_/32, DFF_/32, 1), tb>>>(w2, p_w2Th, p_w2Tl, DFF_, C_, 0, 0);

    // 1. LN1 -> h1 hi/lo
    ln_kernel<<<M_, 256>>>(x, ln1_g, ln1_b, p_h1h, p_h1l);
    // 2. QKV projections (q pre-scaled by sqrt(128))
    qkv_gemm<<<dim3(M_/128, 3*H_, 1), 256, GEMM_SMEM>>>();
    // 3. v transpose -> [z][Dh][T] hi/lo
    transpose_conv<<<dim3(DH_/32, T_/32, B_*H_), tb>>>(p_v, p_vTh, p_vTl, T_, DH_, (size_t)T_*DH_, (size_t)DH_*T_);
    // 4. scores
    qk_gemm<<<dim3(T_/128, T_/128, B_*H_), 256, GEMM_SMEM>>>();
    // 5. softmax -> probs hi/lo
    softmax_kernel<<<B_*H_*T_, 256>>>();
    // 6. attention out + residual -> x1
    pv_gemm<<<dim3(T_/128, 1, B_*H_), 256, GEMM_SMEM>>>(x);
    // 7. LN2 -> h2 hi/lo
    ln_kernel<<<M_, 256>>>(p_x1, ln2_g, ln2_b, p_h2h, p_h2l);
    // 8. FF1 -> f1 hi/lo
    ff1_gemm<<<dim3(M_/128, DFF_/128, 1), 256, GEMM_SMEM>>>(b1);
    // 9. FF2 (+bias +residual) -> out
    ff2_gemm<<<dim3(M_/128, C_/128, 1), 256, GEMM_SMEM>>>(b2, out);
}

// round 7
// speedup vs baseline: 1.0878x; 1.0878x over previous
#include <cuda_runtime.h>
#include <cuda_bf16.h>
#include <cstdint>
#include <math.h>

// ---------------- problem constants ----------------
#define B_  4
#define T_  2048
#define C_  1024
#define H_  8
#define DH_ 128
#define DFF_ 4096
#define M_  (B_ * T_)            // 8192 rows

typedef __nv_bfloat16 bf16;

// ---------------- scratch (device globals, no allocation) ----------------
#define QKV_SZ (B_ * H_ * T_ * DH_)
__device__ bf16  g_h1h[M_ * C_],  g_h1l[M_ * C_];             // LN1 out hi/lo
__device__ bf16  g_q_h[QKV_SZ], g_q_l[QKV_SZ];
__device__ bf16  g_k_h[QKV_SZ], g_k_l[QKV_SZ];
__device__ float g_v  [QKV_SZ];
__device__ bf16  g_vT_h[QKV_SZ], g_vT_l[QKV_SZ];              // [z][Dh][T]
__device__ float g_sc[(size_t)B_ * H_ * T_ * T_];             // scores fp32
__device__ bf16  g_p_h[(size_t)B_ * H_ * T_ * T_];            // probs hi
__device__ bf16  g_p_l[(size_t)B_ * H_ * T_ * T_];            // probs lo
__device__ float g_x1[M_ * C_];                               // x + attn_out
__device__ bf16  g_h2h[M_ * C_], g_h2l[M_ * C_];              // LN2 out hi/lo
__device__ bf16  g_f1h[M_ * DFF_], g_f1l[M_ * DFF_];          // relu(h2 w1 + b1)
__device__ bf16  g_wTh[3 * H_ * DH_ * C_], g_wTl[3 * H_ * DH_ * C_];  // qkv w^T
__device__ bf16  g_w1Th[DFF_ * C_], g_w1Tl[DFF_ * C_];        // w1^T [Dff, C]
__device__ bf16  g_w2Th[C_ * DFF_], g_w2Tl[C_ * DFF_];        // w2^T [C, Dff]

// ---------------- low-level helpers ----------------
__device__ __forceinline__ uint32_t smem_u32(const void* p) {
    uint32_t a;
    asm("{ .reg .u64 t; cvta.to.shared.u64 t, %1; cvt.u32.u64 %0, t; }"
        : "=r"(a) : "l"(p));
    return a;
}
__device__ __forceinline__ void cp16(uint32_t dst, const void* src) {
    asm volatile("cp.async.cg.shared.global [%0], [%1], 16;\n"
                 :: "r"(dst), "l"(__cvta_generic_to_global(src)));
}
__device__ __forceinline__ void cp_commit() {
    asm volatile("cp.async.commit_group;\n" ::: "memory");
}
template<int N> __device__ __forceinline__ void cp_wait() {
    asm volatile("cp.async.wait_group %0;\n" :: "n"(N) : "memory");
}
__device__ __forceinline__ void ldsm4(uint32_t r[4], uint32_t addr) {
    asm volatile("ldmatrix.sync.aligned.m8n8.x4.shared.b16 {%0,%1,%2,%3}, [%4];"
        : "=r"(r[0]), "=r"(r[1]), "=r"(r[2]), "=r"(r[3]) : "r"(addr));
}
__device__ __forceinline__ void mma_bf16(float c[4], const uint32_t a[4],
                                         const uint32_t b0, const uint32_t b1) {
    asm volatile(
        "mma.sync.aligned.m16n8k16.row.col.f32.bf16.bf16.f32 "
        "{%0,%1,%2,%3}, {%4,%5,%6,%7}, {%8,%9}, {%0,%1,%2,%3};"
        : "+f"(c[0]), "+f"(c[1]), "+f"(c[2]), "+f"(c[3])
        : "r"(a[0]), "r"(a[1]), "r"(a[2]), "r"(a[3]), "r"(b0), "r"(b1));
}

// ---------------- smem geometry ----------------
// 4 mats per stage (Ah, Al, Bh, Bl), each 128 rows x 32 bf16, row stride 80B
// (80B = 20-bank stride -> ldmatrix 8-row groups hit all 32 banks exactly once).
#define ROWB   80
#define MATB   (128 * ROWB)        // 10240
#define STAGEB (4 * MATB)          // 40960
#define GEMM_SMEM (2 * STAGEB)     // 81920

// ---------------- stage loader: gmem -> smem via cp.async ----------------
__device__ __forceinline__ void issue_stage(
    uint32_t sbase, int buf,
    const bf16* __restrict__ Ah, const bf16* __restrict__ Al, int lda,
    const bf16* __restrict__ Bh, const bf16* __restrict__ Bl, int ldb, int k0)
{
    const int tid = threadIdx.x;
    const int mat = tid >> 6;
    const int t   = tid & 63;
    const bf16* src; int ld;
    if      (mat == 0) { src = Ah; ld = lda; }
    else if (mat == 1) { src = Al; ld = lda; }
    else if (mat == 2) { src = Bh; ld = ldb; }
    else               { src = Bl; ld = ldb; }
    uint32_t mbase = sbase + (uint32_t)buf * STAGEB + (uint32_t)mat * MATB;
    #pragma unroll
    for (int rr = 0; rr < 2; rr++) {
        int row = t * 2 + rr;
        const bf16* s = src + (size_t)row * ld + k0;
        uint32_t d = mbase + row * ROWB;
        #pragma unroll
        for (int seg = 0; seg < 4; seg++)
            cp16(d + seg * 16, s + seg * 8);
    }
    cp_commit();
}

// ---------------- block GEMM mainloop ----------------
// D(128x128 fp32) = (Ah+Al)(128xK) * (Bh+Bl)(128xK)^T, 3-term bf16 split.
// acc[mi][ni][4] per thread; warp (wid&3)->M32, (wid>>2)->N64.
// Term-major MMA order: 16 independent MMAs between accumulator reuses.
__device__ __forceinline__ void gemm_mainloop(
    float acc[2][8][4],
    const bf16* __restrict__ Ah, const bf16* __restrict__ Al, int lda,
    const bf16* __restrict__ Bh, const bf16* __restrict__ Bl, int ldb, int K)
{
    extern __shared__ char smem_raw[];
    uint32_t sbase = smem_u32(smem_raw);
    const int tid  = threadIdx.x;
    const int wid  = tid >> 5, lane = tid & 31;
    const int m0w  = (wid & 3) * 32;
    const int n0w  = (wid >> 2) * 64;
    const int g    = lane >> 3, lr = lane & 7;

    // A ldmatrix x4 offset: 16x16 tile (g&1 -> row 8-group, g>>1 -> 16B col half)
    const uint32_t a_off = (uint32_t)((m0w + (g & 1) * 8 + lr) * ROWB + (g >> 1) * 16);
    // B ldmatrix x4 offset: two n8 tiles per load (g>>1 -> n8 tile, g&1 -> 16B col half)
    const uint32_t b_off = (uint32_t)((n0w + (g >> 1) * 8 + lr) * ROWB + (g & 1) * 16);

    #pragma unroll
    for (int mi = 0; mi < 2; mi++)
        #pragma unroll
        for (int ni = 0; ni < 8; ni++)
            #pragma unroll
            for (int i = 0; i < 4; i++)
                acc[mi][ni][i] = 0.f;

    const int nstage = K >> 5;
    issue_stage(sbase, 0, Ah, Al, lda, Bh, Bl, ldb, 0);

    for (int c = 0; c < nstage; c++) {
        if (c + 1 < nstage) {
            issue_stage(sbase, (c + 1) & 1, Ah, Al, lda, Bh, Bl, ldb, (c + 1) << 5);
            cp_wait<1>();
        } else {
            cp_wait<0>();
        }
        __syncthreads();

        uint32_t st = sbase + (uint32_t)(c & 1) * STAGEB;
        #pragma unroll
        for (int ks = 0; ks < 2; ks++) {
            uint32_t kb = (uint32_t)ks * 32;        // k16 step = 32 bytes
            // load all fragments for this k16 step
            uint32_t ah[2][4], al[2][4];
            ldsm4(ah[0], st + 0 * MATB + a_off + kb);
            ldsm4(ah[1], st + 0 * MATB + a_off + kb + 16 * ROWB);
            ldsm4(al[0], st + 1 * MATB + a_off + kb);
            ldsm4(al[1], st + 1 * MATB + a_off + kb + 16 * ROWB);
            uint32_t bh[4][4], bl[4][4];            // [pair][2 ni x 2 regs]
            #pragma unroll
            for (int pn = 0; pn < 4; pn++) {
                ldsm4(bh[pn], st + 2 * MATB + b_off + kb + (uint32_t)pn * 16 * ROWB);
                ldsm4(bl[pn], st + 3 * MATB + b_off + kb + (uint32_t)pn * 16 * ROWB);
            }
            // term 1: ah * bh  (16 independent MMAs)
            #pragma unroll
            for (int ni = 0; ni < 8; ni++)
                #pragma unroll
                for (int mi = 0; mi < 2; mi++)
                    mma_bf16(acc[mi][ni], ah[mi], bh[ni >> 1][(ni & 1) * 2],
                                                   bh[ni >> 1][(ni & 1) * 2 + 1]);
            // term 2: ah * bl
            #pragma unroll
            for (int ni = 0; ni < 8; ni++)
                #pragma unroll
                for (int mi = 0; mi < 2; mi++)
                    mma_bf16(acc[mi][ni], ah[mi], bl[ni >> 1][(ni & 1) * 2],
                                                   bl[ni >> 1][(ni & 1) * 2 + 1]);
            // term 3: al * bh
            #pragma unroll
            for (int ni = 0; ni < 8; ni++)
                #pragma unroll
                for (int mi = 0; mi < 2; mi++)
                    mma_bf16(acc[mi][ni], al[mi], bh[ni >> 1][(ni & 1) * 2],
                                                   bh[ni >> 1][(ni & 1) * 2 + 1]);
        }
        __syncthreads();
    }
}

// epilogue iteration: calls f(ml, nl, float2) for this thread's 32 output pairs
template<class F>
__device__ __forceinline__ void epilogue_loop(float acc[2][8][4], F f)
{
    const int wid = threadIdx.x >> 5, lane = threadIdx.x & 31;
    const int m0w = (wid & 3) * 32, n0w = (wid >> 2) * 64;
    const int lr = lane >> 2, lc = (lane & 3) * 2;
    #pragma unroll
    for (int mi = 0; mi < 2; mi++)
        #pragma unroll
        for (int hf = 0; hf < 2; hf++) {
            const int ml = m0w + mi * 16 + hf * 8 + lr;
            #pragma unroll
            for (int ni = 0; ni < 8; ni++) {
                const int nl = n0w + ni * 8 + lc;
                f(ml, nl, make_float2(acc[mi][ni][hf * 2], acc[mi][ni][hf * 2 + 1]));
            }
        }
}

__device__ __forceinline__ void store_hilo2(bf16* oh, bf16* ol, float2 v) {
    bf16 h0 = __float2bfloat16_rn(v.x);
    bf16 h1 = __float2bfloat16_rn(v.y);
    __nv_bfloat162 hh; hh.x = h0; hh.y = h1;
    __nv_bfloat162 ll;
    ll.x = __float2bfloat16_rn(v.x - __bfloat162float(h0));
    ll.y = __float2bfloat16_rn(v.y - __bfloat162float(h1));
    *reinterpret_cast<__nv_bfloat162*>(oh) = hh;
    *reinterpret_cast<__nv_bfloat162*>(ol) = ll;
}

// ============================================================================
// GEMM kernels
// ============================================================================
__global__ void __launch_bounds__(256) qkv_gemm()
{
    int m0   = blockIdx.x * 128;
    int sel  = blockIdx.y >> 3;
    int head = blockIdx.y & 7;
    size_t woff = (size_t)blockIdx.y * DH_ * C_;
    float acc[2][8][4];
    gemm_mainloop(acc,
        g_h1h + (size_t)m0 * C_, g_h1l + (size_t)m0 * C_, C_,
        g_wTh + woff,            g_wTl + woff,            C_, C_);

    const float AL = 11.313708498984761f;   // sqrt(128) folded into q
    epilogue_loop(acc, [&](int ml, int nl, float2 vv) {
        int m = m0 + ml, b = m >> 11, t = m & (T_ - 1);
        size_t base = ((size_t)(b * H_ + head) * T_ + t) * DH_ + nl;
        if (sel == 0)      store_hilo2(g_q_h + base, g_q_l + base,
                                       make_float2(vv.x * AL, vv.y * AL));
        else if (sel == 1) store_hilo2(g_k_h + base, g_k_l + base, vv);
        else               *(float2*)(g_v + base) = vv;
    });
}

__global__ void __launch_bounds__(256) qk_gemm()
{
    int z = blockIdx.z, m0 = blockIdx.x * 128, n0 = blockIdx.y * 128;
    size_t zb = (size_t)z * T_ * DH_;
    float acc[2][8][4];
    gemm_mainloop(acc,
        g_q_h + zb + (size_t)m0 * DH_, g_q_l + zb + (size_t)m0 * DH_, DH_,
        g_k_h + zb + (size_t)n0 * DH_, g_k_l + zb + (size_t)n0 * DH_, DH_, DH_);

    float* outp = g_sc + (size_t)z * T_ * T_;
    epilogue_loop(acc, [&](int ml, int nl, float2 vv) {
        *(float2*)(outp + (size_t)(m0 + ml) * T_ + n0 + nl) = vv;
    });
}

__global__ void __launch_bounds__(256) pv_gemm(const float* __restrict__ x)
{
    int z = blockIdx.z, m0 = blockIdx.x * 128;
    int b = z >> 3, head = z & 7;
    size_t pb = (size_t)z * T_ * T_ + (size_t)m0 * T_;
    size_t vb = (size_t)z * DH_ * T_;
    float acc[2][8][4];
    gemm_mainloop(acc,
        g_p_h + pb, g_p_l + pb, T_,
        g_vT_h + vb, g_vT_l + vb, T_, T_);

    epilogue_loop(acc, [&](int ml, int nl, float2 vv) {
        int t = m0 + ml;
        size_t idx = ((size_t)(b * T_ + t)) * C_ + head * DH_ + nl;
        float2 xr = *(const float2*)(x + idx);
        *(float2*)(g_x1 + idx) = make_float2(vv.x + xr.x, vv.y + xr.y);
    });
}

__global__ void __launch_bounds__(256) ff1_gemm(const float* __restrict__ b1)
{
    int m0 = blockIdx.x * 128, n0 = blockIdx.y * 128;
    float acc[2][8][4];
    gemm_mainloop(acc,
        g_h2h + (size_t)m0 * C_,  g_h2l + (size_t)m0 * C_,  C_,
        g_w1Th + (size_t)n0 * C_, g_w1Tl + (size_t)n0 * C_, C_, C_);

    epilogue_loop(acc, [&](int ml, int nl, float2 vv) {
        float2 bb = *(const float2*)(b1 + n0 + nl);
        float r0 = fmaxf(vv.x + bb.x, 0.f);
        float r1 = fmaxf(vv.y + bb.y, 0.f);
        size_t base = (size_t)(m0 + ml) * DFF_ + n0 + nl;
        store_hilo2(g_f1h + base, g_f1l + base, make_float2(r0, r1));
    });
}

__global__ void __launch_bounds__(256) ff2_gemm(const float* __restrict__ b2,
                                                float* __restrict__ out)
{
    int m0 = blockIdx.x * 128, n0 = blockIdx.y * 128;
    float acc[2][8][4];
    gemm_mainloop(acc,
        g_f1h + (size_t)m0 * DFF_,  g_f1l + (size_t)m0 * DFF_,  DFF_,
        g_w2Th + (size_t)n0 * DFF_, g_w2Tl + (size_t)n0 * DFF_, DFF_, DFF_);

    epilogue_loop(acc, [&](int ml, int nl, float2 vv) {
        float2 bb = *(const float2*)(b2 + n0 + nl);
        size_t idx = (size_t)(m0 + ml) * C_ + n0 + nl;
        float2 xr = *(const float2*)(g_x1 + idx);
        *(float2*)(out + idx) = make_float2(vv.x + bb.x + xr.x,
                                            vv.y + bb.y + xr.y);
    });
}

// ============================================================================
// transpose + bf16 hi/lo convert: in [R, Cc] fp32 -> out [Cc, R] hi/lo
// ============================================================================
__global__ void transpose_conv(const float* __restrict__ in, bf16* __restrict__ oh,
                               bf16* __restrict__ ol, int R, int Cc,
                               size_t in_bstride, size_t out_bstride)
{
    __shared__ float tile[32][33];
    const float* src = in + (size_t)blockIdx.z * in_bstride;
    int c0 = blockIdx.x * 32, r0 = blockIdx.y * 32;
    int tx = threadIdx.x, ty = threadIdx.y;          // 32 x 8
    #pragma unroll
    for (int i = 0; i < 32; i += 8)
        tile[ty + i][tx] = src[(size_t)(r0 + ty + i) * Cc + c0 + tx];
    __syncthreads();
    #pragma unroll
    for (int i = 0; i < 32; i += 8) {
        float v = tile[tx][ty + i];
        bf16 h = __float2bfloat16_rn(v);
        bf16 l = __float2bfloat16_rn(v - __bfloat162float(h));
        size_t o = (size_t)blockIdx.z * out_bstride + (size_t)(c0 + ty + i) * R + r0 + tx;
        oh[o] = h; ol[o] = l;
    }
}

// ============================================================================
// LayerNorm -> bf16 hi/lo
// ============================================================================
__device__ __forceinline__ void block_reduce2(float& a, float& b)
{
    #pragma unroll
    for (int o = 16; o; o >>= 1) {
        a += __shfl_xor_sync(0xFFFFFFFFu, a, o);
        b += __shfl_xor_sync(0xFFFFFFFFu, b, o);
    }
    __shared__ float sa[8], sb_[8];
    int w = threadIdx.x >> 5, l = threadIdx.x & 31;
    if (l == 0) { sa[w] = a; sb_[w] = b; }
    __syncthreads();
    a = 0.f; b = 0.f;
    #pragma unroll
    for (int i = 0; i < 8; i++) { a += sa[i]; b += sb_[i]; }
}

__global__ void ln_kernel(const float* __restrict__ x, const float* __restrict__ g,
                          const float* __restrict__ bb, bf16* __restrict__ oh,
                          bf16* __restrict__ ol)
{
    size_t row = blockIdx.x;
    float4 v = ((const float4*)(x + row * C_))[threadIdx.x];
    float s  = v.x + v.y + v.z + v.w;
    float sq = v.x*v.x + v.y*v.y + v.z*v.z + v.w*v.w;
    block_reduce2(s, sq);
    float mean = s * (1.0f / C_);
    float var  = sq * (1.0f / C_) - mean * mean;
    float inv  = rsqrtf(var + 1e-5f);
    float4 gv = ((const float4*)g)[threadIdx.x];
    float4 bv = ((const float4*)bb)[threadIdx.x];
    float o0 = (v.x - mean) * inv * gv.x + bv.x;
    float o1 = (v.y - mean) * inv * gv.y + bv.y;
    float o2 = (v.z - mean) * inv * gv.z + bv.z;
    float o3 = (v.w - mean) * inv * gv.w + bv.w;
    size_t base = row * C_ + threadIdx.x * 4;
    store_hilo2(oh + base,     ol + base,     make_float2(o0, o1));
    store_hilo2(oh + base + 2, ol + base + 2, make_float2(o2, o3));
}

// ============================================================================
// row softmax over 2048, fp32 scores in -> bf16 hi/lo probs out
// ============================================================================
__global__ void softmax_kernel()
{
    size_t row = blockIdx.x;
    const float* p = g_sc + row * T_;
    float4 v0 = *(const float4*)(p + threadIdx.x * 8);
    float4 v1 = *(const float4*)(p + threadIdx.x * 8 + 4);

    float mx = fmaxf(fmaxf(fmaxf(v0.x, v0.y), fmaxf(v0.z, v0.w)),
                     fmaxf(fmaxf(v1.x, v1.y), fmaxf(v1.z, v1.w)));
    #pragma unroll
    for (int o = 16; o; o >>= 1) mx = fmaxf(mx, __shfl_xor_sync(0xFFFFFFFFu, mx, o));
    __shared__ float sm[8];
    int w = threadIdx.x >> 5, l = threadIdx.x & 31;
    if (l == 0) sm[w] = mx;
    __syncthreads();
    mx = fmaxf(fmaxf(fmaxf(sm[0], sm[1]), fmaxf(sm[2], sm[3])),
               fmaxf(fmaxf(sm[4], sm[5]), fmaxf(sm[6], sm[7])));

    v0.x = expf(v0.x - mx); v0.y = expf(v0.y - mx); v0.z = expf(v0.z - mx); v0.w = expf(v0.w - mx);
    v1.x = expf(v1.x - mx); v1.y = expf(v1.y - mx); v1.z = expf(v1.z - mx); v1.w = expf(v1.w - mx);
    float s = v0.x + v0.y + v0.z + v0.w + v1.x + v1.y + v1.z + v1.w;
    float s2 = s;
    __syncthreads();
    block_reduce2(s, s2);
    float inv = 1.0f / s;
    float vals[8] = {v0.x*inv, v0.y*inv, v0.z*inv, v0.w*inv,
                     v1.x*inv, v1.y*inv, v1.z*inv, v1.w*inv};
    size_t base = row * T_ + threadIdx.x * 8;
    #pragma unroll
    for (int j = 0; j < 8; j += 2)
        store_hilo2(g_p_h + base + j, g_p_l + base + j,
                    make_float2(vals[j], vals[j + 1]));
}

// ============================================================================
// host
// ============================================================================
extern "C" void kernel_launch(void* const* d_in, const int* in_sizes, int n_in,
                              void* d_out, int out_size)
{
    const float* x     = (const float*)d_in[0];
    const float* wq    = (const float*)d_in[1];
    const float* wk    = (const float*)d_in[2];
    const float* wv    = (const float*)d_in[3];
    const float* w1    = (const float*)d_in[4];
    const float* b1    = (const float*)d_in[5];
    const float* w2    = (const float*)d_in[6];
    const float* b2    = (const float*)d_in[7];
    const float* ln1_g = (const float*)d_in[8];
    const float* ln1_b = (const float*)d_in[9];
    const float* ln2_g = (const float*)d_in[10];
    const float* ln2_b = (const float*)d_in[11];
    float* out = (float*)d_out;

    cudaFuncSetAttribute(qkv_gemm, cudaFuncAttributeMaxDynamicSharedMemorySize, GEMM_SMEM);
    cudaFuncSetAttribute(qk_gemm,  cudaFuncAttributeMaxDynamicSharedMemorySize, GEMM_SMEM);
    cudaFuncSetAttribute(pv_gemm,  cudaFuncAttributeMaxDynamicSharedMemorySize, GEMM_SMEM);
    cudaFuncSetAttribute(ff1_gemm, cudaFuncAttributeMaxDynamicSharedMemorySize, GEMM_SMEM);
    cudaFuncSetAttribute(ff2_gemm, cudaFuncAttributeMaxDynamicSharedMemorySize, GEMM_SMEM);

    bf16 *p_h1h, *p_h1l, *p_h2h, *p_h2l, *p_wTh, *p_wTl, *p_w1Th, *p_w1Tl, *p_w2Th, *p_w2Tl;
    bf16 *p_vTh, *p_vTl;
    float *p_x1, *p_v;
    cudaGetSymbolAddress((void**)&p_h1h, g_h1h);
    cudaGetSymbolAddress((void**)&p_h1l, g_h1l);
    cudaGetSymbolAddress((void**)&p_h2h, g_h2h);
    cudaGetSymbolAddress((void**)&p_h2l, g_h2l);
    cudaGetSymbolAddress((void**)&p_wTh, g_wTh);
    cudaGetSymbolAddress((void**)&p_wTl, g_wTl);
    cudaGetSymbolAddress((void**)&p_w1Th, g_w1Th);
    cudaGetSymbolAddress((void**)&p_w1Tl, g_w1Tl);
    cudaGetSymbolAddress((void**)&p_w2Th, g_w2Th);
    cudaGetSymbolAddress((void**)&p_w2Tl, g_w2Tl);
    cudaGetSymbolAddress((void**)&p_vTh, g_vT_h);
    cudaGetSymbolAddress((void**)&p_vTl, g_vT_l);
    cudaGetSymbolAddress((void**)&p_x1, g_x1);
    cudaGetSymbolAddress((void**)&p_v,  g_v);

    dim3 tb(32, 8);
    // weight transposes -> [N, K] bf16 hi/lo
    transpose_conv<<<dim3(DH_/32, C_/32, H_), tb>>>(wq, p_wTh, p_wTl, C_, DH_, (size_t)C_*DH_, (size_t)DH_*C_);
    transpose_conv<<<dim3(DH_/32, C_/32, H_), tb>>>(wk, p_wTh + (size_t)H_*DH_*C_, p_wTl + (size_t)H_*DH_*C_, C_, DH_, (size_t)C_*DH_, (size_t)DH_*C_);
    transpose_conv<<<dim3(DH_/32, C_/32, H_), tb>>>(wv, p_wTh + (size_t)2*H_*DH_*C_, p_wTl + (size_t)2*H_*DH_*C_, C_, DH_, (size_t)C_*DH_, (size_t)DH_*C_);
    transpose_conv<<<dim3(DFF_/32, C_/32, 1), tb>>>(w1, p_w1Th, p_w1Tl, C_, DFF_, 0, 0);
    transpose_conv<<<dim3(C_/32, DFF_/32, 1), tb>>>(w2, p_w2Th, p_w2Tl, DFF_, C_, 0, 0);

    // 1. LN1 -> h1 hi/lo
    ln_kernel<<<M_, 256>>>(x, ln1_g, ln1_b, p_h1h, p_h1l);
    // 2. QKV projections (q pre-scaled by sqrt(128))
    qkv_gemm<<<dim3(M_/128, 3*H_, 1), 256, GEMM_SMEM>>>();
    // 3. v transpose -> [z][Dh][T] hi/lo
    transpose_conv<<<dim3(DH_/32, T_/32, B_*H_), tb>>>(p_v, p_vTh, p_vTl, T_, DH_, (size_t)T_*DH_, (size_t)DH_*T_);
    // 4. scores
    qk_gemm<<<dim3(T_/128, T_/128, B_*H_), 256, GEMM_SMEM>>>();
    // 5. softmax -> probs hi/lo
    softmax_kernel<<<B_*H_*T_, 256>>>();
    // 6. attention out + residual -> x1
    pv_gemm<<<dim3(T_/128, 1, B_*H_), 256, GEMM_SMEM>>>(x);
    // 7. LN2 -> h2 hi/lo
    ln_kernel<<<M_, 256>>>(p_x1, ln2_g, ln2_b, p_h2h, p_h2l);
    // 8. FF1 -> f1 hi/lo
    ff1_gemm<<<dim3(M_/128, DFF_/128, 1), 256, GEMM_SMEM>>>(b1);
    // 9. FF2 (+bias +residual) -> out
    ff2_gemm<<<dim3(M_/128, C_/128, 1), 256, GEMM_SMEM>>>(b2, out);
}

// round 8
// speedup vs baseline: 1.2100x; 1.1123x over previous
#include <cuda_runtime.h>
#include <cuda_bf16.h>
#include <cstdint>
#include <math.h>

// ---------------- problem constants ----------------
#define B_  4
#define T_  2048
#define C_  1024
#define H_  8
#define DH_ 128
#define DFF_ 4096
#define M_  (B_ * T_)            // 8192 rows

typedef __nv_bfloat16 bf16;

// ---------------- scratch (device globals, no allocation) ----------------
#define QKV_SZ (B_ * H_ * T_ * DH_)
__device__ bf16  g_h1h[M_ * C_],  g_h1l[M_ * C_];             // LN1 out hi/lo
__device__ bf16  g_q_h[QKV_SZ], g_q_l[QKV_SZ];                // q (pre-scaled sqrt(128))
__device__ bf16  g_k_h[QKV_SZ], g_k_l[QKV_SZ];
__device__ float g_v  [QKV_SZ];
__device__ bf16  g_vT_h[QKV_SZ], g_vT_l[QKV_SZ];              // [z][Dh][T]
__device__ float g_x1[M_ * C_];                               // x + attn_out
__device__ bf16  g_h2h[M_ * C_], g_h2l[M_ * C_];              // LN2 out hi/lo
__device__ bf16  g_f1h[M_ * DFF_], g_f1l[M_ * DFF_];          // relu(h2 w1 + b1)
__device__ bf16  g_wTh[3 * H_ * DH_ * C_], g_wTl[3 * H_ * DH_ * C_];  // qkv w^T
__device__ bf16  g_w1Th[DFF_ * C_], g_w1Tl[DFF_ * C_];        // w1^T [Dff, C]
__device__ bf16  g_w2Th[C_ * DFF_], g_w2Tl[C_ * DFF_];        // w2^T [C, Dff]

// ---------------- low-level helpers ----------------
__device__ __forceinline__ uint32_t smem_u32(const void* p) {
    uint32_t a;
    asm("{ .reg .u64 t; cvta.to.shared.u64 t, %1; cvt.u32.u64 %0, t; }"
        : "=r"(a) : "l"(p));
    return a;
}
__device__ __forceinline__ void cp16(uint32_t dst, const void* src) {
    asm volatile("cp.async.cg.shared.global [%0], [%1], 16;\n"
                 :: "r"(dst), "l"(__cvta_generic_to_global(src)));
}
__device__ __forceinline__ void cp_commit() {
    asm volatile("cp.async.commit_group;\n" ::: "memory");
}
template<int N> __device__ __forceinline__ void cp_wait() {
    asm volatile("cp.async.wait_group %0;\n" :: "n"(N) : "memory");
}
__device__ __forceinline__ void ldsm4(uint32_t r[4], uint32_t addr) {
    asm volatile("ldmatrix.sync.aligned.m8n8.x4.shared.b16 {%0,%1,%2,%3}, [%4];"
        : "=r"(r[0]), "=r"(r[1]), "=r"(r[2]), "=r"(r[3]) : "r"(addr));
}
__device__ __forceinline__ void mma_bf16(float c[4], const uint32_t a[4],
                                         const uint32_t b0, const uint32_t b1) {
    asm volatile(
        "mma.sync.aligned.m16n8k16.row.col.f32.bf16.bf16.f32 "
        "{%0,%1,%2,%3}, {%4,%5,%6,%7}, {%8,%9}, {%0,%1,%2,%3};"
        : "+f"(c[0]), "+f"(c[1]), "+f"(c[2]), "+f"(c[3])
        : "r"(a[0]), "r"(a[1]), "r"(a[2]), "r"(a[3]), "r"(b0), "r"(b1));
}
__device__ __forceinline__ uint32_t pack_hi(float a, float b) {
    __nv_bfloat162 t; t.x = __float2bfloat16_rn(a); t.y = __float2bfloat16_rn(b);
    return *(uint32_t*)&t;
}
__device__ __forceinline__ uint32_t pack_lo(float a, float b) {
    bf16 ha = __float2bfloat16_rn(a), hb = __float2bfloat16_rn(b);
    __nv_bfloat162 t;
    t.x = __float2bfloat16_rn(a - __bfloat162float(ha));
    t.y = __float2bfloat16_rn(b - __bfloat162float(hb));
    return *(uint32_t*)&t;
}

// ---------------- GEMM smem geometry (qkv / ff1 / ff2) ----------------
#define ROWB   80
#define MATB   (128 * ROWB)        // 10240
#define STAGEB (4 * MATB)          // 40960
#define GEMM_SMEM (2 * STAGEB)     // 81920

__device__ __forceinline__ void issue_stage(
    uint32_t sbase, int buf,
    const bf16* __restrict__ Ah, const bf16* __restrict__ Al, int lda,
    const bf16* __restrict__ Bh, const bf16* __restrict__ Bl, int ldb, int k0)
{
    const int tid = threadIdx.x;
    const int mat = tid >> 6;
    const int t   = tid & 63;
    const bf16* src; int ld;
    if      (mat == 0) { src = Ah; ld = lda; }
    else if (mat == 1) { src = Al; ld = lda; }
    else if (mat == 2) { src = Bh; ld = ldb; }
    else               { src = Bl; ld = ldb; }
    uint32_t mbase = sbase + (uint32_t)buf * STAGEB + (uint32_t)mat * MATB;
    #pragma unroll
    for (int rr = 0; rr < 2; rr++) {
        int row = t * 2 + rr;
        const bf16* s = src + (size_t)row * ld + k0;
        uint32_t d = mbase + row * ROWB;
        #pragma unroll
        for (int seg = 0; seg < 4; seg++)
            cp16(d + seg * 16, s + seg * 8);
    }
    cp_commit();
}

__device__ __forceinline__ void gemm_mainloop(
    float acc[2][8][4],
    const bf16* __restrict__ Ah, const bf16* __restrict__ Al, int lda,
    const bf16* __restrict__ Bh, const bf16* __restrict__ Bl, int ldb, int K)
{
    extern __shared__ char smem_raw[];
    uint32_t sbase = smem_u32(smem_raw);
    const int tid  = threadIdx.x;
    const int wid  = tid >> 5, lane = tid & 31;
    const int m0w  = (wid & 3) * 32;
    const int n0w  = (wid >> 2) * 64;
    const int g    = lane >> 3, lr = lane & 7;

    const uint32_t a_off = (uint32_t)((m0w + (g & 1) * 8 + lr) * ROWB + (g >> 1) * 16);
    const uint32_t b_off = (uint32_t)((n0w + (g >> 1) * 8 + lr) * ROWB + (g & 1) * 16);

    #pragma unroll
    for (int mi = 0; mi < 2; mi++)
        #pragma unroll
        for (int ni = 0; ni < 8; ni++)
            #pragma unroll
            for (int i = 0; i < 4; i++)
                acc[mi][ni][i] = 0.f;

    const int nstage = K >> 5;
    issue_stage(sbase, 0, Ah, Al, lda, Bh, Bl, ldb, 0);

    for (int c = 0; c < nstage; c++) {
        if (c + 1 < nstage) {
            issue_stage(sbase, (c + 1) & 1, Ah, Al, lda, Bh, Bl, ldb, (c + 1) << 5);
            cp_wait<1>();
        } else {
            cp_wait<0>();
        }
        __syncthreads();

        uint32_t st = sbase + (uint32_t)(c & 1) * STAGEB;
        #pragma unroll
        for (int ks = 0; ks < 2; ks++) {
            uint32_t kb = (uint32_t)ks * 32;
            uint32_t ah[2][4], al[2][4];
            ldsm4(ah[0], st + 0 * MATB + a_off + kb);
            ldsm4(ah[1], st + 0 * MATB + a_off + kb + 16 * ROWB);
            ldsm4(al[0], st + 1 * MATB + a_off + kb);
            ldsm4(al[1], st + 1 * MATB + a_off + kb + 16 * ROWB);
            uint32_t bh[4][4], bl[4][4];
            #pragma unroll
            for (int pn = 0; pn < 4; pn++) {
                ldsm4(bh[pn], st + 2 * MATB + b_off + kb + (uint32_t)pn * 16 * ROWB);
                ldsm4(bl[pn], st + 3 * MATB + b_off + kb + (uint32_t)pn * 16 * ROWB);
            }
            #pragma unroll
            for (int ni = 0; ni < 8; ni++)
                #pragma unroll
                for (int mi = 0; mi < 2; mi++)
                    mma_bf16(acc[mi][ni], ah[mi], bh[ni >> 1][(ni & 1) * 2],
                                                   bh[ni >> 1][(ni & 1) * 2 + 1]);
            #pragma unroll
            for (int ni = 0; ni < 8; ni++)
                #pragma unroll
                for (int mi = 0; mi < 2; mi++)
                    mma_bf16(acc[mi][ni], ah[mi], bl[ni >> 1][(ni & 1) * 2],
                                                   bl[ni >> 1][(ni & 1) * 2 + 1]);
            #pragma unroll
            for (int ni = 0; ni < 8; ni++)
                #pragma unroll
                for (int mi = 0; mi < 2; mi++)
                    mma_bf16(acc[mi][ni], al[mi], bh[ni >> 1][(ni & 1) * 2],
                                                   bh[ni >> 1][(ni & 1) * 2 + 1]);
        }
        __syncthreads();
    }
}

template<class F>
__device__ __forceinline__ void epilogue_loop(float acc[2][8][4], F f)
{
    const int wid = threadIdx.x >> 5, lane = threadIdx.x & 31;
    const int m0w = (wid & 3) * 32, n0w = (wid >> 2) * 64;
    const int lr = lane >> 2, lc = (lane & 3) * 2;
    #pragma unroll
    for (int mi = 0; mi < 2; mi++)
        #pragma unroll
        for (int hf = 0; hf < 2; hf++) {
            const int ml = m0w + mi * 16 + hf * 8 + lr;
            #pragma unroll
            for (int ni = 0; ni < 8; ni++) {
                const int nl = n0w + ni * 8 + lc;
                f(ml, nl, make_float2(acc[mi][ni][hf * 2], acc[mi][ni][hf * 2 + 1]));
            }
        }
}

__device__ __forceinline__ void store_hilo2(bf16* oh, bf16* ol, float2 v) {
    bf16 h0 = __float2bfloat16_rn(v.x);
    bf16 h1 = __float2bfloat16_rn(v.y);
    __nv_bfloat162 hh; hh.x = h0; hh.y = h1;
    __nv_bfloat162 ll;
    ll.x = __float2bfloat16_rn(v.x - __bfloat162float(h0));
    ll.y = __float2bfloat16_rn(v.y - __bfloat162float(h1));
    *reinterpret_cast<__nv_bfloat162*>(oh) = hh;
    *reinterpret_cast<__nv_bfloat162*>(ol) = ll;
}

// ============================================================================
// Flash attention smem geometry
// ============================================================================
#define KT     64                      // keys per tile
#define NKT    (T_ / KT)               // 32 tiles
#define QROW   272                     // 256B data + 16B pad (4r%32 bank walk)
#define KROW   272
#define VROW   144                     // 128B data + 16B pad
#define SM_QH  0
#define SM_QL  34816                   // 128*272
#define SM_K0  69632
#define STG_KH 0
#define STG_KL 17408                   // 64*272
#define STG_VH 34816
#define STG_VL 53248                   // + 128*144
#define STGB   71680
#define FLASH_SMEM 212992              // 69632 + 2*71680

__device__ __forceinline__ void issue_kv_stage(uint32_t sb, int buf,
                                               size_t koff, size_t voff, int j)
{
    uint32_t st = sb + SM_K0 + (uint32_t)buf * STGB;
    const int tid = threadIdx.x;
    {   // K tile: 64 rows(keys) x 256B, hi & lo
        int r = tid >> 2;
        int seg0 = (tid & 3) * 4;
        const bf16* sh = g_k_h + koff + (size_t)(j * KT + r) * DH_ + seg0 * 8;
        const bf16* sl = g_k_l + koff + (size_t)(j * KT + r) * DH_ + seg0 * 8;
        uint32_t dh_ = st + STG_KH + r * KROW + seg0 * 16;
        uint32_t dl_ = st + STG_KL + r * KROW + seg0 * 16;
        #pragma unroll
        for (int s = 0; s < 4; s++) { cp16(dh_ + s * 16, sh + s * 8);
                                      cp16(dl_ + s * 16, sl + s * 8); }
    }
    {   // V tile: 128 rows(dh) x 128B (keys j*KT..), hi & lo
        int r = tid >> 1;
        int seg0 = (tid & 1) * 4;
        const bf16* sh = g_vT_h + voff + (size_t)r * T_ + j * KT + seg0 * 8;
        const bf16* sl = g_vT_l + voff + (size_t)r * T_ + j * KT + seg0 * 8;
        uint32_t dh_ = st + STG_VH + r * VROW + seg0 * 16;
        uint32_t dl_ = st + STG_VL + r * VROW + seg0 * 16;
        #pragma unroll
        for (int s = 0; s < 4; s++) { cp16(dh_ + s * 16, sh + s * 8);
                                      cp16(dl_ + s * 16, sl + s * 8); }
    }
    cp_commit();
}

// ============================================================================
// Flash attention: per-CTA 128 q rows x full 2048 keys; warp = 16-row strip.
// S-acc registers re-used directly as PV A-fragments (layout identity).
// ============================================================================
__global__ void __launch_bounds__(256) flash_attn(const float* __restrict__ x)
{
    extern __shared__ char smem_raw[];
    uint32_t sb = smem_u32(smem_raw);
    const int tid = threadIdx.x, wid = tid >> 5, lane = tid & 31;
    const int z = blockIdx.y;
    const int m0 = blockIdx.x * 128;
    const int b = z >> 3, head = z & 7;
    const size_t qoff = (size_t)z * T_ * DH_ + (size_t)m0 * DH_;
    const size_t koff = (size_t)z * T_ * DH_;
    const size_t voff = (size_t)z * DH_ * T_;

    // Q -> smem (its own cp.async group)
    {
        int r = tid >> 1, half = tid & 1;
        const bf16* sh = g_q_h + qoff + (size_t)r * DH_ + half * 64;
        const bf16* sl = g_q_l + qoff + (size_t)r * DH_ + half * 64;
        uint32_t dh_ = sb + SM_QH + r * QROW + half * 128;
        uint32_t dl_ = sb + SM_QL + r * QROW + half * 128;
        #pragma unroll
        for (int s = 0; s < 8; s++) { cp16(dh_ + s * 16, sh + s * 8);
                                      cp16(dl_ + s * 16, sl + s * 8); }
        cp_commit();
    }
    issue_kv_stage(sb, 0, koff, voff, 0);

    const int g = lane >> 3, lr8 = lane & 7;
    const uint32_t qa  = (uint32_t)((wid * 16 + (g & 1) * 8 + lr8) * QROW + (g >> 1) * 16);
    const uint32_t kbo = (uint32_t)(((g >> 1) * 8 + lr8) * KROW + (g & 1) * 16);
    const uint32_t vbo = (uint32_t)(((g >> 1) * 8 + lr8) * VROW + (g & 1) * 16);

    float o_[16][4];
    #pragma unroll
    for (int i = 0; i < 16; i++) { o_[i][0] = o_[i][1] = o_[i][2] = o_[i][3] = 0.f; }
    float m0r = -1e30f, m1r = -1e30f, l0r = 0.f, l1r = 0.f;

    for (int j = 0; j < NKT; j++) {
        if (j + 1 < NKT) { issue_kv_stage(sb, (j + 1) & 1, koff, voff, j + 1); cp_wait<1>(); }
        else             { cp_wait<0>(); }
        __syncthreads();

        uint32_t st = sb + SM_K0 + (uint32_t)(j & 1) * STGB;
        // ---- S = Q K^T   (strip 16 x 64 keys, k = 128 dh)
        float s_[8][4];
        #pragma unroll
        for (int i = 0; i < 8; i++) { s_[i][0] = s_[i][1] = s_[i][2] = s_[i][3] = 0.f; }
        #pragma unroll
        for (int ks = 0; ks < 8; ks++) {
            uint32_t qh_[4], ql_[4];
            ldsm4(qh_, sb + SM_QH + qa + ks * 32);
            ldsm4(ql_, sb + SM_QL + qa + ks * 32);
            #pragma unroll
            for (int pn = 0; pn < 4; pn++) {
                uint32_t kh_[4], kl_[4];
                ldsm4(kh_, st + STG_KH + kbo + pn * (16 * KROW) + ks * 32);
                ldsm4(kl_, st + STG_KL + kbo + pn * (16 * KROW) + ks * 32);
                mma_bf16(s_[2*pn],   qh_, kh_[0], kh_[1]);
                mma_bf16(s_[2*pn+1], qh_, kh_[2], kh_[3]);
                mma_bf16(s_[2*pn],   qh_, kl_[0], kl_[1]);
                mma_bf16(s_[2*pn+1], qh_, kl_[2], kl_[3]);
                mma_bf16(s_[2*pn],   ql_, kh_[0], kh_[1]);
                mma_bf16(s_[2*pn+1], ql_, kh_[2], kh_[3]);
            }
        }
        // ---- online softmax (rows lr=lane>>2 and lr+8; 4 lanes per row)
        float tm0 = -1e30f, tm1 = -1e30f;
        #pragma unroll
        for (int i = 0; i < 8; i++) {
            tm0 = fmaxf(tm0, fmaxf(s_[i][0], s_[i][1]));
            tm1 = fmaxf(tm1, fmaxf(s_[i][2], s_[i][3]));
        }
        tm0 = fmaxf(tm0, __shfl_xor_sync(0xFFFFFFFFu, tm0, 1));
        tm0 = fmaxf(tm0, __shfl_xor_sync(0xFFFFFFFFu, tm0, 2));
        tm1 = fmaxf(tm1, __shfl_xor_sync(0xFFFFFFFFu, tm1, 1));
        tm1 = fmaxf(tm1, __shfl_xor_sync(0xFFFFFFFFu, tm1, 2));
        float mn0 = fmaxf(m0r, tm0), mn1 = fmaxf(m1r, tm1);
        float sc0 = expf(m0r - mn0), sc1 = expf(m1r - mn1);
        m0r = mn0; m1r = mn1;
        float sum0 = 0.f, sum1 = 0.f;
        #pragma unroll
        for (int i = 0; i < 8; i++) {
            s_[i][0] = expf(s_[i][0] - mn0); s_[i][1] = expf(s_[i][1] - mn0);
            s_[i][2] = expf(s_[i][2] - mn1); s_[i][3] = expf(s_[i][3] - mn1);
            sum0 += s_[i][0] + s_[i][1];     sum1 += s_[i][2] + s_[i][3];
        }
        sum0 += __shfl_xor_sync(0xFFFFFFFFu, sum0, 1);
        sum0 += __shfl_xor_sync(0xFFFFFFFFu, sum0, 2);
        sum1 += __shfl_xor_sync(0xFFFFFFFFu, sum1, 1);
        sum1 += __shfl_xor_sync(0xFFFFFFFFu, sum1, 2);
        l0r = l0r * sc0 + sum0; l1r = l1r * sc1 + sum1;
        #pragma unroll
        for (int i = 0; i < 16; i++) {
            o_[i][0] *= sc0; o_[i][1] *= sc0; o_[i][2] *= sc1; o_[i][3] *= sc1;
        }
        // ---- O += P V   (A = P from registers, k = 64 keys, n = 128 dh)
        #pragma unroll
        for (int kk = 0; kk < 4; kk++) {
            uint32_t ah_[4], al_[4];
            ah_[0] = pack_hi(s_[2*kk][0],   s_[2*kk][1]);
            ah_[1] = pack_hi(s_[2*kk][2],   s_[2*kk][3]);
            ah_[2] = pack_hi(s_[2*kk+1][0], s_[2*kk+1][1]);
            ah_[3] = pack_hi(s_[2*kk+1][2], s_[2*kk+1][3]);
            al_[0] = pack_lo(s_[2*kk][0],   s_[2*kk][1]);
            al_[1] = pack_lo(s_[2*kk][2],   s_[2*kk][3]);
            al_[2] = pack_lo(s_[2*kk+1][0], s_[2*kk+1][1]);
            al_[3] = pack_lo(s_[2*kk+1][2], s_[2*kk+1][3]);
            #pragma unroll
            for (int pn = 0; pn < 8; pn++) {
                uint32_t vh_[4], vl_[4];
                ldsm4(vh_, st + STG_VH + vbo + pn * (16 * VROW) + kk * 32);
                ldsm4(vl_, st + STG_VL + vbo + pn * (16 * VROW) + kk * 32);
                mma_bf16(o_[2*pn],   ah_, vh_[0], vh_[1]);
                mma_bf16(o_[2*pn+1], ah_, vh_[2], vh_[3]);
                mma_bf16(o_[2*pn],   ah_, vl_[0], vl_[1]);
                mma_bf16(o_[2*pn+1], ah_, vl_[2], vl_[3]);
                mma_bf16(o_[2*pn],   al_, vh_[0], vh_[1]);
                mma_bf16(o_[2*pn+1], al_, vh_[2], vh_[3]);
            }
        }
        __syncthreads();
    }

    // ---- epilogue: O / l + residual -> g_x1
    float inv0 = 1.f / l0r, inv1 = 1.f / l1r;
    int r0 = m0 + wid * 16 + (lane >> 2);
    int cb = (lane & 3) * 2;
    #pragma unroll
    for (int ni = 0; ni < 16; ni++) {
        int col = head * DH_ + ni * 8 + cb;
        size_t i0 = ((size_t)(b * T_ + r0)) * C_ + col;
        size_t i1 = ((size_t)(b * T_ + r0 + 8)) * C_ + col;
        float2 x0 = *(const float2*)(x + i0);
        float2 x1v = *(const float2*)(x + i1);
        *(float2*)(g_x1 + i0) = make_float2(o_[ni][0] * inv0 + x0.x,
                                            o_[ni][1] * inv0 + x0.y);
        *(float2*)(g_x1 + i1) = make_float2(o_[ni][2] * inv1 + x1v.x,
                                            o_[ni][3] * inv1 + x1v.y);
    }
}

// ============================================================================
// GEMM kernels (qkv / ff1 / ff2)
// ============================================================================
__global__ void __launch_bounds__(256) qkv_gemm()
{
    int m0   = blockIdx.x * 128;
    int sel  = blockIdx.y >> 3;
    int head = blockIdx.y & 7;
    size_t woff = (size_t)blockIdx.y * DH_ * C_;
    float acc[2][8][4];
    gemm_mainloop(acc,
        g_h1h + (size_t)m0 * C_, g_h1l + (size_t)m0 * C_, C_,
        g_wTh + woff,            g_wTl + woff,            C_, C_);

    const float AL = 11.313708498984761f;   // sqrt(128) folded into q
    epilogue_loop(acc, [&](int ml, int nl, float2 vv) {
        int m = m0 + ml, b = m >> 11, t = m & (T_ - 1);
        size_t base = ((size_t)(b * H_ + head) * T_ + t) * DH_ + nl;
        if (sel == 0)      store_hilo2(g_q_h + base, g_q_l + base,
                                       make_float2(vv.x * AL, vv.y * AL));
        else if (sel == 1) store_hilo2(g_k_h + base, g_k_l + base, vv);
        else               *(float2*)(g_v + base) = vv;
    });
}

__global__ void __launch_bounds__(256) ff1_gemm(const float* __restrict__ b1)
{
    int m0 = blockIdx.x * 128, n0 = blockIdx.y * 128;
    float acc[2][8][4];
    gemm_mainloop(acc,
        g_h2h + (size_t)m0 * C_,  g_h2l + (size_t)m0 * C_,  C_,
        g_w1Th + (size_t)n0 * C_, g_w1Tl + (size_t)n0 * C_, C_, C_);

    epilogue_loop(acc, [&](int ml, int nl, float2 vv) {
        float2 bb = *(const float2*)(b1 + n0 + nl);
        float r0 = fmaxf(vv.x + bb.x, 0.f);
        float r1 = fmaxf(vv.y + bb.y, 0.f);
        size_t base = (size_t)(m0 + ml) * DFF_ + n0 + nl;
        store_hilo2(g_f1h + base, g_f1l + base, make_float2(r0, r1));
    });
}

__global__ void __launch_bounds__(256) ff2_gemm(const float* __restrict__ b2,
                                                float* __restrict__ out)
{
    int m0 = blockIdx.x * 128, n0 = blockIdx.y * 128;
    float acc[2][8][4];
    gemm_mainloop(acc,
        g_f1h + (size_t)m0 * DFF_,  g_f1l + (size_t)m0 * DFF_,  DFF_,
        g_w2Th + (size_t)n0 * DFF_, g_w2Tl + (size_t)n0 * DFF_, DFF_, DFF_);

    epilogue_loop(acc, [&](int ml, int nl, float2 vv) {
        float2 bb = *(const float2*)(b2 + n0 + nl);
        size_t idx = (size_t)(m0 + ml) * C_ + n0 + nl;
        float2 xr = *(const float2*)(g_x1 + idx);
        *(float2*)(out + idx) = make_float2(vv.x + bb.x + xr.x,
                                            vv.y + bb.y + xr.y);
    });
}

// ============================================================================
// transpose + bf16 hi/lo convert: in [R, Cc] fp32 -> out [Cc, R] hi/lo
// ============================================================================
__global__ void transpose_conv(const float* __restrict__ in, bf16* __restrict__ oh,
                               bf16* __restrict__ ol, int R, int Cc,
                               size_t in_bstride, size_t out_bstride)
{
    __shared__ float tile[32][33];
    const float* src = in + (size_t)blockIdx.z * in_bstride;
    int c0 = blockIdx.x * 32, r0 = blockIdx.y * 32;
    int tx = threadIdx.x, ty = threadIdx.y;          // 32 x 8
    #pragma unroll
    for (int i = 0; i < 32; i += 8)
        tile[ty + i][tx] = src[(size_t)(r0 + ty + i) * Cc + c0 + tx];
    __syncthreads();
    #pragma unroll
    for (int i = 0; i < 32; i += 8) {
        float v = tile[tx][ty + i];
        bf16 h = __float2bfloat16_rn(v);
        bf16 l = __float2bfloat16_rn(v - __bfloat162float(h));
        size_t o = (size_t)blockIdx.z * out_bstride + (size_t)(c0 + ty + i) * R + r0 + tx;
        oh[o] = h; ol[o] = l;
    }
}

// ============================================================================
// LayerNorm -> bf16 hi/lo
// ============================================================================
__device__ __forceinline__ void block_reduce2(float& a, float& b)
{
    #pragma unroll
    for (int o = 16; o; o >>= 1) {
        a += __shfl_xor_sync(0xFFFFFFFFu, a, o);
        b += __shfl_xor_sync(0xFFFFFFFFu, b, o);
    }
    __shared__ float sa[8], sb_[8];
    int w = threadIdx.x >> 5, l = threadIdx.x & 31;
    if (l == 0) { sa[w] = a; sb_[w] = b; }
    __syncthreads();
    a = 0.f; b = 0.f;
    #pragma unroll
    for (int i = 0; i < 8; i++) { a += sa[i]; b += sb_[i]; }
}

__global__ void ln_kernel(const float* __restrict__ x, const float* __restrict__ g,
                          const float* __restrict__ bb, bf16* __restrict__ oh,
                          bf16* __restrict__ ol)
{
    size_t row = blockIdx.x;
    float4 v = ((const float4*)(x + row * C_))[threadIdx.x];
    float s  = v.x + v.y + v.z + v.w;
    float sq = v.x*v.x + v.y*v.y + v.z*v.z + v.w*v.w;
    block_reduce2(s, sq);
    float mean = s * (1.0f / C_);
    float var  = sq * (1.0f / C_) - mean * mean;
    float inv  = rsqrtf(var + 1e-5f);
    float4 gv = ((const float4*)g)[threadIdx.x];
    float4 bv = ((const float4*)bb)[threadIdx.x];
    float o0 = (v.x - mean) * inv * gv.x + bv.x;
    float o1 = (v.y - mean) * inv * gv.y + bv.y;
    float o2 = (v.z - mean) * inv * gv.z + bv.z;
    float o3 = (v.w - mean) * inv * gv.w + bv.w;
    size_t base = row * C_ + threadIdx.x * 4;
    store_hilo2(oh + base,     ol + base,     make_float2(o0, o1));
    store_hilo2(oh + base + 2, ol + base + 2, make_float2(o2, o3));
}

// ============================================================================
// host
// ============================================================================
extern "C" void kernel_launch(void* const* d_in, const int* in_sizes, int n_in,
                              void* d_out, int out_size)
{
    const float* x     = (const float*)d_in[0];
    const float* wq    = (const float*)d_in[1];
    const float* wk    = (const float*)d_in[2];
    const float* wv    = (const float*)d_in[3];
    const float* w1    = (const float*)d_in[4];
    const float* b1    = (const float*)d_in[5];
    const float* w2    = (const float*)d_in[6];
    const float* b2    = (const float*)d_in[7];
    const float* ln1_g = (const float*)d_in[8];
    const float* ln1_b = (const float*)d_in[9];
    const float* ln2_g = (const float*)d_in[10];
    const float* ln2_b = (const float*)d_in[11];
    float* out = (float*)d_out;

    cudaFuncSetAttribute(qkv_gemm,   cudaFuncAttributeMaxDynamicSharedMemorySize, GEMM_SMEM);
    cudaFuncSetAttribute(ff1_gemm,   cudaFuncAttributeMaxDynamicSharedMemorySize, GEMM_SMEM);
    cudaFuncSetAttribute(ff2_gemm,   cudaFuncAttributeMaxDynamicSharedMemorySize, GEMM_SMEM);
    cudaFuncSetAttribute(flash_attn, cudaFuncAttributeMaxDynamicSharedMemorySize, FLASH_SMEM);

    bf16 *p_h1h, *p_h1l, *p_h2h, *p_h2l, *p_wTh, *p_wTl, *p_w1Th, *p_w1Tl, *p_w2Th, *p_w2Tl;
    bf16 *p_vTh, *p_vTl;
    float *p_x1, *p_v;
    cudaGetSymbolAddress((void**)&p_h1h, g_h1h);
    cudaGetSymbolAddress((void**)&p_h1l, g_h1l);
    cudaGetSymbolAddress((void**)&p_h2h, g_h2h);
    cudaGetSymbolAddress((void**)&p_h2l, g_h2l);
    cudaGetSymbolAddress((void**)&p_wTh, g_wTh);
    cudaGetSymbolAddress((void**)&p_wTl, g_wTl);
    cudaGetSymbolAddress((void**)&p_w1Th, g_w1Th);
    cudaGetSymbolAddress((void**)&p_w1Tl, g_w1Tl);
    cudaGetSymbolAddress((void**)&p_w2Th, g_w2Th);
    cudaGetSymbolAddress((void**)&p_w2Tl, g_w2Tl);
    cudaGetSymbolAddress((void**)&p_vTh, g_vT_h);
    cudaGetSymbolAddress((void**)&p_vTl, g_vT_l);
    cudaGetSymbolAddress((void**)&p_x1, g_x1);
    cudaGetSymbolAddress((void**)&p_v,  g_v);

    dim3 tb(32, 8);
    // weight transposes -> [N, K] bf16 hi/lo
    transpose_conv<<<dim3(DH_/32, C_/32, H_), tb>>>(wq, p_wTh, p_wTl, C_, DH_, (size_t)C_*DH_, (size_t)DH_*C_);
    transpose_conv<<<dim3(DH_/32, C_/32, H_), tb>>>(wk, p_wTh + (size_t)H_*DH_*C_, p_wTl + (size_t)H_*DH_*C_, C_, DH_, (size_t)C_*DH_, (size_t)DH_*C_);
    transpose_conv<<<dim3(DH_/32, C_/32, H_), tb>>>(wv, p_wTh + (size_t)2*H_*DH_*C_, p_wTl + (size_t)2*H_*DH_*C_, C_, DH_, (size_t)C_*DH_, (size_t)DH_*C_);
    transpose_conv<<<dim3(DFF_/32, C_/32, 1), tb>>>(w1, p_w1Th, p_w1Tl, C_, DFF_, 0, 0);
    transpose_conv<<<dim3(C_/32, DFF_/32, 1), tb>>>(w2, p_w2Th, p_w2Tl, DFF_, C_, 0, 0);

    // 1. LN1 -> h1 hi/lo
    ln_kernel<<<M_, 256>>>(x, ln1_g, ln1_b, p_h1h, p_h1l);
    // 2. QKV projections (q pre-scaled by sqrt(128))
    qkv_gemm<<<dim3(M_/128, 3*H_, 1), 256, GEMM_SMEM>>>();
    // 3. v transpose -> [z][Dh][T] hi/lo
    transpose_conv<<<dim3(DH_/32, T_/32, B_*H_), tb>>>(p_v, p_vTh, p_vTl, T_, DH_, (size_t)T_*DH_, (size_t)DH_*T_);
    // 4. fused attention (QK^T + online softmax + PV + residual) -> x1
    flash_attn<<<dim3(T_/128, B_*H_), 256, FLASH_SMEM>>>(x);
    // 5. LN2 -> h2 hi/lo
    ln_kernel<<<M_, 256>>>(p_x1, ln2_g, ln2_b, p_h2h, p_h2l);
    // 6. FF1 -> f1 hi/lo
    ff1_gemm<<<dim3(M_/128, DFF_/128, 1), 256, GEMM_SMEM>>>(b1);
    // 7. FF2 (+bias +residual) -> out
    ff2_gemm<<<dim3(M_/128, C_/128, 1), 256, GEMM_SMEM>>>(b2, out);
}

// round 9
// speedup vs baseline: 1.3004x; 1.0747x over previous
#include <cuda_runtime.h>
#include <cuda_bf16.h>
#include <cstdint>
#include <math.h>

// ---------------- problem constants ----------------
#define B_  4
#define T_  2048
#define C_  1024
#define H_  8
#define DH_ 128
#define DFF_ 4096
#define M_  (B_ * T_)            // 8192 rows
#define BHT (B_ * H_ * T_)       // 65536

typedef __nv_bfloat16 bf16;

// ---------------- scratch (device globals, no allocation) ----------------
#define QKV_SZ (B_ * H_ * T_ * DH_)
__device__ bf16  g_h1h[M_ * C_],  g_h1l[M_ * C_];             // LN1 out hi/lo
__device__ bf16  g_q_h[QKV_SZ], g_q_l[QKV_SZ];                // q (pre-scaled sqrt(128))
__device__ bf16  g_k_h[QKV_SZ], g_k_l[QKV_SZ];
__device__ float g_v  [QKV_SZ];
__device__ bf16  g_vT_h[QKV_SZ], g_vT_l[QKV_SZ];              // [z][Dh][T]
__device__ float g_oP [2 * QKV_SZ];                           // flash O partials (unnorm)
__device__ float2 g_mlP[2 * BHT];                             // flash (m, l) per row/half
__device__ float g_x1[M_ * C_];                               // x + attn_out
__device__ bf16  g_h2h[M_ * C_], g_h2l[M_ * C_];              // LN2 out hi/lo
__device__ bf16  g_f1h[M_ * DFF_], g_f1l[M_ * DFF_];          // relu(h2 w1 + b1)
__device__ float g_f2p[2 * M_ * C_];                          // ff2 split-K partials
__device__ bf16  g_wTh[3 * H_ * DH_ * C_], g_wTl[3 * H_ * DH_ * C_];  // qkv w^T
__device__ bf16  g_w1Th[DFF_ * C_], g_w1Tl[DFF_ * C_];        // w1^T [Dff, C]
__device__ bf16  g_w2Th[C_ * DFF_], g_w2Tl[C_ * DFF_];        // w2^T [C, Dff]

// ---------------- low-level helpers ----------------
__device__ __forceinline__ uint32_t smem_u32(const void* p) {
    uint32_t a;
    asm("{ .reg .u64 t; cvta.to.shared.u64 t, %1; cvt.u32.u64 %0, t; }"
        : "=r"(a) : "l"(p));
    return a;
}
__device__ __forceinline__ void cp16(uint32_t dst, const void* src) {
    asm volatile("cp.async.cg.shared.global [%0], [%1], 16;\n"
                 :: "r"(dst), "l"(__cvta_generic_to_global(src)));
}
__device__ __forceinline__ void cp_commit() {
    asm volatile("cp.async.commit_group;\n" ::: "memory");
}
template<int N> __device__ __forceinline__ void cp_wait() {
    asm volatile("cp.async.wait_group %0;\n" :: "n"(N) : "memory");
}
__device__ __forceinline__ void ldsm4(uint32_t r[4], uint32_t addr) {
    asm volatile("ldmatrix.sync.aligned.m8n8.x4.shared.b16 {%0,%1,%2,%3}, [%4];"
        : "=r"(r[0]), "=r"(r[1]), "=r"(r[2]), "=r"(r[3]) : "r"(addr));
}
__device__ __forceinline__ void mma_bf16(float c[4], const uint32_t a[4],
                                         const uint32_t b0, const uint32_t b1) {
    asm volatile(
        "mma.sync.aligned.m16n8k16.row.col.f32.bf16.bf16.f32 "
        "{%0,%1,%2,%3}, {%4,%5,%6,%7}, {%8,%9}, {%0,%1,%2,%3};"
        : "+f"(c[0]), "+f"(c[1]), "+f"(c[2]), "+f"(c[3])
        : "r"(a[0]), "r"(a[1]), "r"(a[2]), "r"(a[3]), "r"(b0), "r"(b1));
}
__device__ __forceinline__ uint32_t pack_hi(float a, float b) {
    __nv_bfloat162 t; t.x = __float2bfloat16_rn(a); t.y = __float2bfloat16_rn(b);
    return *(uint32_t*)&t;
}
__device__ __forceinline__ uint32_t pack_lo(float a, float b) {
    bf16 ha = __float2bfloat16_rn(a), hb = __float2bfloat16_rn(b);
    __nv_bfloat162 t;
    t.x = __float2bfloat16_rn(a - __bfloat162float(ha));
    t.y = __float2bfloat16_rn(b - __bfloat162float(hb));
    return *(uint32_t*)&t;
}

// ---------------- GEMM smem geometry (qkv / ff1 / ff2) ----------------
#define ROWB   80
#define MATB   (128 * ROWB)        // 10240
#define STAGEB (4 * MATB)          // 40960
#define GEMM_SMEM (2 * STAGEB)     // 81920

__device__ __forceinline__ void issue_stage(
    uint32_t sbase, int buf,
    const bf16* __restrict__ Ah, const bf16* __restrict__ Al, int lda,
    const bf16* __restrict__ Bh, const bf16* __restrict__ Bl, int ldb, int k0)
{
    const int tid = threadIdx.x;
    const int mat = tid >> 6;
    const int t   = tid & 63;
    const bf16* src; int ld;
    if      (mat == 0) { src = Ah; ld = lda; }
    else if (mat == 1) { src = Al; ld = lda; }
    else if (mat == 2) { src = Bh; ld = ldb; }
    else               { src = Bl; ld = ldb; }
    uint32_t mbase = sbase + (uint32_t)buf * STAGEB + (uint32_t)mat * MATB;
    #pragma unroll
    for (int rr = 0; rr < 2; rr++) {
        int row = t * 2 + rr;
        const bf16* s = src + (size_t)row * ld + k0;
        uint32_t d = mbase + row * ROWB;
        #pragma unroll
        for (int seg = 0; seg < 4; seg++)
            cp16(d + seg * 16, s + seg * 8);
    }
    cp_commit();
}

__device__ __forceinline__ void gemm_mainloop(
    float acc[2][8][4],
    const bf16* __restrict__ Ah, const bf16* __restrict__ Al, int lda,
    const bf16* __restrict__ Bh, const bf16* __restrict__ Bl, int ldb, int K)
{
    extern __shared__ char smem_raw[];
    uint32_t sbase = smem_u32(smem_raw);
    const int tid  = threadIdx.x;
    const int wid  = tid >> 5, lane = tid & 31;
    const int m0w  = (wid & 3) * 32;
    const int n0w  = (wid >> 2) * 64;
    const int g    = lane >> 3, lr = lane & 7;

    const uint32_t a_off = (uint32_t)((m0w + (g & 1) * 8 + lr) * ROWB + (g >> 1) * 16);
    const uint32_t b_off = (uint32_t)((n0w + (g >> 1) * 8 + lr) * ROWB + (g & 1) * 16);

    #pragma unroll
    for (int mi = 0; mi < 2; mi++)
        #pragma unroll
        for (int ni = 0; ni < 8; ni++)
            #pragma unroll
            for (int i = 0; i < 4; i++)
                acc[mi][ni][i] = 0.f;

    const int nstage = K >> 5;
    issue_stage(sbase, 0, Ah, Al, lda, Bh, Bl, ldb, 0);

    for (int c = 0; c < nstage; c++) {
        if (c + 1 < nstage) {
            issue_stage(sbase, (c + 1) & 1, Ah, Al, lda, Bh, Bl, ldb, (c + 1) << 5);
            cp_wait<1>();
        } else {
            cp_wait<0>();
        }
        __syncthreads();

        uint32_t st = sbase + (uint32_t)(c & 1) * STAGEB;
        #pragma unroll
        for (int ks = 0; ks < 2; ks++) {
            uint32_t kb = (uint32_t)ks * 32;
            uint32_t ah[2][4], al[2][4];
            ldsm4(ah[0], st + 0 * MATB + a_off + kb);
            ldsm4(ah[1], st + 0 * MATB + a_off + kb + 16 * ROWB);
            ldsm4(al[0], st + 1 * MATB + a_off + kb);
            ldsm4(al[1], st + 1 * MATB + a_off + kb + 16 * ROWB);
            uint32_t bh[4][4], bl[4][4];
            #pragma unroll
            for (int pn = 0; pn < 4; pn++) {
                ldsm4(bh[pn], st + 2 * MATB + b_off + kb + (uint32_t)pn * 16 * ROWB);
                ldsm4(bl[pn], st + 3 * MATB + b_off + kb + (uint32_t)pn * 16 * ROWB);
            }
            #pragma unroll
            for (int ni = 0; ni < 8; ni++)
                #pragma unroll
                for (int mi = 0; mi < 2; mi++)
                    mma_bf16(acc[mi][ni], ah[mi], bh[ni >> 1][(ni & 1) * 2],
                                                   bh[ni >> 1][(ni & 1) * 2 + 1]);
            #pragma unroll
            for (int ni = 0; ni < 8; ni++)
                #pragma unroll
                for (int mi = 0; mi < 2; mi++)
                    mma_bf16(acc[mi][ni], ah[mi], bl[ni >> 1][(ni & 1) * 2],
                                                   bl[ni >> 1][(ni & 1) * 2 + 1]);
            #pragma unroll
            for (int ni = 0; ni < 8; ni++)
                #pragma unroll
                for (int mi = 0; mi < 2; mi++)
                    mma_bf16(acc[mi][ni], al[mi], bh[ni >> 1][(ni & 1) * 2],
                                                   bh[ni >> 1][(ni & 1) * 2 + 1]);
        }
        __syncthreads();
    }
}

template<class F>
__device__ __forceinline__ void epilogue_loop(float acc[2][8][4], F f)
{
    const int wid = threadIdx.x >> 5, lane = threadIdx.x & 31;
    const int m0w = (wid & 3) * 32, n0w = (wid >> 2) * 64;
    const int lr = lane >> 2, lc = (lane & 3) * 2;
    #pragma unroll
    for (int mi = 0; mi < 2; mi++)
        #pragma unroll
        for (int hf = 0; hf < 2; hf++) {
            const int ml = m0w + mi * 16 + hf * 8 + lr;
            #pragma unroll
            for (int ni = 0; ni < 8; ni++) {
                const int nl = n0w + ni * 8 + lc;
                f(ml, nl, make_float2(acc[mi][ni][hf * 2], acc[mi][ni][hf * 2 + 1]));
            }
        }
}

__device__ __forceinline__ void store_hilo2(bf16* oh, bf16* ol, float2 v) {
    bf16 h0 = __float2bfloat16_rn(v.x);
    bf16 h1 = __float2bfloat16_rn(v.y);
    __nv_bfloat162 hh; hh.x = h0; hh.y = h1;
    __nv_bfloat162 ll;
    ll.x = __float2bfloat16_rn(v.x - __bfloat162float(h0));
    ll.y = __float2bfloat16_rn(v.y - __bfloat162float(h1));
    *reinterpret_cast<__nv_bfloat162*>(oh) = hh;
    *reinterpret_cast<__nv_bfloat162*>(ol) = ll;
}

// ============================================================================
// Flash attention smem geometry
// ============================================================================
#define KT     64                      // keys per tile
#define NKT    (T_ / KT)               // 32 tiles total
#define HKT    (NKT / 2)               // 16 tiles per half (split-KV)
#define QROW   272
#define KROW   272
#define VROW   144
#define SM_QH  0
#define SM_QL  34816
#define SM_K0  69632
#define STG_KH 0
#define STG_KL 17408
#define STG_VH 34816
#define STG_VL 53248
#define STGB   71680
#define FLASH_SMEM 212992

__device__ __forceinline__ void issue_kv_stage(uint32_t sb, int buf,
                                               size_t koff, size_t voff, int j)
{
    uint32_t st = sb + SM_K0 + (uint32_t)buf * STGB;
    const int tid = threadIdx.x;
    {   // K tile: 64 rows(keys) x 256B, hi & lo
        int r = tid >> 2;
        int seg0 = (tid & 3) * 4;
        const bf16* sh = g_k_h + koff + (size_t)(j * KT + r) * DH_ + seg0 * 8;
        const bf16* sl = g_k_l + koff + (size_t)(j * KT + r) * DH_ + seg0 * 8;
        uint32_t dh_ = st + STG_KH + r * KROW + seg0 * 16;
        uint32_t dl_ = st + STG_KL + r * KROW + seg0 * 16;
        #pragma unroll
        for (int s = 0; s < 4; s++) { cp16(dh_ + s * 16, sh + s * 8);
                                      cp16(dl_ + s * 16, sl + s * 8); }
    }
    {   // V tile: 128 rows(dh) x 128B, hi & lo
        int r = tid >> 1;
        int seg0 = (tid & 1) * 4;
        const bf16* sh = g_vT_h + voff + (size_t)r * T_ + j * KT + seg0 * 8;
        const bf16* sl = g_vT_l + voff + (size_t)r * T_ + j * KT + seg0 * 8;
        uint32_t dh_ = st + STG_VH + r * VROW + seg0 * 16;
        uint32_t dl_ = st + STG_VL + r * VROW + seg0 * 16;
        #pragma unroll
        for (int s = 0; s < 4; s++) { cp16(dh_ + s * 16, sh + s * 8);
                                      cp16(dl_ + s * 16, sl + s * 8); }
    }
    cp_commit();
}

// ============================================================================
// Flash attention (split-KV): CTA = 128 q rows x 1024 keys (half).
// Writes unnormalized O + (m, l) partials; combine_ln merges halves.
// ============================================================================
__global__ void __launch_bounds__(256) flash_attn()
{
    extern __shared__ char smem_raw[];
    uint32_t sb = smem_u32(smem_raw);
    const int tid = threadIdx.x, wid = tid >> 5, lane = tid & 31;
    const int z = blockIdx.y;
    const int m0 = blockIdx.x * 128;
    const int half = blockIdx.z;
    const int j0 = half * HKT;
    const size_t qoff = (size_t)z * T_ * DH_ + (size_t)m0 * DH_;
    const size_t koff = (size_t)z * T_ * DH_;
    const size_t voff = (size_t)z * DH_ * T_;

    // Q -> smem (its own cp.async group)
    {
        int r = tid >> 1, hf = tid & 1;
        const bf16* sh = g_q_h + qoff + (size_t)r * DH_ + hf * 64;
        const bf16* sl = g_q_l + qoff + (size_t)r * DH_ + hf * 64;
        uint32_t dh_ = sb + SM_QH + r * QROW + hf * 128;
        uint32_t dl_ = sb + SM_QL + r * QROW + hf * 128;
        #pragma unroll
        for (int s = 0; s < 8; s++) { cp16(dh_ + s * 16, sh + s * 8);
                                      cp16(dl_ + s * 16, sl + s * 8); }
        cp_commit();
    }
    issue_kv_stage(sb, 0, koff, voff, j0);

    const int g = lane >> 3, lr8 = lane & 7;
    const uint32_t qa  = (uint32_t)((wid * 16 + (g & 1) * 8 + lr8) * QROW + (g >> 1) * 16);
    const uint32_t kbo = (uint32_t)(((g >> 1) * 8 + lr8) * KROW + (g & 1) * 16);
    const uint32_t vbo = (uint32_t)(((g >> 1) * 8 + lr8) * VROW + (g & 1) * 16);

    float o_[16][4];
    #pragma unroll
    for (int i = 0; i < 16; i++) { o_[i][0] = o_[i][1] = o_[i][2] = o_[i][3] = 0.f; }
    float m0r = -1e30f, m1r = -1e30f, l0r = 0.f, l1r = 0.f;

    for (int jj = 0; jj < HKT; jj++) {
        if (jj + 1 < HKT) { issue_kv_stage(sb, (jj + 1) & 1, koff, voff, j0 + jj + 1); cp_wait<1>(); }
        else              { cp_wait<0>(); }
        __syncthreads();

        uint32_t st = sb + SM_K0 + (uint32_t)(jj & 1) * STGB;
        // ---- S = Q K^T
        float s_[8][4];
        #pragma unroll
        for (int i = 0; i < 8; i++) { s_[i][0] = s_[i][1] = s_[i][2] = s_[i][3] = 0.f; }
        #pragma unroll
        for (int ks = 0; ks < 8; ks++) {
            uint32_t qh_[4], ql_[4];
            ldsm4(qh_, sb + SM_QH + qa + ks * 32);
            ldsm4(ql_, sb + SM_QL + qa + ks * 32);
            #pragma unroll
            for (int pn = 0; pn < 4; pn++) {
                uint32_t kh_[4], kl_[4];
                ldsm4(kh_, st + STG_KH + kbo + pn * (16 * KROW) + ks * 32);
                ldsm4(kl_, st + STG_KL + kbo + pn * (16 * KROW) + ks * 32);
                mma_bf16(s_[2*pn],   qh_, kh_[0], kh_[1]);
                mma_bf16(s_[2*pn+1], qh_, kh_[2], kh_[3]);
                mma_bf16(s_[2*pn],   qh_, kl_[0], kl_[1]);
                mma_bf16(s_[2*pn+1], qh_, kl_[2], kl_[3]);
                mma_bf16(s_[2*pn],   ql_, kh_[0], kh_[1]);
                mma_bf16(s_[2*pn+1], ql_, kh_[2], kh_[3]);
            }
        }
        // ---- online softmax
        float tm0 = -1e30f, tm1 = -1e30f;
        #pragma unroll
        for (int i = 0; i < 8; i++) {
            tm0 = fmaxf(tm0, fmaxf(s_[i][0], s_[i][1]));
            tm1 = fmaxf(tm1, fmaxf(s_[i][2], s_[i][3]));
        }
        tm0 = fmaxf(tm0, __shfl_xor_sync(0xFFFFFFFFu, tm0, 1));
        tm0 = fmaxf(tm0, __shfl_xor_sync(0xFFFFFFFFu, tm0, 2));
        tm1 = fmaxf(tm1, __shfl_xor_sync(0xFFFFFFFFu, tm1, 1));
        tm1 = fmaxf(tm1, __shfl_xor_sync(0xFFFFFFFFu, tm1, 2));
        float mn0 = fmaxf(m0r, tm0), mn1 = fmaxf(m1r, tm1);
        float sc0 = expf(m0r - mn0), sc1 = expf(m1r - mn1);
        m0r = mn0; m1r = mn1;
        float sum0 = 0.f, sum1 = 0.f;
        #pragma unroll
        for (int i = 0; i < 8; i++) {
            s_[i][0] = expf(s_[i][0] - mn0); s_[i][1] = expf(s_[i][1] - mn0);
            s_[i][2] = expf(s_[i][2] - mn1); s_[i][3] = expf(s_[i][3] - mn1);
            sum0 += s_[i][0] + s_[i][1];     sum1 += s_[i][2] + s_[i][3];
        }
        sum0 += __shfl_xor_sync(0xFFFFFFFFu, sum0, 1);
        sum0 += __shfl_xor_sync(0xFFFFFFFFu, sum0, 2);
        sum1 += __shfl_xor_sync(0xFFFFFFFFu, sum1, 1);
        sum1 += __shfl_xor_sync(0xFFFFFFFFu, sum1, 2);
        l0r = l0r * sc0 + sum0; l1r = l1r * sc1 + sum1;
        #pragma unroll
        for (int i = 0; i < 16; i++) {
            o_[i][0] *= sc0; o_[i][1] *= sc0; o_[i][2] *= sc1; o_[i][3] *= sc1;
        }
        // ---- O += P V
        #pragma unroll
        for (int kk = 0; kk < 4; kk++) {
            uint32_t ah_[4], al_[4];
            ah_[0] = pack_hi(s_[2*kk][0],   s_[2*kk][1]);
            ah_[1] = pack_hi(s_[2*kk][2],   s_[2*kk][3]);
            ah_[2] = pack_hi(s_[2*kk+1][0], s_[2*kk+1][1]);
            ah_[3] = pack_hi(s_[2*kk+1][2], s_[2*kk+1][3]);
            al_[0] = pack_lo(s_[2*kk][0],   s_[2*kk][1]);
            al_[1] = pack_lo(s_[2*kk][2],   s_[2*kk][3]);
            al_[2] = pack_lo(s_[2*kk+1][0], s_[2*kk+1][1]);
            al_[3] = pack_lo(s_[2*kk+1][2], s_[2*kk+1][3]);
            #pragma unroll
            for (int pn = 0; pn < 8; pn++) {
                uint32_t vh_[4], vl_[4];
                ldsm4(vh_, st + STG_VH + vbo + pn * (16 * VROW) + kk * 32);
                ldsm4(vl_, st + STG_VL + vbo + pn * (16 * VROW) + kk * 32);
                mma_bf16(o_[2*pn],   ah_, vh_[0], vh_[1]);
                mma_bf16(o_[2*pn+1], ah_, vh_[2], vh_[3]);
                mma_bf16(o_[2*pn],   ah_, vl_[0], vl_[1]);
                mma_bf16(o_[2*pn+1], ah_, vl_[2], vl_[3]);
                mma_bf16(o_[2*pn],   al_, vh_[0], vh_[1]);
                mma_bf16(o_[2*pn+1], al_, vh_[2], vh_[3]);
            }
        }
        __syncthreads();
    }

    // ---- epilogue: write unnormalized O + (m, l)
    float* oP = g_oP + (size_t)half * QKV_SZ + (size_t)z * T_ * DH_;
    int r0 = m0 + wid * 16 + (lane >> 2);
    int cb = (lane & 3) * 2;
    #pragma unroll
    for (int ni = 0; ni < 16; ni++) {
        int col = ni * 8 + cb;
        *(float2*)(oP + (size_t)r0 * DH_ + col)       = make_float2(o_[ni][0], o_[ni][1]);
        *(float2*)(oP + (size_t)(r0 + 8) * DH_ + col) = make_float2(o_[ni][2], o_[ni][3]);
    }
    if ((lane & 3) == 0) {
        g_mlP[half * BHT + z * T_ + r0]     = make_float2(m0r, l0r);
        g_mlP[half * BHT + z * T_ + r0 + 8] = make_float2(m1r, l1r);
    }
}

// ============================================================================
// combine_ln: merge flash halves + residual -> x1; LayerNorm -> h2 hi/lo
// ============================================================================
__device__ __forceinline__ void block_reduce2(float& a, float& b)
{
    #pragma unroll
    for (int o = 16; o; o >>= 1) {
        a += __shfl_xor_sync(0xFFFFFFFFu, a, o);
        b += __shfl_xor_sync(0xFFFFFFFFu, b, o);
    }
    __shared__ float sa[8], sb_[8];
    int w = threadIdx.x >> 5, l = threadIdx.x & 31;
    if (l == 0) { sa[w] = a; sb_[w] = b; }
    __syncthreads();
    a = 0.f; b = 0.f;
    #pragma unroll
    for (int i = 0; i < 8; i++) { a += sa[i]; b += sb_[i]; }
}

__global__ void combine_ln(const float* __restrict__ x, const float* __restrict__ gg,
                           const float* __restrict__ bb)
{
    int m = blockIdx.x;                  // b*T + t
    int b = m >> 11, t = m & (T_ - 1);
    int col = threadIdx.x * 4;
    int head = col >> 7;
    int z = b * H_ + head;
    int dh = col & (DH_ - 1);

    float2 ml0 = g_mlP[z * T_ + t];
    float2 ml1 = g_mlP[BHT + z * T_ + t];
    float mm = fmaxf(ml0.x, ml1.x);
    float a0 = expf(ml0.x - mm), a1 = expf(ml1.x - mm);
    float inv = 1.0f / (ml0.y * a0 + ml1.y * a1);

    size_t oidx = (size_t)z * T_ * DH_ + (size_t)t * DH_ + dh;
    float4 o0 = *(const float4*)(g_oP + oidx);
    float4 o1 = *(const float4*)(g_oP + QKV_SZ + oidx);
    float4 xr = *(const float4*)(x + (size_t)m * C_ + col);
    float v0 = (o0.x * a0 + o1.x * a1) * inv + xr.x;
    float v1 = (o0.y * a0 + o1.y * a1) * inv + xr.y;
    float v2 = (o0.z * a0 + o1.z * a1) * inv + xr.z;
    float v3 = (o0.w * a0 + o1.w * a1) * inv + xr.w;
    *(float4*)(g_x1 + (size_t)m * C_ + col) = make_float4(v0, v1, v2, v3);

    // LayerNorm over the row
    float s  = v0 + v1 + v2 + v3;
    float sq = v0*v0 + v1*v1 + v2*v2 + v3*v3;
    block_reduce2(s, sq);
    float mean = s * (1.0f / C_);
    float var  = sq * (1.0f / C_) - mean * mean;
    float istd = rsqrtf(var + 1e-5f);
    float4 gv = ((const float4*)gg)[threadIdx.x];
    float4 bv = ((const float4*)bb)[threadIdx.x];
    size_t base = (size_t)m * C_ + col;
    store_hilo2(g_h2h + base,     g_h2l + base,
                make_float2((v0 - mean) * istd * gv.x + bv.x,
                            (v1 - mean) * istd * gv.y + bv.y));
    store_hilo2(g_h2h + base + 2, g_h2l + base + 2,
                make_float2((v2 - mean) * istd * gv.z + bv.z,
                            (v3 - mean) * istd * gv.w + bv.w));
}

// ============================================================================
// GEMM kernels (qkv / ff1 / ff2 split-K)
// ============================================================================
__global__ void __launch_bounds__(256) qkv_gemm()
{
    int m0   = blockIdx.x * 128;
    int sel  = blockIdx.y >> 3;
    int head = blockIdx.y & 7;
    size_t woff = (size_t)blockIdx.y * DH_ * C_;
    float acc[2][8][4];
    gemm_mainloop(acc,
        g_h1h + (size_t)m0 * C_, g_h1l + (size_t)m0 * C_, C_,
        g_wTh + woff,            g_wTl + woff,            C_, C_);

    const float AL = 11.313708498984761f;   // sqrt(128) folded into q
    epilogue_loop(acc, [&](int ml, int nl, float2 vv) {
        int m = m0 + ml, b = m >> 11, t = m & (T_ - 1);
        size_t base = ((size_t)(b * H_ + head) * T_ + t) * DH_ + nl;
        if (sel == 0)      store_hilo2(g_q_h + base, g_q_l + base,
                                       make_float2(vv.x * AL, vv.y * AL));
        else if (sel == 1) store_hilo2(g_k_h + base, g_k_l + base, vv);
        else               *(float2*)(g_v + base) = vv;
    });
}

__global__ void __launch_bounds__(256) ff1_gemm(const float* __restrict__ b1)
{
    int m0 = blockIdx.x * 128, n0 = blockIdx.y * 128;
    float acc[2][8][4];
    gemm_mainloop(acc,
        g_h2h + (size_t)m0 * C_,  g_h2l + (size_t)m0 * C_,  C_,
        g_w1Th + (size_t)n0 * C_, g_w1Tl + (size_t)n0 * C_, C_, C_);

    epilogue_loop(acc, [&](int ml, int nl, float2 vv) {
        float2 bb = *(const float2*)(b1 + n0 + nl);
        float r0 = fmaxf(vv.x + bb.x, 0.f);
        float r1 = fmaxf(vv.y + bb.y, 0.f);
        size_t base = (size_t)(m0 + ml) * DFF_ + n0 + nl;
        store_hilo2(g_f1h + base, g_f1l + base, make_float2(r0, r1));
    });
}

__global__ void __launch_bounds__(256) ff2_gemm()
{
    int m0 = blockIdx.x * 128, n0 = blockIdx.y * 128;
    int half = blockIdx.z;
    int k0 = half * (DFF_ / 2);
    float acc[2][8][4];
    gemm_mainloop(acc,
        g_f1h + (size_t)m0 * DFF_ + k0,  g_f1l + (size_t)m0 * DFF_ + k0,  DFF_,
        g_w2Th + (size_t)n0 * DFF_ + k0, g_w2Tl + (size_t)n0 * DFF_ + k0, DFF_,
        DFF_ / 2);

    float* dst = g_f2p + (size_t)half * M_ * C_;
    epilogue_loop(acc, [&](int ml, int nl, float2 vv) {
        *(float2*)(dst + (size_t)(m0 + ml) * C_ + n0 + nl) = vv;
    });
}

__global__ void ff2_combine(const float* __restrict__ b2, float* __restrict__ out)
{
    size_t i = ((size_t)blockIdx.x * 256 + threadIdx.x) * 4;
    int col = (int)(i & (C_ - 1));
    float4 p0 = *(const float4*)(g_f2p + i);
    float4 p1 = *(const float4*)(g_f2p + (size_t)M_ * C_ + i);
    float4 xr = *(const float4*)(g_x1 + i);
    float4 bb = *(const float4*)(b2 + col);
    *(float4*)(out + i) = make_float4(p0.x + p1.x + xr.x + bb.x,
                                      p0.y + p1.y + xr.y + bb.y,
                                      p0.z + p1.z + xr.z + bb.z,
                                      p0.w + p1.w + xr.w + bb.w);
}

// ============================================================================
// transpose + bf16 hi/lo convert: in [R, Cc] fp32 -> out [Cc, R] hi/lo
// ============================================================================
__global__ void transpose_conv(const float* __restrict__ in, bf16* __restrict__ oh,
                               bf16* __restrict__ ol, int R, int Cc,
                               size_t in_bstride, size_t out_bstride)
{
    __shared__ float tile[32][33];
    const float* src = in + (size_t)blockIdx.z * in_bstride;
    int c0 = blockIdx.x * 32, r0 = blockIdx.y * 32;
    int tx = threadIdx.x, ty = threadIdx.y;          // 32 x 8
    #pragma unroll
    for (int i = 0; i < 32; i += 8)
        tile[ty + i][tx] = src[(size_t)(r0 + ty + i) * Cc + c0 + tx];
    __syncthreads();
    #pragma unroll
    for (int i = 0; i < 32; i += 8) {
        float v = tile[tx][ty + i];
        bf16 h = __float2bfloat16_rn(v);
        bf16 l = __float2bfloat16_rn(v - __bfloat162float(h));
        size_t o = (size_t)blockIdx.z * out_bstride + (size_t)(c0 + ty + i) * R + r0 + tx;
        oh[o] = h; ol[o] = l;
    }
}

// ============================================================================
// LayerNorm (LN1) -> bf16 hi/lo
// ============================================================================
__global__ void ln_kernel(const float* __restrict__ x, const float* __restrict__ g,
                          const float* __restrict__ bb, bf16* __restrict__ oh,
                          bf16* __restrict__ ol)
{
    size_t row = blockIdx.x;
    float4 v = ((const float4*)(x + row * C_))[threadIdx.x];
    float s  = v.x + v.y + v.z + v.w;
    float sq = v.x*v.x + v.y*v.y + v.z*v.z + v.w*v.w;
    block_reduce2(s, sq);
    float mean = s * (1.0f / C_);
    float var  = sq * (1.0f / C_) - mean * mean;
    float inv  = rsqrtf(var + 1e-5f);
    float4 gv = ((const float4*)g)[threadIdx.x];
    float4 bv = ((const float4*)bb)[threadIdx.x];
    float o0 = (v.x - mean) * inv * gv.x + bv.x;
    float o1 = (v.y - mean) * inv * gv.y + bv.y;
    float o2 = (v.z - mean) * inv * gv.z + bv.z;
    float o3 = (v.w - mean) * inv * gv.w + bv.w;
    size_t base = row * C_ + threadIdx.x * 4;
    store_hilo2(oh + base,     ol + base,     make_float2(o0, o1));
    store_hilo2(oh + base + 2, ol + base + 2, make_float2(o2, o3));
}

// ============================================================================
// host
// ============================================================================
extern "C" void kernel_launch(void* const* d_in, const int* in_sizes, int n_in,
                              void* d_out, int out_size)
{
    const float* x     = (const float*)d_in[0];
    const float* wq    = (const float*)d_in[1];
    const float* wk    = (const float*)d_in[2];
    const float* wv    = (const float*)d_in[3];
    const float* w1    = (const float*)d_in[4];
    const float* b1    = (const float*)d_in[5];
    const float* w2    = (const float*)d_in[6];
    const float* b2    = (const float*)d_in[7];
    const float* ln1_g = (const float*)d_in[8];
    const float* ln1_b = (const float*)d_in[9];
    const float* ln2_g = (const float*)d_in[10];
    const float* ln2_b = (const float*)d_in[11];
    float* out = (float*)d_out;

    cudaFuncSetAttribute(qkv_gemm,   cudaFuncAttributeMaxDynamicSharedMemorySize, GEMM_SMEM);
    cudaFuncSetAttribute(ff1_gemm,   cudaFuncAttributeMaxDynamicSharedMemorySize, GEMM_SMEM);
    cudaFuncSetAttribute(ff2_gemm,   cudaFuncAttributeMaxDynamicSharedMemorySize, GEMM_SMEM);
    cudaFuncSetAttribute(flash_attn, cudaFuncAttributeMaxDynamicSharedMemorySize, FLASH_SMEM);

    bf16 *p_h1h, *p_h1l, *p_wTh, *p_wTl, *p_w1Th, *p_w1Tl, *p_w2Th, *p_w2Tl;
    bf16 *p_vTh, *p_vTl;
    float *p_v;
    cudaGetSymbolAddress((void**)&p_h1h, g_h1h);
    cudaGetSymbolAddress((void**)&p_h1l, g_h1l);
    cudaGetSymbolAddress((void**)&p_wTh, g_wTh);
    cudaGetSymbolAddress((void**)&p_wTl, g_wTl);
    cudaGetSymbolAddress((void**)&p_w1Th, g_w1Th);
    cudaGetSymbolAddress((void**)&p_w1Tl, g_w1Tl);
    cudaGetSymbolAddress((void**)&p_w2Th, g_w2Th);
    cudaGetSymbolAddress((void**)&p_w2Tl, g_w2Tl);
    cudaGetSymbolAddress((void**)&p_vTh, g_vT_h);
    cudaGetSymbolAddress((void**)&p_vTl, g_vT_l);
    cudaGetSymbolAddress((void**)&p_v,  g_v);

    dim3 tb(32, 8);
    // weight transposes -> [N, K] bf16 hi/lo
    transpose_conv<<<dim3(DH_/32, C_/32, H_), tb>>>(wq, p_wTh, p_wTl, C_, DH_, (size_t)C_*DH_, (size_t)DH_*C_);
    transpose_conv<<<dim3(DH_/32, C_/32, H_), tb>>>(wk, p_wTh + (size_t)H_*DH_*C_, p_wTl + (size_t)H_*DH_*C_, C_, DH_, (size_t)C_*DH_, (size_t)DH_*C_);
    transpose_conv<<<dim3(DH_/32, C_/32, H_), tb>>>(wv, p_wTh + (size_t)2*H_*DH_*C_, p_wTl + (size_t)2*H_*DH_*C_, C_, DH_, (size_t)C_*DH_, (size_t)DH_*C_);
    transpose_conv<<<dim3(DFF_/32, C_/32, 1), tb>>>(w1, p_w1Th, p_w1Tl, C_, DFF_, 0, 0);
    transpose_conv<<<dim3(C_/32, DFF_/32, 1), tb>>>(w2, p_w2Th, p_w2Tl, DFF_, C_, 0, 0);

    // 1. LN1 -> h1 hi/lo
    ln_kernel<<<M_, 256>>>(x, ln1_g, ln1_b, p_h1h, p_h1l);
    // 2. QKV projections (q pre-scaled by sqrt(128))
    qkv_gemm<<<dim3(M_/128, 3*H_, 1), 256, GEMM_SMEM>>>();
    // 3. v transpose -> [z][Dh][T] hi/lo
    transpose_conv<<<dim3(DH_/32, T_/32, B_*H_), tb>>>(p_v, p_vTh, p_vTl, T_, DH_, (size_t)T_*DH_, (size_t)DH_*T_);
    // 4. fused attention, split-KV halves -> O/(m,l) partials
    flash_attn<<<dim3(T_/128, B_*H_, 2), 256, FLASH_SMEM>>>();
    // 5. combine halves + residual -> x1; LN2 -> h2 hi/lo
    combine_ln<<<M_, 256>>>(x, ln2_g, ln2_b);
    // 6. FF1 -> f1 hi/lo
    ff1_gemm<<<dim3(M_/128, DFF_/128, 1), 256, GEMM_SMEM>>>(b1);
    // 7. FF2 split-K halves -> partials
    ff2_gemm<<<dim3(M_/128, C_/128, 2), 256, GEMM_SMEM>>>();
    // 8. combine partials + bias + residual -> out
    ff2_combine<<<M_ * C_ / 1024, 256>>>(b2, out);
}

// round 11
// speedup vs baseline: 1.6674x; 1.2822x over previous
#include <cuda_runtime.h>
#include <cuda_bf16.h>
#include <cuda_fp16.h>
#include <cstdint>
#include <math.h>

// ---------------- problem constants ----------------
#define B_  4
#define T_  2048
#define C_  1024
#define H_  8
#define DH_ 128
#define DFF_ 4096
#define M_  (B_ * T_)            // 8192 rows
#define BHT (B_ * H_ * T_)       // 65536

typedef __nv_bfloat16 bf16;
typedef __half fp16;

// ---------------- scratch (device globals, no allocation) ----------------
#define QKV_SZ (B_ * H_ * T_ * DH_)
__device__ bf16  g_h1h[M_ * C_],  g_h1l[M_ * C_];             // LN1 out hi/lo (bf16)
__device__ bf16  g_q_h[QKV_SZ], g_q_l[QKV_SZ];                // q (pre-scaled sqrt(128))
__device__ bf16  g_k_h[QKV_SZ], g_k_l[QKV_SZ];
__device__ float g_v  [QKV_SZ];
__device__ fp16  g_vT [QKV_SZ];                               // [z][Dh][T] fp16 single
__device__ float g_oP [2 * QKV_SZ];                           // flash O partials (unnorm)
__device__ float2 g_mlP[2 * BHT];                             // flash (m, l) per row/half
__device__ float g_x1[M_ * C_];                               // x + attn_out
__device__ fp16  g_h2h[M_ * C_], g_h2l[M_ * C_];              // LN2 out hi/lo (fp16)
__device__ fp16  g_f1h[M_ * DFF_], g_f1l[M_ * DFF_];          // relu(h2 w1 + b1) fp16
__device__ float g_f2p[2 * M_ * C_];                          // ff2 split-K partials
__device__ bf16  g_wTh[3 * H_ * DH_ * C_], g_wTl[3 * H_ * DH_ * C_];  // qkv w^T bf16
__device__ fp16  g_w1T[DFF_ * C_];                            // w1^T [Dff, C] fp16
__device__ fp16  g_w2T[C_ * DFF_];                            // w2^T [C, Dff] fp16

// ---------------- low-level helpers ----------------
__device__ __forceinline__ uint32_t smem_u32(const void* p) {
    uint32_t a;
    asm("{ .reg .u64 t; cvta.to.shared.u64 t, %1; cvt.u32.u64 %0, t; }"
        : "=r"(a) : "l"(p));
    return a;
}
__device__ __forceinline__ void cp16(uint32_t dst, const void* src) {
    asm volatile("cp.async.cg.shared.global [%0], [%1], 16;\n"
                 :: "r"(dst), "l"(__cvta_generic_to_global(src)));
}
__device__ __forceinline__ void cp_commit() {
    asm volatile("cp.async.commit_group;\n" ::: "memory");
}
template<int N> __device__ __forceinline__ void cp_wait() {
    asm volatile("cp.async.wait_group %0;\n" :: "n"(N) : "memory");
}
__device__ __forceinline__ void ldsm4(uint32_t r[4], uint32_t addr) {
    asm volatile("ldmatrix.sync.aligned.m8n8.x4.shared.b16 {%0,%1,%2,%3}, [%4];"
        : "=r"(r[0]), "=r"(r[1]), "=r"(r[2]), "=r"(r[3]) : "r"(addr));
}
__device__ __forceinline__ void mma_bf16(float c[4], const uint32_t a[4],
                                         const uint32_t b0, const uint32_t b1) {
    asm volatile(
        "mma.sync.aligned.m16n8k16.row.col.f32.bf16.bf16.f32 "
        "{%0,%1,%2,%3}, {%4,%5,%6,%7}, {%8,%9}, {%0,%1,%2,%3};"
        : "+f"(c[0]), "+f"(c[1]), "+f"(c[2]), "+f"(c[3])
        : "r"(a[0]), "r"(a[1]), "r"(a[2]), "r"(a[3]), "r"(b0), "r"(b1));
}
__device__ __forceinline__ void mma_fp16(float c[4], const uint32_t a[4],
                                         const uint32_t b0, const uint32_t b1) {
    asm volatile(
        "mma.sync.aligned.m16n8k16.row.col.f32.f16.f16.f32 "
        "{%0,%1,%2,%3}, {%4,%5,%6,%7}, {%8,%9}, {%0,%1,%2,%3};"
        : "+f"(c[0]), "+f"(c[1]), "+f"(c[2]), "+f"(c[3])
        : "r"(a[0]), "r"(a[1]), "r"(a[2]), "r"(a[3]), "r"(b0), "r"(b1));
}
__device__ __forceinline__ uint32_t pack_hi(float a, float b) {
    __nv_bfloat162 t; t.x = __float2bfloat16_rn(a); t.y = __float2bfloat16_rn(b);
    return *(uint32_t*)&t;
}
__device__ __forceinline__ uint32_t pack_h2(float a, float b) {
    __half2 t; t.x = __float2half_rn(a); t.y = __float2half_rn(b);
    return *(uint32_t*)&t;
}
__device__ __forceinline__ uint32_t pack_l2(float a, float b) {
    fp16 ha = __float2half_rn(a), hb = __float2half_rn(b);
    __half2 t;
    t.x = __float2half_rn(a - __half2float(ha));
    t.y = __float2half_rn(b - __half2float(hb));
    return *(uint32_t*)&t;
}

// ---------------- GEMM smem geometry ----------------
#define ROWB   80
#define MATB   (128 * ROWB)        // 10240
#define STAGEB (4 * MATB)          // 40960  (3-term: Ah Al Bh Bl)
#define GEMM_SMEM (2 * STAGEB)     // 81920
#define STAGE2B (3 * MATB)         // 30720  (2-term: Ah Al B)
#define GEMM2_SMEM (2 * STAGE2B)   // 61440

// ---------------- stage loader, 3-term bf16 ----------------
__device__ __forceinline__ void issue_stage(
    uint32_t sbase, int buf,
    const bf16* __restrict__ Ah, const bf16* __restrict__ Al, int lda,
    const bf16* __restrict__ Bh, const bf16* __restrict__ Bl, int ldb, int k0)
{
    const int tid = threadIdx.x;
    const int mat = tid >> 6;
    const int t   = tid & 63;
    const bf16* src; int ld;
    if      (mat == 0) { src = Ah; ld = lda; }
    else if (mat == 1) { src = Al; ld = lda; }
    else if (mat == 2) { src = Bh; ld = ldb; }
    else               { src = Bl; ld = ldb; }
    uint32_t mbase = sbase + (uint32_t)buf * STAGEB + (uint32_t)mat * MATB;
    #pragma unroll
    for (int rr = 0; rr < 2; rr++) {
        int row = t * 2 + rr;
        const bf16* s = src + (size_t)row * ld + k0;
        uint32_t d = mbase + row * ROWB;
        #pragma unroll
        for (int seg = 0; seg < 4; seg++)
            cp16(d + seg * 16, s + seg * 8);
    }
    cp_commit();
}

// ---------------- stage loader, 2-term fp16 ----------------
__device__ __forceinline__ void issue_stage2(
    uint32_t sbase, int buf,
    const fp16* __restrict__ Ah, const fp16* __restrict__ Al, int lda,
    const fp16* __restrict__ B, int ldb, int k0)
{
    const int tid = threadIdx.x;
    uint32_t mbase = sbase + (uint32_t)buf * STAGE2B;
    if (tid < 128) {
        int mat = tid >> 6, t = tid & 63;
        const fp16* src = mat ? Al : Ah;
        #pragma unroll
        for (int rr = 0; rr < 2; rr++) {
            int row = t * 2 + rr;
            const fp16* s = src + (size_t)row * lda + k0;
            uint32_t d = mbase + (uint32_t)mat * MATB + row * ROWB;
            #pragma unroll
            for (int seg = 0; seg < 4; seg++)
                cp16(d + seg * 16, s + seg * 8);
        }
    } else {
        int row = tid - 128;
        const fp16* s = B + (size_t)row * ldb + k0;
        uint32_t d = mbase + 2 * MATB + row * ROWB;
        #pragma unroll
        for (int seg = 0; seg < 4; seg++)
            cp16(d + seg * 16, s + seg * 8);
    }
    cp_commit();
}

// ---------------- 3-term bf16 mainloop ----------------
__device__ __forceinline__ void gemm_mainloop(
    float acc[2][8][4],
    const bf16* __restrict__ Ah, const bf16* __restrict__ Al, int lda,
    const bf16* __restrict__ Bh, const bf16* __restrict__ Bl, int ldb, int K)
{
    extern __shared__ char smem_raw[];
    uint32_t sbase = smem_u32(smem_raw);
    const int tid  = threadIdx.x;
    const int wid  = tid >> 5, lane = tid & 31;
    const int m0w  = (wid & 3) * 32;
    const int n0w  = (wid >> 2) * 64;
    const int g    = lane >> 3, lr = lane & 7;

    const uint32_t a_off = (uint32_t)((m0w + (g & 1) * 8 + lr) * ROWB + (g >> 1) * 16);
    const uint32_t b_off = (uint32_t)((n0w + (g >> 1) * 8 + lr) * ROWB + (g & 1) * 16);

    #pragma unroll
    for (int mi = 0; mi < 2; mi++)
        #pragma unroll
        for (int ni = 0; ni < 8; ni++)
            #pragma unroll
            for (int i = 0; i < 4; i++)
                acc[mi][ni][i] = 0.f;

    const int nstage = K >> 5;
    issue_stage(sbase, 0, Ah, Al, lda, Bh, Bl, ldb, 0);

    for (int c = 0; c < nstage; c++) {
        if (c + 1 < nstage) {
            issue_stage(sbase, (c + 1) & 1, Ah, Al, lda, Bh, Bl, ldb, (c + 1) << 5);
            cp_wait<1>();
        } else {
            cp_wait<0>();
        }
        __syncthreads();

        uint32_t st = sbase + (uint32_t)(c & 1) * STAGEB;
        #pragma unroll
        for (int ks = 0; ks < 2; ks++) {
            uint32_t kb = (uint32_t)ks * 32;
            uint32_t ah[2][4], al[2][4];
            ldsm4(ah[0], st + 0 * MATB + a_off + kb);
            ldsm4(ah[1], st + 0 * MATB + a_off + kb + 16 * ROWB);
            ldsm4(al[0], st + 1 * MATB + a_off + kb);
            ldsm4(al[1], st + 1 * MATB + a_off + kb + 16 * ROWB);
            uint32_t bh[4][4], bl[4][4];
            #pragma unroll
            for (int pn = 0; pn < 4; pn++) {
                ldsm4(bh[pn], st + 2 * MATB + b_off + kb + (uint32_t)pn * 16 * ROWB);
                ldsm4(bl[pn], st + 3 * MATB + b_off + kb + (uint32_t)pn * 16 * ROWB);
            }
            #pragma unroll
            for (int ni = 0; ni < 8; ni++)
                #pragma unroll
                for (int mi = 0; mi < 2; mi++)
                    mma_bf16(acc[mi][ni], ah[mi], bh[ni >> 1][(ni & 1) * 2],
                                                   bh[ni >> 1][(ni & 1) * 2 + 1]);
            #pragma unroll
            for (int ni = 0; ni < 8; ni++)
                #pragma unroll
                for (int mi = 0; mi < 2; mi++)
                    mma_bf16(acc[mi][ni], ah[mi], bl[ni >> 1][(ni & 1) * 2],
                                                   bl[ni >> 1][(ni & 1) * 2 + 1]);
            #pragma unroll
            for (int ni = 0; ni < 8; ni++)
                #pragma unroll
                for (int mi = 0; mi < 2; mi++)
                    mma_bf16(acc[mi][ni], al[mi], bh[ni >> 1][(ni & 1) * 2],
                                                   bh[ni >> 1][(ni & 1) * 2 + 1]);
        }
        __syncthreads();
    }
}

// ---------------- 2-term fp16 mainloop ----------------
__device__ __forceinline__ void gemm2_mainloop(
    float acc[2][8][4],
    const fp16* __restrict__ Ah, const fp16* __restrict__ Al, int lda,
    const fp16* __restrict__ B, int ldb, int K)
{
    extern __shared__ char smem_raw[];
    uint32_t sbase = smem_u32(smem_raw);
    const int tid  = threadIdx.x;
    const int wid  = tid >> 5, lane = tid & 31;
    const int m0w  = (wid & 3) * 32;
    const int n0w  = (wid >> 2) * 64;
    const int g    = lane >> 3, lr = lane & 7;

    const uint32_t a_off = (uint32_t)((m0w + (g & 1) * 8 + lr) * ROWB + (g >> 1) * 16);
    const uint32_t b_off = (uint32_t)((n0w + (g >> 1) * 8 + lr) * ROWB + (g & 1) * 16);

    #pragma unroll
    for (int mi = 0; mi < 2; mi++)
        #pragma unroll
        for (int ni = 0; ni < 8; ni++)
            #pragma unroll
            for (int i = 0; i < 4; i++)
                acc[mi][ni][i] = 0.f;

    const int nstage = K >> 5;
    issue_stage2(sbase, 0, Ah, Al, lda, B, ldb, 0);

    for (int c = 0; c < nstage; c++) {
        if (c + 1 < nstage) {
            issue_stage2(sbase, (c + 1) & 1, Ah, Al, lda, B, ldb, (c + 1) << 5);
            cp_wait<1>();
        } else {
            cp_wait<0>();
        }
        __syncthreads();

        uint32_t st = sbase + (uint32_t)(c & 1) * STAGE2B;
        #pragma unroll
        for (int ks = 0; ks < 2; ks++) {
            uint32_t kb = (uint32_t)ks * 32;
            uint32_t ah[2][4], al[2][4];
            ldsm4(ah[0], st + 0 * MATB + a_off + kb);
            ldsm4(ah[1], st + 0 * MATB + a_off + kb + 16 * ROWB);
            ldsm4(al[0], st + 1 * MATB + a_off + kb);
            ldsm4(al[1], st + 1 * MATB + a_off + kb + 16 * ROWB);
            uint32_t bb[4][4];
            #pragma unroll
            for (int pn = 0; pn < 4; pn++)
                ldsm4(bb[pn], st + 2 * MATB + b_off + kb + (uint32_t)pn * 16 * ROWB);
            #pragma unroll
            for (int ni = 0; ni < 8; ni++)
                #pragma unroll
                for (int mi = 0; mi < 2; mi++)
                    mma_fp16(acc[mi][ni], ah[mi], bb[ni >> 1][(ni & 1) * 2],
                                                   bb[ni >> 1][(ni & 1) * 2 + 1]);
            #pragma unroll
            for (int ni = 0; ni < 8; ni++)
                #pragma unroll
                for (int mi = 0; mi < 2; mi++)
                    mma_fp16(acc[mi][ni], al[mi], bb[ni >> 1][(ni & 1) * 2],
                                                   bb[ni >> 1][(ni & 1) * 2 + 1]);
        }
        __syncthreads();
    }
}

template<class F>
__device__ __forceinline__ void epilogue_loop(float acc[2][8][4], F f)
{
    const int wid = threadIdx.x >> 5, lane = threadIdx.x & 31;
    const int m0w = (wid & 3) * 32, n0w = (wid >> 2) * 64;
    const int lr = lane >> 2, lc = (lane & 3) * 2;
    #pragma unroll
    for (int mi = 0; mi < 2; mi++)
        #pragma unroll
        for (int hf = 0; hf < 2; hf++) {
            const int ml = m0w + mi * 16 + hf * 8 + lr;
            #pragma unroll
            for (int ni = 0; ni < 8; ni++) {
                const int nl = n0w + ni * 8 + lc;
                f(ml, nl, make_float2(acc[mi][ni][hf * 2], acc[mi][ni][hf * 2 + 1]));
            }
        }
}

__device__ __forceinline__ void store_hilo2(bf16* oh, bf16* ol, float2 v) {
    bf16 h0 = __float2bfloat16_rn(v.x);
    bf16 h1 = __float2bfloat16_rn(v.y);
    __nv_bfloat162 hh; hh.x = h0; hh.y = h1;
    __nv_bfloat162 ll;
    ll.x = __float2bfloat16_rn(v.x - __bfloat162float(h0));
    ll.y = __float2bfloat16_rn(v.y - __bfloat162float(h1));
    *reinterpret_cast<__nv_bfloat162*>(oh) = hh;
    *reinterpret_cast<__nv_bfloat162*>(ol) = ll;
}
__device__ __forceinline__ void store_hilo2h(fp16* oh, fp16* ol, float2 v) {
    fp16 h0 = __float2half_rn(v.x);
    fp16 h1 = __float2half_rn(v.y);
    __half2 hh; hh.x = h0; hh.y = h1;
    __half2 ll;
    ll.x = __float2half_rn(v.x - __half2float(h0));
    ll.y = __float2half_rn(v.y - __half2float(h1));
    *reinterpret_cast<__half2*>(oh) = hh;
    *reinterpret_cast<__half2*>(ol) = ll;
}

// ============================================================================
// Flash attention smem geometry (V single fp16)
// ============================================================================
#define KT     64                      // keys per tile
#define NKT    (T_ / KT)               // 32 tiles total
#define HKT    (NKT / 2)               // 16 tiles per half (split-KV)
#define QROW   272
#define KROW   272
#define VROW   144
#define SM_QH  0
#define SM_QL  34816
#define SM_K0  69632
#define STG_KH 0
#define STG_KL 17408
#define STG_V  34816
#define STGB   53248                   // 2*17408 + 128*144
#define FLASH_SMEM 176128              // 69632 + 2*53248

__device__ __forceinline__ void issue_kv_stage(uint32_t sb, int buf,
                                               size_t koff, size_t voff, int j)
{
    uint32_t st = sb + SM_K0 + (uint32_t)buf * STGB;
    const int tid = threadIdx.x;
    {   // K tile: 64 rows(keys) x 256B, hi & lo bf16
        int r = tid >> 2;
        int seg0 = (tid & 3) * 4;
        const bf16* sh = g_k_h + koff + (size_t)(j * KT + r) * DH_ + seg0 * 8;
        const bf16* sl = g_k_l + koff + (size_t)(j * KT + r) * DH_ + seg0 * 8;
        uint32_t dh_ = st + STG_KH + r * KROW + seg0 * 16;
        uint32_t dl_ = st + STG_KL + r * KROW + seg0 * 16;
        #pragma unroll
        for (int s = 0; s < 4; s++) { cp16(dh_ + s * 16, sh + s * 8);
                                      cp16(dl_ + s * 16, sl + s * 8); }
    }
    {   // V tile: 128 rows(dh) x 128B fp16 single
        int r = tid >> 1;
        int seg0 = (tid & 1) * 4;
        const fp16* sv = g_vT + voff + (size_t)r * T_ + j * KT + seg0 * 8;
        uint32_t dv = st + STG_V + r * VROW + seg0 * 16;
        #pragma unroll
        for (int s = 0; s < 4; s++) cp16(dv + s * 16, sv + s * 8);
    }
    cp_commit();
}

// ============================================================================
// Flash attention (split-KV): CTA = 128 q rows x 1024 keys (half).
// QK^T 3-term bf16; PV 2-term fp16 (P hi/lo x V single).
// ============================================================================
__global__ void __launch_bounds__(256) flash_attn()
{
    extern __shared__ char smem_raw[];
    uint32_t sb = smem_u32(smem_raw);
    const int tid = threadIdx.x, wid = tid >> 5, lane = tid & 31;
    const int z = blockIdx.y;
    const int m0 = blockIdx.x * 128;
    const int half = blockIdx.z;
    const int j0 = half * HKT;
    const size_t qoff = (size_t)z * T_ * DH_ + (size_t)m0 * DH_;
    const size_t koff = (size_t)z * T_ * DH_;
    const size_t voff = (size_t)z * DH_ * T_;

    // Q -> smem (its own cp.async group)
    {
        int r = tid >> 1, hf = tid & 1;
        const bf16* sh = g_q_h + qoff + (size_t)r * DH_ + hf * 64;
        const bf16* sl = g_q_l + qoff + (size_t)r * DH_ + hf * 64;
        uint32_t dh_ = sb + SM_QH + r * QROW + hf * 128;
        uint32_t dl_ = sb + SM_QL + r * QROW + hf * 128;
        #pragma unroll
        for (int s = 0; s < 8; s++) { cp16(dh_ + s * 16, sh + s * 8);
                                      cp16(dl_ + s * 16, sl + s * 8); }
        cp_commit();
    }
    issue_kv_stage(sb, 0, koff, voff, j0);

    const int g = lane >> 3, lr8 = lane & 7;
    const uint32_t qa  = (uint32_t)((wid * 16 + (g & 1) * 8 + lr8) * QROW + (g >> 1) * 16);
    const uint32_t kbo = (uint32_t)(((g >> 1) * 8 + lr8) * KROW + (g & 1) * 16);
    const uint32_t vbo = (uint32_t)(((g >> 1) * 8 + lr8) * VROW + (g & 1) * 16);

    float o_[16][4];
    #pragma unroll
    for (int i = 0; i < 16; i++) { o_[i][0] = o_[i][1] = o_[i][2] = o_[i][3] = 0.f; }
    float m0r = -1e30f, m1r = -1e30f, l0r = 0.f, l1r = 0.f;

    for (int jj = 0; jj < HKT; jj++) {
        if (jj + 1 < HKT) { issue_kv_stage(sb, (jj + 1) & 1, koff, voff, j0 + jj + 1); cp_wait<1>(); }
        else              { cp_wait<0>(); }
        __syncthreads();

        uint32_t st = sb + SM_K0 + (uint32_t)(jj & 1) * STGB;
        // ---- S = Q K^T  (3-term bf16)
        float s_[8][4];
        #pragma unroll
        for (int i = 0; i < 8; i++) { s_[i][0] = s_[i][1] = s_[i][2] = s_[i][3] = 0.f; }
        #pragma unroll
        for (int ks = 0; ks < 8; ks++) {
            uint32_t qh_[4], ql_[4];
            ldsm4(qh_, sb + SM_QH + qa + ks * 32);
            ldsm4(ql_, sb + SM_QL + qa + ks * 32);
            #pragma unroll
            for (int pn = 0; pn < 4; pn++) {
                uint32_t kh_[4], kl_[4];
                ldsm4(kh_, st + STG_KH + kbo + pn * (16 * KROW) + ks * 32);
                ldsm4(kl_, st + STG_KL + kbo + pn * (16 * KROW) + ks * 32);
                mma_bf16(s_[2*pn],   qh_, kh_[0], kh_[1]);
                mma_bf16(s_[2*pn+1], qh_, kh_[2], kh_[3]);
                mma_bf16(s_[2*pn],   qh_, kl_[0], kl_[1]);
                mma_bf16(s_[2*pn+1], qh_, kl_[2], kl_[3]);
                mma_bf16(s_[2*pn],   ql_, kh_[0], kh_[1]);
                mma_bf16(s_[2*pn+1], ql_, kh_[2], kh_[3]);
            }
        }
        // ---- online softmax
        float tm0 = -1e30f, tm1 = -1e30f;
        #pragma unroll
        for (int i = 0; i < 8; i++) {
            tm0 = fmaxf(tm0, fmaxf(s_[i][0], s_[i][1]));
            tm1 = fmaxf(tm1, fmaxf(s_[i][2], s_[i][3]));
        }
        tm0 = fmaxf(tm0, __shfl_xor_sync(0xFFFFFFFFu, tm0, 1));
        tm0 = fmaxf(tm0, __shfl_xor_sync(0xFFFFFFFFu, tm0, 2));
        tm1 = fmaxf(tm1, __shfl_xor_sync(0xFFFFFFFFu, tm1, 1));
        tm1 = fmaxf(tm1, __shfl_xor_sync(0xFFFFFFFFu, tm1, 2));
        float mn0 = fmaxf(m0r, tm0), mn1 = fmaxf(m1r, tm1);
        float sc0 = expf(m0r - mn0), sc1 = expf(m1r - mn1);
        m0r = mn0; m1r = mn1;
        float sum0 = 0.f, sum1 = 0.f;
        #pragma unroll
        for (int i = 0; i < 8; i++) {
            s_[i][0] = expf(s_[i][0] - mn0); s_[i][1] = expf(s_[i][1] - mn0);
            s_[i][2] = expf(s_[i][2] - mn1); s_[i][3] = expf(s_[i][3] - mn1);
            sum0 += s_[i][0] + s_[i][1];     sum1 += s_[i][2] + s_[i][3];
        }
        sum0 += __shfl_xor_sync(0xFFFFFFFFu, sum0, 1);
        sum0 += __shfl_xor_sync(0xFFFFFFFFu, sum0, 2);
        sum1 += __shfl_xor_sync(0xFFFFFFFFu, sum1, 1);
        sum1 += __shfl_xor_sync(0xFFFFFFFFu, sum1, 2);
        l0r = l0r * sc0 + sum0; l1r = l1r * sc1 + sum1;
        #pragma unroll
        for (int i = 0; i < 16; i++) {
            o_[i][0] *= sc0; o_[i][1] *= sc0; o_[i][2] *= sc1; o_[i][3] *= sc1;
        }
        // ---- O += P V   (2-term fp16: P hi/lo x V single)
        #pragma unroll
        for (int kk = 0; kk < 4; kk++) {
            uint32_t ph_[4], pl_[4];
            ph_[0] = pack_h2(s_[2*kk][0],   s_[2*kk][1]);
            ph_[1] = pack_h2(s_[2*kk][2],   s_[2*kk][3]);
            ph_[2] = pack_h2(s_[2*kk+1][0], s_[2*kk+1][1]);
            ph_[3] = pack_h2(s_[2*kk+1][2], s_[2*kk+1][3]);
            pl_[0] = pack_l2(s_[2*kk][0],   s_[2*kk][1]);
            pl_[1] = pack_l2(s_[2*kk][2],   s_[2*kk][3]);
            pl_[2] = pack_l2(s_[2*kk+1][0], s_[2*kk+1][1]);
            pl_[3] = pack_l2(s_[2*kk+1][2], s_[2*kk+1][3]);
            #pragma unroll
            for (int pn = 0; pn < 8; pn++) {
                uint32_t vh_[4];
                ldsm4(vh_, st + STG_V + vbo + pn * (16 * VROW) + kk * 32);
                mma_fp16(o_[2*pn],   ph_, vh_[0], vh_[1]);
                mma_fp16(o_[2*pn+1], ph_, vh_[2], vh_[3]);
                mma_fp16(o_[2*pn],   pl_, vh_[0], vh_[1]);
                mma_fp16(o_[2*pn+1], pl_, vh_[2], vh_[3]);
            }
        }
        __syncthreads();
    }

    // ---- epilogue: write unnormalized O + (m, l)
    float* oP = g_oP + (size_t)half * QKV_SZ + (size_t)z * T_ * DH_;
    int r0 = m0 + wid * 16 + (lane >> 2);
    int cb = (lane & 3) * 2;
    #pragma unroll
    for (int ni = 0; ni < 16; ni++) {
        int col = ni * 8 + cb;
        *(float2*)(oP + (size_t)r0 * DH_ + col)       = make_float2(o_[ni][0], o_[ni][1]);
        *(float2*)(oP + (size_t)(r0 + 8) * DH_ + col) = make_float2(o_[ni][2], o_[ni][3]);
    }
    if ((lane & 3) == 0) {
        g_mlP[half * BHT + z * T_ + r0]     = make_float2(m0r, l0r);
        g_mlP[half * BHT + z * T_ + r0 + 8] = make_float2(m1r, l1r);
    }
}

// ============================================================================
// combine_ln: merge flash halves + residual -> x1; LayerNorm -> h2 (fp16 hi/lo)
// ============================================================================
__device__ __forceinline__ void block_reduce2(float& a, float& b)
{
    #pragma unroll
    for (int o = 16; o; o >>= 1) {
        a += __shfl_xor_sync(0xFFFFFFFFu, a, o);
        b += __shfl_xor_sync(0xFFFFFFFFu, b, o);
    }
    __shared__ float sa[8], sb_[8];
    int w = threadIdx.x >> 5, l = threadIdx.x & 31;
    if (l == 0) { sa[w] = a; sb_[w] = b; }
    __syncthreads();
    a = 0.f; b = 0.f;
    #pragma unroll
    for (int i = 0; i < 8; i++) { a += sa[i]; b += sb_[i]; }
}

__global__ void combine_ln(const float* __restrict__ x, const float* __restrict__ gg,
                           const float* __restrict__ bb)
{
    int m = blockIdx.x;                  // b*T + t
    int b = m >> 11, t = m & (T_ - 1);
    int col = threadIdx.x * 4;
    int head = col >> 7;
    int z = b * H_ + head;
    int dh = col & (DH_ - 1);

    float2 ml0 = g_mlP[z * T_ + t];
    float2 ml1 = g_mlP[BHT + z * T_ + t];
    float mm = fmaxf(ml0.x, ml1.x);
    float a0 = expf(ml0.x - mm), a1 = expf(ml1.x - mm);
    float inv = 1.0f / (ml0.y * a0 + ml1.y * a1);

    size_t oidx = (size_t)z * T_ * DH_ + (size_t)t * DH_ + dh;
    float4 o0 = *(const float4*)(g_oP + oidx);
    float4 o1 = *(const float4*)(g_oP + QKV_SZ + oidx);
    float4 xr = *(const float4*)(x + (size_t)m * C_ + col);
    float v0 = (o0.x * a0 + o1.x * a1) * inv + xr.x;
    float v1 = (o0.y * a0 + o1.y * a1) * inv + xr.y;
    float v2 = (o0.z * a0 + o1.z * a1) * inv + xr.z;
    float v3 = (o0.w * a0 + o1.w * a1) * inv + xr.w;
    *(float4*)(g_x1 + (size_t)m * C_ + col) = make_float4(v0, v1, v2, v3);

    float s  = v0 + v1 + v2 + v3;
    float sq = v0*v0 + v1*v1 + v2*v2 + v3*v3;
    block_reduce2(s, sq);
    float mean = s * (1.0f / C_);
    float var  = sq * (1.0f / C_) - mean * mean;
    float istd = rsqrtf(var + 1e-5f);
    float4 gv = ((const float4*)gg)[threadIdx.x];
    float4 bv = ((const float4*)bb)[threadIdx.x];
    size_t base = (size_t)m * C_ + col;
    store_hilo2h(g_h2h + base,     g_h2l + base,
                 make_float2((v0 - mean) * istd * gv.x + bv.x,
                             (v1 - mean) * istd * gv.y + bv.y));
    store_hilo2h(g_h2h + base + 2, g_h2l + base + 2,
                 make_float2((v2 - mean) * istd * gv.z + bv.z,
                             (v3 - mean) * istd * gv.w + bv.w));
}

// ============================================================================
// GEMM kernels
// ============================================================================
__global__ void __launch_bounds__(256) qkv_gemm()
{
    int m0   = blockIdx.x * 128;
    int sel  = blockIdx.y >> 3;
    int head = blockIdx.y & 7;
    size_t woff = (size_t)blockIdx.y * DH_ * C_;
    float acc[2][8][4];
    gemm_mainloop(acc,
        g_h1h + (size_t)m0 * C_, g_h1l + (size_t)m0 * C_, C_,
        g_wTh + woff,            g_wTl + woff,            C_, C_);

    const float AL = 11.313708498984761f;   // sqrt(128) folded into q
    epilogue_loop(acc, [&](int ml, int nl, float2 vv) {
        int m = m0 + ml, b = m >> 11, t = m & (T_ - 1);
        size_t base = ((size_t)(b * H_ + head) * T_ + t) * DH_ + nl;
        if (sel == 0)      store_hilo2(g_q_h + base, g_q_l + base,
                                       make_float2(vv.x * AL, vv.y * AL));
        else if (sel == 1) store_hilo2(g_k_h + base, g_k_l + base, vv);
        else               *(float2*)(g_v + base) = vv;
    });
}

__global__ void __launch_bounds__(256) ff1_gemm(const float* __restrict__ b1)
{
    int m0 = blockIdx.x * 128, n0 = blockIdx.y * 128;
    float acc[2][8][4];
    gemm2_mainloop(acc,
        g_h2h + (size_t)m0 * C_, g_h2l + (size_t)m0 * C_, C_,
        g_w1T + (size_t)n0 * C_, C_, C_);

    epilogue_loop(acc, [&](int ml, int nl, float2 vv) {
        float2 bb = *(const float2*)(b1 + n0 + nl);
        float r0 = fmaxf(vv.x + bb.x, 0.f);
        float r1 = fmaxf(vv.y + bb.y, 0.f);
        size_t base = (size_t)(m0 + ml) * DFF_ + n0 + nl;
        store_hilo2h(g_f1h + base, g_f1l + base, make_float2(r0, r1));
    });
}

__global__ void __launch_bounds__(256) ff2_gemm()
{
    int m0 = blockIdx.x * 128, n0 = blockIdx.y * 128;
    int half = blockIdx.z;
    int k0 = half * (DFF_ / 2);
    float acc[2][8][4];
    gemm2_mainloop(acc,
        g_f1h + (size_t)m0 * DFF_ + k0, g_f1l + (size_t)m0 * DFF_ + k0, DFF_,
        g_w2T + (size_t)n0 * DFF_ + k0, DFF_, DFF_ / 2);

    float* dst = g_f2p + (size_t)half * M_ * C_;
    epilogue_loop(acc, [&](int ml, int nl, float2 vv) {
        *(float2*)(dst + (size_t)(m0 + ml) * C_ + n0 + nl) = vv;
    });
}

__global__ void ff2_combine(const float* __restrict__ b2, float* __restrict__ out)
{
    size_t i = ((size_t)blockIdx.x * 256 + threadIdx.x) * 4;
    int col = (int)(i & (C_ - 1));
    float4 p0 = *(const float4*)(g_f2p + i);
    float4 p1 = *(const float4*)(g_f2p + (size_t)M_ * C_ + i);
    float4 xr = *(const float4*)(g_x1 + i);
    float4 bb = *(const float4*)(b2 + col);
    *(float4*)(out + i) = make_float4(p0.x + p1.x + xr.x + bb.x,
                                      p0.y + p1.y + xr.y + bb.y,
                                      p0.z + p1.z + xr.z + bb.z,
                                      p0.w + p1.w + xr.w + bb.w);
}

// ============================================================================
// transposes
// ============================================================================
__global__ void transpose_conv(const float* __restrict__ in, bf16* __restrict__ oh,
                               bf16* __restrict__ ol, int R, int Cc,
                               size_t in_bstride, size_t out_bstride)
{
    __shared__ float tile[32][33];
    const float* src = in + (size_t)blockIdx.z * in_bstride;
    int c0 = blockIdx.x * 32, r0 = blockIdx.y * 32;
    int tx = threadIdx.x, ty = threadIdx.y;          // 32 x 8
    #pragma unroll
    for (int i = 0; i < 32; i += 8)
        tile[ty + i][tx] = src[(size_t)(r0 + ty + i) * Cc + c0 + tx];
    __syncthreads();
    #pragma unroll
    for (int i = 0; i < 32; i += 8) {
        float v = tile[tx][ty + i];
        bf16 h = __float2bfloat16_rn(v);
        bf16 l = __float2bfloat16_rn(v - __bfloat162float(h));
        size_t o = (size_t)blockIdx.z * out_bstride + (size_t)(c0 + ty + i) * R + r0 + tx;
        oh[o] = h; ol[o] = l;
    }
}

__global__ void transpose_conv_h(const float* __restrict__ in, fp16* __restrict__ oh,
                                 int R, int Cc, size_t in_bstride, size_t out_bstride)
{
    __shared__ float tile[32][33];
    const float* src = in + (size_t)blockIdx.z * in_bstride;
    int c0 = blockIdx.x * 32, r0 = blockIdx.y * 32;
    int tx = threadIdx.x, ty = threadIdx.y;
    #pragma unroll
    for (int i = 0; i < 32; i += 8)
        tile[ty + i][tx] = src[(size_t)(r0 + ty + i) * Cc + c0 + tx];
    __syncthreads();
    #pragma unroll
    for (int i = 0; i < 32; i += 8) {
        size_t o = (size_t)blockIdx.z * out_bstride + (size_t)(c0 + ty + i) * R + r0 + tx;
        oh[o] = __float2half_rn(tile[tx][ty + i]);
    }
}

// ============================================================================
// LayerNorm (LN1) -> bf16 hi/lo
// ============================================================================
__global__ void ln_kernel(const float* __restrict__ x, const float* __restrict__ g,
                          const float* __restrict__ bb, bf16* __restrict__ oh,
                          bf16* __restrict__ ol)
{
    size_t row = blockIdx.x;
    float4 v = ((const float4*)(x + row * C_))[threadIdx.x];
    float s  = v.x + v.y + v.z + v.w;
    float sq = v.x*v.x + v.y*v.y + v.z*v.z + v.w*v.w;
    block_reduce2(s, sq);
    float mean = s * (1.0f / C_);
    float var  = sq * (1.0f / C_) - mean * mean;
    float inv  = rsqrtf(var + 1e-5f);
    float4 gv = ((const float4*)g)[threadIdx.x];
    float4 bv = ((const float4*)bb)[threadIdx.x];
    float o0 = (v.x - mean) * inv * gv.x + bv.x;
    float o1 = (v.y - mean) * inv * gv.y + bv.y;
    float o2 = (v.z - mean) * inv * gv.z + bv.z;
    float o3 = (v.w - mean) * inv * gv.w + bv.w;
    size_t base = row * C_ + threadIdx.x * 4;
    store_hilo2(oh + base,     ol + base,     make_float2(o0, o1));
    store_hilo2(oh + base + 2, ol + base + 2, make_float2(o2, o3));
}

// ============================================================================
// host
// ============================================================================
extern "C" void kernel_launch(void* const* d_in, const int* in_sizes, int n_in,
                              void* d_out, int out_size)
{
    const float* x     = (const float*)d_in[0];
    const float* wq    = (const float*)d_in[1];
    const float* wk    = (const float*)d_in[2];
    const float* wv    = (const float*)d_in[3];
    const float* w1    = (const float*)d_in[4];
    const float* b1    = (const float*)d_in[5];
    const float* w2    = (const float*)d_in[6];
    const float* b2    = (const float*)d_in[7];
    const float* ln1_g = (const float*)d_in[8];
    const float* ln1_b = (const float*)d_in[9];
    const float* ln2_g = (const float*)d_in[10];
    const float* ln2_b = (const float*)d_in[11];
    float* out = (float*)d_out;

    cudaFuncSetAttribute(qkv_gemm,   cudaFuncAttributeMaxDynamicSharedMemorySize, GEMM_SMEM);
    cudaFuncSetAttribute(ff1_gemm,   cudaFuncAttributeMaxDynamicSharedMemorySize, GEMM2_SMEM);
    cudaFuncSetAttribute(ff2_gemm,   cudaFuncAttributeMaxDynamicSharedMemorySize, GEMM2_SMEM);
    cudaFuncSetAttribute(flash_attn, cudaFuncAttributeMaxDynamicSharedMemorySize, FLASH_SMEM);

    bf16 *p_h1h, *p_h1l, *p_wTh, *p_wTl;
    fp16 *p_w1T, *p_w2T, *p_vT;
    float *p_v;
    cudaGetSymbolAddress((void**)&p_h1h, g_h1h);
    cudaGetSymbolAddress((void**)&p_h1l, g_h1l);
    cudaGetSymbolAddress((void**)&p_wTh, g_wTh);
    cudaGetSymbolAddress((void**)&p_wTl, g_wTl);
    cudaGetSymbolAddress((void**)&p_w1T, g_w1T);
    cudaGetSymbolAddress((void**)&p_w2T, g_w2T);
    cudaGetSymbolAddress((void**)&p_vT,  g_vT);
    cudaGetSymbolAddress((void**)&p_v,   g_v);

    dim3 tb(32, 8);
    // qkv weight transposes -> [N, K] bf16 hi/lo
    transpose_conv<<<dim3(DH_/32, C_/32, H_), tb>>>(wq, p_wTh, p_wTl, C_, DH_, (size_t)C_*DH_, (size_t)DH_*C_);
    transpose_conv<<<dim3(DH_/32, C_/32, H_), tb>>>(wk, p_wTh + (size_t)H_*DH_*C_, p_wTl + (size_t)H_*DH_*C_, C_, DH_, (size_t)C_*DH_, (size_t)DH_*C_);
    transpose_conv<<<dim3(DH_/32, C_/32, H_), tb>>>(wv, p_wTh + (size_t)2*H_*DH_*C_, p_wTl + (size_t)2*H_*DH_*C_, C_, DH_, (size_t)C_*DH_, (size_t)DH_*C_);
    // ff weight transposes -> fp16 single
    transpose_conv_h<<<dim3(DFF_/32, C_/32, 1), tb>>>(w1, p_w1T, C_, DFF_, 0, 0);
    transpose_conv_h<<<dim3(C_/32, DFF_/32, 1), tb>>>(w2, p_w2T, DFF_, C_, 0, 0);

    // 1. LN1 -> h1 hi/lo (bf16)
    ln_kernel<<<M_, 256>>>(x, ln1_g, ln1_b, p_h1h, p_h1l);
    // 2. QKV projections (3-term bf16; q pre-scaled)
    qkv_gemm<<<dim3(M_/128, 3*H_, 1), 256, GEMM_SMEM>>>();
    // 3. v transpose -> [z][Dh][T] fp16 single
    transpose_conv_h<<<dim3(DH_/32, T_/32, B_*H_), tb>>>(p_v, p_vT, T_, DH_, (size_t)T_*DH_, (size_t)DH_*T_);
    // 4. fused attention, split-KV halves -> O/(m,l) partials
    flash_attn<<<dim3(T_/128, B_*H_, 2), 256, FLASH_SMEM>>>();
    // 5. combine halves + residual -> x1; LN2 -> h2 fp16 hi/lo
    combine_ln<<<M_, 256>>>(x, ln2_g, ln2_b);
    // 6. FF1 (2-term fp16) -> f1 fp16 hi/lo
    ff1_gemm<<<dim3(M_/128, DFF_/128, 1), 256, GEMM2_SMEM>>>(b1);
    // 7. FF2 (2-term fp16) split-K halves -> partials
    ff2_gemm<<<dim3(M_/128, C_/128, 2), 256, GEMM2_SMEM>>>();
    // 8. combine partials + bias + residual -> out
    ff2_combine<<<M_ * C_ / 1024, 256>>>(b2, out);
}

// round 12
// speedup vs baseline: 1.7543x; 1.0521x over previous
#include <cuda_runtime.h>
#include <cuda_bf16.h>
#include <cuda_fp16.h>
#include <cstdint>
#include <math.h>

// ---------------- problem constants ----------------
#define B_  4
#define T_  2048
#define C_  1024
#define H_  8
#define DH_ 128
#define DFF_ 4096
#define M_  (B_ * T_)            // 8192 rows
#define BHT (B_ * H_ * T_)       // 65536

typedef __nv_bfloat16 bf16;
typedef __half fp16;

// ---------------- scratch (device globals, no allocation) ----------------
#define QKV_SZ (B_ * H_ * T_ * DH_)
__device__ bf16  g_h1h[M_ * C_],  g_h1l[M_ * C_];             // LN1 out hi/lo (bf16)
__device__ fp16  g_q_h[QKV_SZ], g_q_l[QKV_SZ];                // q fp16 hi/lo (pre-scaled)
__device__ fp16  g_k  [QKV_SZ];                               // k fp16 single
__device__ float g_v  [QKV_SZ];
__device__ fp16  g_vT [QKV_SZ];                               // [z][Dh][T] fp16 single
__device__ float g_oP [2 * QKV_SZ];                           // flash O partials (unnorm)
__device__ float2 g_mlP[2 * BHT];                             // flash (m, l) per row/half
__device__ float g_x1[M_ * C_];                               // x + attn_out
__device__ fp16  g_h2h[M_ * C_], g_h2l[M_ * C_];              // LN2 out hi/lo (fp16)
__device__ fp16  g_f1h[M_ * DFF_], g_f1l[M_ * DFF_];          // relu(h2 w1 + b1) fp16
__device__ float g_f2p[2 * M_ * C_];                          // ff2 split-K partials
__device__ bf16  g_wTh[3 * H_ * DH_ * C_], g_wTl[3 * H_ * DH_ * C_];  // qkv w^T bf16
__device__ fp16  g_w1T[DFF_ * C_];                            // w1^T [Dff, C] fp16
__device__ fp16  g_w2T[C_ * DFF_];                            // w2^T [C, Dff] fp16

// ---------------- low-level helpers ----------------
__device__ __forceinline__ uint32_t smem_u32(const void* p) {
    uint32_t a;
    asm("{ .reg .u64 t; cvta.to.shared.u64 t, %1; cvt.u32.u64 %0, t; }"
        : "=r"(a) : "l"(p));
    return a;
}
__device__ __forceinline__ void cp16(uint32_t dst, const void* src) {
    asm volatile("cp.async.cg.shared.global [%0], [%1], 16;\n"
                 :: "r"(dst), "l"(__cvta_generic_to_global(src)));
}
__device__ __forceinline__ void cp_commit() {
    asm volatile("cp.async.commit_group;\n" ::: "memory");
}
template<int N> __device__ __forceinline__ void cp_wait() {
    asm volatile("cp.async.wait_group %0;\n" :: "n"(N) : "memory");
}
__device__ __forceinline__ void ldsm4(uint32_t r[4], uint32_t addr) {
    asm volatile("ldmatrix.sync.aligned.m8n8.x4.shared.b16 {%0,%1,%2,%3}, [%4];"
        : "=r"(r[0]), "=r"(r[1]), "=r"(r[2]), "=r"(r[3]) : "r"(addr));
}
__device__ __forceinline__ void mma_bf16(float c[4], const uint32_t a[4],
                                         const uint32_t b0, const uint32_t b1) {
    asm volatile(
        "mma.sync.aligned.m16n8k16.row.col.f32.bf16.bf16.f32 "
        "{%0,%1,%2,%3}, {%4,%5,%6,%7}, {%8,%9}, {%0,%1,%2,%3};"
        : "+f"(c[0]), "+f"(c[1]), "+f"(c[2]), "+f"(c[3])
        : "r"(a[0]), "r"(a[1]), "r"(a[2]), "r"(a[3]), "r"(b0), "r"(b1));
}
__device__ __forceinline__ void mma_fp16(float c[4], const uint32_t a[4],
                                         const uint32_t b0, const uint32_t b1) {
    asm volatile(
        "mma.sync.aligned.m16n8k16.row.col.f32.f16.f16.f32 "
        "{%0,%1,%2,%3}, {%4,%5,%6,%7}, {%8,%9}, {%0,%1,%2,%3};"
        : "+f"(c[0]), "+f"(c[1]), "+f"(c[2]), "+f"(c[3])
        : "r"(a[0]), "r"(a[1]), "r"(a[2]), "r"(a[3]), "r"(b0), "r"(b1));
}
__device__ __forceinline__ uint32_t pack_h2(float a, float b) {
    __half2 t; t.x = __float2half_rn(a); t.y = __float2half_rn(b);
    return *(uint32_t*)&t;
}
__device__ __forceinline__ uint32_t pack_l2(float a, float b) {
    fp16 ha = __float2half_rn(a), hb = __float2half_rn(b);
    __half2 t;
    t.x = __float2half_rn(a - __half2float(ha));
    t.y = __float2half_rn(b - __half2float(hb));
    return *(uint32_t*)&t;
}

// ---------------- GEMM smem geometry ----------------
#define ROWB   80
#define MATB   (128 * ROWB)        // 10240
#define STAGEB (4 * MATB)          // 40960  (3-term: Ah Al Bh Bl)
#define GEMM_SMEM (2 * STAGEB)     // 81920
#define STAGE2B (3 * MATB)         // 30720  (2-term: Ah Al B)
#define GEMM2_SMEM (2 * STAGE2B)   // 61440

// ---------------- stage loader, 3-term bf16 ----------------
__device__ __forceinline__ void issue_stage(
    uint32_t sbase, int buf,
    const bf16* __restrict__ Ah, const bf16* __restrict__ Al, int lda,
    const bf16* __restrict__ Bh, const bf16* __restrict__ Bl, int ldb, int k0)
{
    const int tid = threadIdx.x;
    const int mat = tid >> 6;
    const int t   = tid & 63;
    const bf16* src; int ld;
    if      (mat == 0) { src = Ah; ld = lda; }
    else if (mat == 1) { src = Al; ld = lda; }
    else if (mat == 2) { src = Bh; ld = ldb; }
    else               { src = Bl; ld = ldb; }
    uint32_t mbase = sbase + (uint32_t)buf * STAGEB + (uint32_t)mat * MATB;
    #pragma unroll
    for (int rr = 0; rr < 2; rr++) {
        int row = t * 2 + rr;
        const bf16* s = src + (size_t)row * ld + k0;
        uint32_t d = mbase + row * ROWB;
        #pragma unroll
        for (int seg = 0; seg < 4; seg++)
            cp16(d + seg * 16, s + seg * 8);
    }
    cp_commit();
}

// ---------------- stage loader, 2-term fp16 ----------------
__device__ __forceinline__ void issue_stage2(
    uint32_t sbase, int buf,
    const fp16* __restrict__ Ah, const fp16* __restrict__ Al, int lda,
    const fp16* __restrict__ B, int ldb, int k0)
{
    const int tid = threadIdx.x;
    uint32_t mbase = sbase + (uint32_t)buf * STAGE2B;
    if (tid < 128) {
        int mat = tid >> 6, t = tid & 63;
        const fp16* src = mat ? Al : Ah;
        #pragma unroll
        for (int rr = 0; rr < 2; rr++) {
            int row = t * 2 + rr;
            const fp16* s = src + (size_t)row * lda + k0;
            uint32_t d = mbase + (uint32_t)mat * MATB + row * ROWB;
            #pragma unroll
            for (int seg = 0; seg < 4; seg++)
                cp16(d + seg * 16, s + seg * 8);
        }
    } else {
        int row = tid - 128;
        const fp16* s = B + (size_t)row * ldb + k0;
        uint32_t d = mbase + 2 * MATB + row * ROWB;
        #pragma unroll
        for (int seg = 0; seg < 4; seg++)
            cp16(d + seg * 16, s + seg * 8);
    }
    cp_commit();
}

// ---------------- 3-term bf16 mainloop ----------------
__device__ __forceinline__ void gemm_mainloop(
    float acc[2][8][4],
    const bf16* __restrict__ Ah, const bf16* __restrict__ Al, int lda,
    const bf16* __restrict__ Bh, const bf16* __restrict__ Bl, int ldb, int K)
{
    extern __shared__ char smem_raw[];
    uint32_t sbase = smem_u32(smem_raw);
    const int tid  = threadIdx.x;
    const int wid  = tid >> 5, lane = tid & 31;
    const int m0w  = (wid & 3) * 32;
    const int n0w  = (wid >> 2) * 64;
    const int g    = lane >> 3, lr = lane & 7;

    const uint32_t a_off = (uint32_t)((m0w + (g & 1) * 8 + lr) * ROWB + (g >> 1) * 16);
    const uint32_t b_off = (uint32_t)((n0w + (g >> 1) * 8 + lr) * ROWB + (g & 1) * 16);

    #pragma unroll
    for (int mi = 0; mi < 2; mi++)
        #pragma unroll
        for (int ni = 0; ni < 8; ni++)
            #pragma unroll
            for (int i = 0; i < 4; i++)
                acc[mi][ni][i] = 0.f;

    const int nstage = K >> 5;
    issue_stage(sbase, 0, Ah, Al, lda, Bh, Bl, ldb, 0);

    for (int c = 0; c < nstage; c++) {
        if (c + 1 < nstage) {
            issue_stage(sbase, (c + 1) & 1, Ah, Al, lda, Bh, Bl, ldb, (c + 1) << 5);
            cp_wait<1>();
        } else {
            cp_wait<0>();
        }
        __syncthreads();

        uint32_t st = sbase + (uint32_t)(c & 1) * STAGEB;
        #pragma unroll
        for (int ks = 0; ks < 2; ks++) {
            uint32_t kb = (uint32_t)ks * 32;
            uint32_t ah[2][4], al[2][4];
            ldsm4(ah[0], st + 0 * MATB + a_off + kb);
            ldsm4(ah[1], st + 0 * MATB + a_off + kb + 16 * ROWB);
            ldsm4(al[0], st + 1 * MATB + a_off + kb);
            ldsm4(al[1], st + 1 * MATB + a_off + kb + 16 * ROWB);
            uint32_t bh[4][4], bl[4][4];
            #pragma unroll
            for (int pn = 0; pn < 4; pn++) {
                ldsm4(bh[pn], st + 2 * MATB + b_off + kb + (uint32_t)pn * 16 * ROWB);
                ldsm4(bl[pn], st + 3 * MATB + b_off + kb + (uint32_t)pn * 16 * ROWB);
            }
            #pragma unroll
            for (int ni = 0; ni < 8; ni++)
                #pragma unroll
                for (int mi = 0; mi < 2; mi++)
                    mma_bf16(acc[mi][ni], ah[mi], bh[ni >> 1][(ni & 1) * 2],
                                                   bh[ni >> 1][(ni & 1) * 2 + 1]);
            #pragma unroll
            for (int ni = 0; ni < 8; ni++)
                #pragma unroll
                for (int mi = 0; mi < 2; mi++)
                    mma_bf16(acc[mi][ni], ah[mi], bl[ni >> 1][(ni & 1) * 2],
                                                   bl[ni >> 1][(ni & 1) * 2 + 1]);
            #pragma unroll
            for (int ni = 0; ni < 8; ni++)
                #pragma unroll
                for (int mi = 0; mi < 2; mi++)
                    mma_bf16(acc[mi][ni], al[mi], bh[ni >> 1][(ni & 1) * 2],
                                                   bh[ni >> 1][(ni & 1) * 2 + 1]);
        }
        __syncthreads();
    }
}

// ---------------- 2-term fp16 mainloop ----------------
__device__ __forceinline__ void gemm2_mainloop(
    float acc[2][8][4],
    const fp16* __restrict__ Ah, const fp16* __restrict__ Al, int lda,
    const fp16* __restrict__ B, int ldb, int K)
{
    extern __shared__ char smem_raw[];
    uint32_t sbase = smem_u32(smem_raw);
    const int tid  = threadIdx.x;
    const int wid  = tid >> 5, lane = tid & 31;
    const int m0w  = (wid & 3) * 32;
    const int n0w  = (wid >> 2) * 64;
    const int g    = lane >> 3, lr = lane & 7;

    const uint32_t a_off = (uint32_t)((m0w + (g & 1) * 8 + lr) * ROWB + (g >> 1) * 16);
    const uint32_t b_off = (uint32_t)((n0w + (g >> 1) * 8 + lr) * ROWB + (g & 1) * 16);

    #pragma unroll
    for (int mi = 0; mi < 2; mi++)
        #pragma unroll
        for (int ni = 0; ni < 8; ni++)
            #pragma unroll
            for (int i = 0; i < 4; i++)
                acc[mi][ni][i] = 0.f;

    const int nstage = K >> 5;
    issue_stage2(sbase, 0, Ah, Al, lda, B, ldb, 0);

    for (int c = 0; c < nstage; c++) {
        if (c + 1 < nstage) {
            issue_stage2(sbase, (c + 1) & 1, Ah, Al, lda, B, ldb, (c + 1) << 5);
            cp_wait<1>();
        } else {
            cp_wait<0>();
        }
        __syncthreads();

        uint32_t st = sbase + (uint32_t)(c & 1) * STAGE2B;
        #pragma unroll
        for (int ks = 0; ks < 2; ks++) {
            uint32_t kb = (uint32_t)ks * 32;
            uint32_t ah[2][4], al[2][4];
            ldsm4(ah[0], st + 0 * MATB + a_off + kb);
            ldsm4(ah[1], st + 0 * MATB + a_off + kb + 16 * ROWB);
            ldsm4(al[0], st + 1 * MATB + a_off + kb);
            ldsm4(al[1], st + 1 * MATB + a_off + kb + 16 * ROWB);
            uint32_t bb[4][4];
            #pragma unroll
            for (int pn = 0; pn < 4; pn++)
                ldsm4(bb[pn], st + 2 * MATB + b_off + kb + (uint32_t)pn * 16 * ROWB);
            #pragma unroll
            for (int ni = 0; ni < 8; ni++)
                #pragma unroll
                for (int mi = 0; mi < 2; mi++)
                    mma_fp16(acc[mi][ni], ah[mi], bb[ni >> 1][(ni & 1) * 2],
                                                   bb[ni >> 1][(ni & 1) * 2 + 1]);
            #pragma unroll
            for (int ni = 0; ni < 8; ni++)
                #pragma unroll
                for (int mi = 0; mi < 2; mi++)
                    mma_fp16(acc[mi][ni], al[mi], bb[ni >> 1][(ni & 1) * 2],
                                                   bb[ni >> 1][(ni & 1) * 2 + 1]);
        }
        __syncthreads();
    }
}

template<class F>
__device__ __forceinline__ void epilogue_loop(float acc[2][8][4], F f)
{
    const int wid = threadIdx.x >> 5, lane = threadIdx.x & 31;
    const int m0w = (wid & 3) * 32, n0w = (wid >> 2) * 64;
    const int lr = lane >> 2, lc = (lane & 3) * 2;
    #pragma unroll
    for (int mi = 0; mi < 2; mi++)
        #pragma unroll
        for (int hf = 0; hf < 2; hf++) {
            const int ml = m0w + mi * 16 + hf * 8 + lr;
            #pragma unroll
            for (int ni = 0; ni < 8; ni++) {
                const int nl = n0w + ni * 8 + lc;
                f(ml, nl, make_float2(acc[mi][ni][hf * 2], acc[mi][ni][hf * 2 + 1]));
            }
        }
}

__device__ __forceinline__ void store_hilo2(bf16* oh, bf16* ol, float2 v) {
    bf16 h0 = __float2bfloat16_rn(v.x);
    bf16 h1 = __float2bfloat16_rn(v.y);
    __nv_bfloat162 hh; hh.x = h0; hh.y = h1;
    __nv_bfloat162 ll;
    ll.x = __float2bfloat16_rn(v.x - __bfloat162float(h0));
    ll.y = __float2bfloat16_rn(v.y - __bfloat162float(h1));
    *reinterpret_cast<__nv_bfloat162*>(oh) = hh;
    *reinterpret_cast<__nv_bfloat162*>(ol) = ll;
}
__device__ __forceinline__ void store_hilo2h(fp16* oh, fp16* ol, float2 v) {
    fp16 h0 = __float2half_rn(v.x);
    fp16 h1 = __float2half_rn(v.y);
    __half2 hh; hh.x = h0; hh.y = h1;
    __half2 ll;
    ll.x = __float2half_rn(v.x - __half2float(h0));
    ll.y = __float2half_rn(v.y - __half2float(h1));
    *reinterpret_cast<__half2*>(oh) = hh;
    *reinterpret_cast<__half2*>(ol) = ll;
}

// ============================================================================
// Flash attention smem geometry (K single fp16, V single fp16)
// ============================================================================
#define KT     64                      // keys per tile
#define NKT    (T_ / KT)               // 32 tiles total
#define HKT    (NKT / 2)               // 16 tiles per half (split-KV)
#define QROW   272
#define KROW   272
#define VROW   144
#define SM_QH  0
#define SM_QL  34816
#define SM_K0  69632
#define STG_K  0
#define STG_V  17408                   // 64*272
#define STGB   35840                   // 17408 + 128*144
#define FLASH_SMEM 141312              // 69632 + 2*35840

__device__ __forceinline__ void issue_kv_stage(uint32_t sb, int buf,
                                               size_t koff, size_t voff, int j)
{
    uint32_t st = sb + SM_K0 + (uint32_t)buf * STGB;
    const int tid = threadIdx.x;
    {   // K tile: 64 rows(keys) x 256B fp16 single
        int r = tid >> 2;
        int seg0 = (tid & 3) * 4;
        const fp16* sk = g_k + koff + (size_t)(j * KT + r) * DH_ + seg0 * 8;
        uint32_t dk = st + STG_K + r * KROW + seg0 * 16;
        #pragma unroll
        for (int s = 0; s < 4; s++) cp16(dk + s * 16, sk + s * 8);
    }
    {   // V tile: 128 rows(dh) x 128B fp16 single
        int r = tid >> 1;
        int seg0 = (tid & 1) * 4;
        const fp16* sv = g_vT + voff + (size_t)r * T_ + j * KT + seg0 * 8;
        uint32_t dv = st + STG_V + r * VROW + seg0 * 16;
        #pragma unroll
        for (int s = 0; s < 4; s++) cp16(dv + s * 16, sv + s * 8);
    }
    cp_commit();
}

// ============================================================================
// Flash attention (split-KV): CTA = 128 q rows x 1024 keys (half).
// QK^T 2-term fp16 (q hi/lo x k single); PV 2-term fp16 (P hi/lo x V single).
// ============================================================================
__global__ void __launch_bounds__(256) flash_attn()
{
    extern __shared__ char smem_raw[];
    uint32_t sb = smem_u32(smem_raw);
    const int tid = threadIdx.x, wid = tid >> 5, lane = tid & 31;
    const int z = blockIdx.y;
    const int m0 = blockIdx.x * 128;
    const int half = blockIdx.z;
    const int j0 = half * HKT;
    const size_t qoff = (size_t)z * T_ * DH_ + (size_t)m0 * DH_;
    const size_t koff = (size_t)z * T_ * DH_;
    const size_t voff = (size_t)z * DH_ * T_;

    // Q -> smem (its own cp.async group)
    {
        int r = tid >> 1, hf = tid & 1;
        const fp16* sh = g_q_h + qoff + (size_t)r * DH_ + hf * 64;
        const fp16* sl = g_q_l + qoff + (size_t)r * DH_ + hf * 64;
        uint32_t dh_ = sb + SM_QH + r * QROW + hf * 128;
        uint32_t dl_ = sb + SM_QL + r * QROW + hf * 128;
        #pragma unroll
        for (int s = 0; s < 8; s++) { cp16(dh_ + s * 16, sh + s * 8);
                                      cp16(dl_ + s * 16, sl + s * 8); }
        cp_commit();
    }
    issue_kv_stage(sb, 0, koff, voff, j0);

    const int g = lane >> 3, lr8 = lane & 7;
    const uint32_t qa  = (uint32_t)((wid * 16 + (g & 1) * 8 + lr8) * QROW + (g >> 1) * 16);
    const uint32_t kbo = (uint32_t)(((g >> 1) * 8 + lr8) * KROW + (g & 1) * 16);
    const uint32_t vbo = (uint32_t)(((g >> 1) * 8 + lr8) * VROW + (g & 1) * 16);

    float o_[16][4];
    #pragma unroll
    for (int i = 0; i < 16; i++) { o_[i][0] = o_[i][1] = o_[i][2] = o_[i][3] = 0.f; }
    float m0r = -1e30f, m1r = -1e30f, l0r = 0.f, l1r = 0.f;

    for (int jj = 0; jj < HKT; jj++) {
        if (jj + 1 < HKT) { issue_kv_stage(sb, (jj + 1) & 1, koff, voff, j0 + jj + 1); cp_wait<1>(); }
        else              { cp_wait<0>(); }
        __syncthreads();

        uint32_t st = sb + SM_K0 + (uint32_t)(jj & 1) * STGB;
        // ---- S = Q K^T  (2-term fp16: q hi/lo x k single)
        float s_[8][4];
        #pragma unroll
        for (int i = 0; i < 8; i++) { s_[i][0] = s_[i][1] = s_[i][2] = s_[i][3] = 0.f; }
        #pragma unroll
        for (int ks = 0; ks < 8; ks++) {
            uint32_t qh_[4], ql_[4];
            ldsm4(qh_, sb + SM_QH + qa + ks * 32);
            ldsm4(ql_, sb + SM_QL + qa + ks * 32);
            #pragma unroll
            for (int pn = 0; pn < 4; pn++) {
                uint32_t kk_[4];
                ldsm4(kk_, st + STG_K + kbo + pn * (16 * KROW) + ks * 32);
                mma_fp16(s_[2*pn],   qh_, kk_[0], kk_[1]);
                mma_fp16(s_[2*pn+1], qh_, kk_[2], kk_[3]);
                mma_fp16(s_[2*pn],   ql_, kk_[0], kk_[1]);
                mma_fp16(s_[2*pn+1], ql_, kk_[2], kk_[3]);
            }
        }
        // ---- online softmax
        float tm0 = -1e30f, tm1 = -1e30f;
        #pragma unroll
        for (int i = 0; i < 8; i++) {
            tm0 = fmaxf(tm0, fmaxf(s_[i][0], s_[i][1]));
            tm1 = fmaxf(tm1, fmaxf(s_[i][2], s_[i][3]));
        }
        tm0 = fmaxf(tm0, __shfl_xor_sync(0xFFFFFFFFu, tm0, 1));
        tm0 = fmaxf(tm0, __shfl_xor_sync(0xFFFFFFFFu, tm0, 2));
        tm1 = fmaxf(tm1, __shfl_xor_sync(0xFFFFFFFFu, tm1, 1));
        tm1 = fmaxf(tm1, __shfl_xor_sync(0xFFFFFFFFu, tm1, 2));
        float mn0 = fmaxf(m0r, tm0), mn1 = fmaxf(m1r, tm1);
        float sc0 = expf(m0r - mn0), sc1 = expf(m1r - mn1);
        m0r = mn0; m1r = mn1;
        float sum0 = 0.f, sum1 = 0.f;
        #pragma unroll
        for (int i = 0; i < 8; i++) {
            s_[i][0] = expf(s_[i][0] - mn0); s_[i][1] = expf(s_[i][1] - mn0);
            s_[i][2] = expf(s_[i][2] - mn1); s_[i][3] = expf(s_[i][3] - mn1);
            sum0 += s_[i][0] + s_[i][1];     sum1 += s_[i][2] + s_[i][3];
        }
        sum0 += __shfl_xor_sync(0xFFFFFFFFu, sum0, 1);
        sum0 += __shfl_xor_sync(0xFFFFFFFFu, sum0, 2);
        sum1 += __shfl_xor_sync(0xFFFFFFFFu, sum1, 1);
        sum1 += __shfl_xor_sync(0xFFFFFFFFu, sum1, 2);
        l0r = l0r * sc0 + sum0; l1r = l1r * sc1 + sum1;
        #pragma unroll
        for (int i = 0; i < 16; i++) {
            o_[i][0] *= sc0; o_[i][1] *= sc0; o_[i][2] *= sc1; o_[i][3] *= sc1;
        }
        // ---- O += P V   (2-term fp16: P hi/lo x V single)
        #pragma unroll
        for (int kk = 0; kk < 4; kk++) {
            uint32_t ph_[4], pl_[4];
            ph_[0] = pack_h2(s_[2*kk][0],   s_[2*kk][1]);
            ph_[1] = pack_h2(s_[2*kk][2],   s_[2*kk][3]);
            ph_[2] = pack_h2(s_[2*kk+1][0], s_[2*kk+1][1]);
            ph_[3] = pack_h2(s_[2*kk+1][2], s_[2*kk+1][3]);
            pl_[0] = pack_l2(s_[2*kk][0],   s_[2*kk][1]);
            pl_[1] = pack_l2(s_[2*kk][2],   s_[2*kk][3]);
            pl_[2] = pack_l2(s_[2*kk+1][0], s_[2*kk+1][1]);
            pl_[3] = pack_l2(s_[2*kk+1][2], s_[2*kk+1][3]);
            #pragma unroll
            for (int pn = 0; pn < 8; pn++) {
                uint32_t vh_[4];
                ldsm4(vh_, st + STG_V + vbo + pn * (16 * VROW) + kk * 32);
                mma_fp16(o_[2*pn],   ph_, vh_[0], vh_[1]);
                mma_fp16(o_[2*pn+1], ph_, vh_[2], vh_[3]);
                mma_fp16(o_[2*pn],   pl_, vh_[0], vh_[1]);
                mma_fp16(o_[2*pn+1], pl_, vh_[2], vh_[3]);
            }
        }
        __syncthreads();
    }

    // ---- epilogue: write unnormalized O + (m, l)
    float* oP = g_oP + (size_t)half * QKV_SZ + (size_t)z * T_ * DH_;
    int r0 = m0 + wid * 16 + (lane >> 2);
    int cb = (lane & 3) * 2;
    #pragma unroll
    for (int ni = 0; ni < 16; ni++) {
        int col = ni * 8 + cb;
        *(float2*)(oP + (size_t)r0 * DH_ + col)       = make_float2(o_[ni][0], o_[ni][1]);
        *(float2*)(oP + (size_t)(r0 + 8) * DH_ + col) = make_float2(o_[ni][2], o_[ni][3]);
    }
    if ((lane & 3) == 0) {
        g_mlP[half * BHT + z * T_ + r0]     = make_float2(m0r, l0r);
        g_mlP[half * BHT + z * T_ + r0 + 8] = make_float2(m1r, l1r);
    }
}

// ============================================================================
// combine_ln: merge flash halves + residual -> x1; LayerNorm -> h2 (fp16 hi/lo)
// ============================================================================
__device__ __forceinline__ void block_reduce2(float& a, float& b)
{
    #pragma unroll
    for (int o = 16; o; o >>= 1) {
        a += __shfl_xor_sync(0xFFFFFFFFu, a, o);
        b += __shfl_xor_sync(0xFFFFFFFFu, b, o);
    }
    __shared__ float sa[8], sb_[8];
    int w = threadIdx.x >> 5, l = threadIdx.x & 31;
    if (l == 0) { sa[w] = a; sb_[w] = b; }
    __syncthreads();
    a = 0.f; b = 0.f;
    #pragma unroll
    for (int i = 0; i < 8; i++) { a += sa[i]; b += sb_[i]; }
}

__global__ void combine_ln(const float* __restrict__ x, const float* __restrict__ gg,
                           const float* __restrict__ bb)
{
    int m = blockIdx.x;                  // b*T + t
    int b = m >> 11, t = m & (T_ - 1);
    int col = threadIdx.x * 4;
    int head = col >> 7;
    int z = b * H_ + head;
    int dh = col & (DH_ - 1);

    float2 ml0 = g_mlP[z * T_ + t];
    float2 ml1 = g_mlP[BHT + z * T_ + t];
    float mm = fmaxf(ml0.x, ml1.x);
    float a0 = expf(ml0.x - mm), a1 = expf(ml1.x - mm);
    float inv = 1.0f / (ml0.y * a0 + ml1.y * a1);

    size_t oidx = (size_t)z * T_ * DH_ + (size_t)t * DH_ + dh;
    float4 o0 = *(const float4*)(g_oP + oidx);
    float4 o1 = *(const float4*)(g_oP + QKV_SZ + oidx);
    float4 xr = *(const float4*)(x + (size_t)m * C_ + col);
    float v0 = (o0.x * a0 + o1.x * a1) * inv + xr.x;
    float v1 = (o0.y * a0 + o1.y * a1) * inv + xr.y;
    float v2 = (o0.z * a0 + o1.z * a1) * inv + xr.z;
    float v3 = (o0.w * a0 + o1.w * a1) * inv + xr.w;
    *(float4*)(g_x1 + (size_t)m * C_ + col) = make_float4(v0, v1, v2, v3);

    float s  = v0 + v1 + v2 + v3;
    float sq = v0*v0 + v1*v1 + v2*v2 + v3*v3;
    block_reduce2(s, sq);
    float mean = s * (1.0f / C_);
    float var  = sq * (1.0f / C_) - mean * mean;
    float istd = rsqrtf(var + 1e-5f);
    float4 gv = ((const float4*)gg)[threadIdx.x];
    float4 bv = ((const float4*)bb)[threadIdx.x];
    size_t base = (size_t)m * C_ + col;
    store_hilo2h(g_h2h + base,     g_h2l + base,
                 make_float2((v0 - mean) * istd * gv.x + bv.x,
                             (v1 - mean) * istd * gv.y + bv.y));
    store_hilo2h(g_h2h + base + 2, g_h2l + base + 2,
                 make_float2((v2 - mean) * istd * gv.z + bv.z,
                             (v3 - mean) * istd * gv.w + bv.w));
}

// ============================================================================
// GEMM kernels
// ============================================================================
__global__ void __launch_bounds__(256) qkv_gemm()
{
    int m0   = blockIdx.x * 128;
    int sel  = blockIdx.y >> 3;
    int head = blockIdx.y & 7;
    size_t woff = (size_t)blockIdx.y * DH_ * C_;
    float acc[2][8][4];
    gemm_mainloop(acc,
        g_h1h + (size_t)m0 * C_, g_h1l + (size_t)m0 * C_, C_,
        g_wTh + woff,            g_wTl + woff,            C_, C_);

    const float AL = 11.313708498984761f;   // sqrt(128) folded into q
    epilogue_loop(acc, [&](int ml, int nl, float2 vv) {
        int m = m0 + ml, b = m >> 11, t = m & (T_ - 1);
        size_t base = ((size_t)(b * H_ + head) * T_ + t) * DH_ + nl;
        if (sel == 0)      store_hilo2h(g_q_h + base, g_q_l + base,
                                        make_float2(vv.x * AL, vv.y * AL));
        else if (sel == 1) *(uint32_t*)(g_k + base) = pack_h2(vv.x, vv.y);
        else               *(float2*)(g_v + base) = vv;
    });
}

__global__ void __launch_bounds__(256) ff1_gemm(const float* __restrict__ b1)
{
    int m0 = blockIdx.x * 128, n0 = blockIdx.y * 128;
    float acc[2][8][4];
    gemm2_mainloop(acc,
        g_h2h + (size_t)m0 * C_, g_h2l + (size_t)m0 * C_, C_,
        g_w1T + (size_t)n0 * C_, C_, C_);

    epilogue_loop(acc, [&](int ml, int nl, float2 vv) {
        float2 bb = *(const float2*)(b1 + n0 + nl);
        float r0 = fmaxf(vv.x + bb.x, 0.f);
        float r1 = fmaxf(vv.y + bb.y, 0.f);
        size_t base = (size_t)(m0 + ml) * DFF_ + n0 + nl;
        store_hilo2h(g_f1h + base, g_f1l + base, make_float2(r0, r1));
    });
}

__global__ void __launch_bounds__(256) ff2_gemm()
{
    int m0 = blockIdx.x * 128, n0 = blockIdx.y * 128;
    int half = blockIdx.z;
    int k0 = half * (DFF_ / 2);
    float acc[2][8][4];
    gemm2_mainloop(acc,
        g_f1h + (size_t)m0 * DFF_ + k0, g_f1l + (size_t)m0 * DFF_ + k0, DFF_,
        g_w2T + (size_t)n0 * DFF_ + k0, DFF_, DFF_ / 2);

    float* dst = g_f2p + (size_t)half * M_ * C_;
    epilogue_loop(acc, [&](int ml, int nl, float2 vv) {
        *(float2*)(dst + (size_t)(m0 + ml) * C_ + n0 + nl) = vv;
    });
}

__global__ void ff2_combine(const float* __restrict__ b2, float* __restrict__ out)
{
    size_t i = ((size_t)blockIdx.x * 256 + threadIdx.x) * 4;
    int col = (int)(i & (C_ - 1));
    float4 p0 = *(const float4*)(g_f2p + i);
    float4 p1 = *(const float4*)(g_f2p + (size_t)M_ * C_ + i);
    float4 xr = *(const float4*)(g_x1 + i);
    float4 bb = *(const float4*)(b2 + col);
    *(float4*)(out + i) = make_float4(p0.x + p1.x + xr.x + bb.x,
                                      p0.y + p1.y + xr.y + bb.y,
                                      p0.z + p1.z + xr.z + bb.z,
                                      p0.w + p1.w + xr.w + bb.w);
}

// ============================================================================
// transposes
// ============================================================================
__global__ void transpose_conv(const float* __restrict__ in, bf16* __restrict__ oh,
                               bf16* __restrict__ ol, int R, int Cc,
                               size_t in_bstride, size_t out_bstride)
{
    __shared__ float tile[32][33];
    const float* src = in + (size_t)blockIdx.z * in_bstride;
    int c0 = blockIdx.x * 32, r0 = blockIdx.y * 32;
    int tx = threadIdx.x, ty = threadIdx.y;          // 32 x 8
    #pragma unroll
    for (int i = 0; i < 32; i += 8)
        tile[ty + i][tx] = src[(size_t)(r0 + ty + i) * Cc + c0 + tx];
    __syncthreads();
    #pragma unroll
    for (int i = 0; i < 32; i += 8) {
        float v = tile[tx][ty + i];
        bf16 h = __float2bfloat16_rn(v);
        bf16 l = __float2bfloat16_rn(v - __bfloat162float(h));
        size_t o = (size_t)blockIdx.z * out_bstride + (size_t)(c0 + ty + i) * R + r0 + tx;
        oh[o] = h; ol[o] = l;
    }
}

__global__ void transpose_conv_h(const float* __restrict__ in, fp16* __restrict__ oh,
                                 int R, int Cc, size_t in_bstride, size_t out_bstride)
{
    __shared__ float tile[32][33];
    const float* src = in + (size_t)blockIdx.z * in_bstride;
    int c0 = blockIdx.x * 32, r0 = blockIdx.y * 32;
    int tx = threadIdx.x, ty = threadIdx.y;
    #pragma unroll
    for (int i = 0; i < 32; i += 8)
        tile[ty + i][tx] = src[(size_t)(r0 + ty + i) * Cc + c0 + tx];
    __syncthreads();
    #pragma unroll
    for (int i = 0; i < 32; i += 8) {
        size_t o = (size_t)blockIdx.z * out_bstride + (size_t)(c0 + ty + i) * R + r0 + tx;
        oh[o] = __float2half_rn(tile[tx][ty + i]);
    }
}

// ============================================================================
// LayerNorm (LN1) -> bf16 hi/lo
// ============================================================================
__global__ void ln_kernel(const float* __restrict__ x, const float* __restrict__ g,
                          const float* __restrict__ bb, bf16* __restrict__ oh,
                          bf16* __restrict__ ol)
{
    size_t row = blockIdx.x;
    float4 v = ((const float4*)(x + row * C_))[threadIdx.x];
    float s  = v.x + v.y + v.z + v.w;
    float sq = v.x*v.x + v.y*v.y + v.z*v.z + v.w*v.w;
    block_reduce2(s, sq);
    float mean = s * (1.0f / C_);
    float var  = sq * (1.0f / C_) - mean * mean;
    float inv  = rsqrtf(var + 1e-5f);
    float4 gv = ((const float4*)g)[threadIdx.x];
    float4 bv = ((const float4*)bb)[threadIdx.x];
    float o0 = (v.x - mean) * inv * gv.x + bv.x;
    float o1 = (v.y - mean) * inv * gv.y + bv.y;
    float o2 = (v.z - mean) * inv * gv.z + bv.z;
    float o3 = (v.w - mean) * inv * gv.w + bv.w;
    size_t base = row * C_ + threadIdx.x * 4;
    store_hilo2(oh + base,     ol + base,     make_float2(o0, o1));
    store_hilo2(oh + base + 2, ol + base + 2, make_float2(o2, o3));
}

// ============================================================================
// host
// ============================================================================
extern "C" void kernel_launch(void* const* d_in, const int* in_sizes, int n_in,
                              void* d_out, int out_size)
{
    const float* x     = (const float*)d_in[0];
    const float* wq    = (const float*)d_in[1];
    const float* wk    = (const float*)d_in[2];
    const float* wv    = (const float*)d_in[3];
    const float* w1    = (const float*)d_in[4];
    const float* b1    = (const float*)d_in[5];
    const float* w2    = (const float*)d_in[6];
    const float* b2    = (const float*)d_in[7];
    const float* ln1_g = (const float*)d_in[8];
    const float* ln1_b = (const float*)d_in[9];
    const float* ln2_g = (const float*)d_in[10];
    const float* ln2_b = (const float*)d_in[11];
    float* out = (float*)d_out;

    cudaFuncSetAttribute(qkv_gemm,   cudaFuncAttributeMaxDynamicSharedMemorySize, GEMM_SMEM);
    cudaFuncSetAttribute(ff1_gemm,   cudaFuncAttributeMaxDynamicSharedMemorySize, GEMM2_SMEM);
    cudaFuncSetAttribute(ff2_gemm,   cudaFuncAttributeMaxDynamicSharedMemorySize, GEMM2_SMEM);
    cudaFuncSetAttribute(flash_attn, cudaFuncAttributeMaxDynamicSharedMemorySize, FLASH_SMEM);

    bf16 *p_h1h, *p_h1l, *p_wTh, *p_wTl;
    fp16 *p_w1T, *p_w2T, *p_vT;
    float *p_v;
    cudaGetSymbolAddress((void**)&p_h1h, g_h1h);
    cudaGetSymbolAddress((void**)&p_h1l, g_h1l);
    cudaGetSymbolAddress((void**)&p_wTh, g_wTh);
    cudaGetSymbolAddress((void**)&p_wTl, g_wTl);
    cudaGetSymbolAddress((void**)&p_w1T, g_w1T);
    cudaGetSymbolAddress((void**)&p_w2T, g_w2T);
    cudaGetSymbolAddress((void**)&p_vT,  g_vT);
    cudaGetSymbolAddress((void**)&p_v,   g_v);

    dim3 tb(32, 8);
    // qkv weight transposes -> [N, K] bf16 hi/lo
    transpose_conv<<<dim3(DH_/32, C_/32, H_), tb>>>(wq, p_wTh, p_wTl, C_, DH_, (size_t)C_*DH_, (size_t)DH_*C_);
    transpose_conv<<<dim3(DH_/32, C_/32, H_), tb>>>(wk, p_wTh + (size_t)H_*DH_*C_, p_wTl + (size_t)H_*DH_*C_, C_, DH_, (size_t)C_*DH_, (size_t)DH_*C_);
    transpose_conv<<<dim3(DH_/32, C_/32, H_), tb>>>(wv, p_wTh + (size_t)2*H_*DH_*C_, p_wTl + (size_t)2*H_*DH_*C_, C_, DH_, (size_t)C_*DH_, (size_t)DH_*C_);
    // ff weight transposes -> fp16 single
    transpose_conv_h<<<dim3(DFF_/32, C_/32, 1), tb>>>(w1, p_w1T, C_, DFF_, 0, 0);
    transpose_conv_h<<<dim3(C_/32, DFF_/32, 1), tb>>>(w2, p_w2T, DFF_, C_, 0, 0);

    // 1. LN1 -> h1 hi/lo (bf16)
    ln_kernel<<<M_, 256>>>(x, ln1_g, ln1_b, p_h1h, p_h1l);
    // 2. QKV projections (3-term bf16; q fp16 hi/lo pre-scaled, k fp16 single)
    qkv_gemm<<<dim3(M_/128, 3*H_, 1), 256, GEMM_SMEM>>>();
    // 3. v transpose -> [z][Dh][T] fp16 single
    transpose_conv_h<<<dim3(DH_/32, T_/32, B_*H_), tb>>>(p_v, p_vT, T_, DH_, (size_t)T_*DH_, (size_t)DH_*T_);
    // 4. fused attention, split-KV halves -> O/(m,l) partials
    flash_attn<<<dim3(T_/128, B_*H_, 2), 256, FLASH_SMEM>>>();
    // 5. combine halves + residual -> x1; LN2 -> h2 fp16 hi/lo
    combine_ln<<<M_, 256>>>(x, ln2_g, ln2_b);
    // 6. FF1 (2-term fp16) -> f1 fp16 hi/lo
    ff1_gemm<<<dim3(M_/128, DFF_/128, 1), 256, GEMM2_SMEM>>>(b1);
    // 7. FF2 (2-term fp16) split-K halves -> partials
    ff2_gemm<<<dim3(M_/128, C_/128, 2), 256, GEMM2_SMEM>>>();
    // 8. combine partials + bias + residual -> out
    ff2_combine<<<M_ * C_ / 1024, 256>>>(b2, out);
}